// round 6
// baseline (speedup 1.0000x reference)
#include <cuda_runtime.h>
#include <cstdint>
#include <math.h>

// Problem sizes (fixed)
#define BB   4
#define TT   1024
#define CC   512
#define HH   8
#define NN   64
#define BT   (BB*TT)        // 4096
#define BTC  (BT*CC)        // 2097152
#define SPAD (4*CC)         // over-read guard for branch-free scan prefetch

// ---------------------------------------------------------------------------
// Workspace (static __device__ arrays; no allocation at runtime)
// Scan operand arrays are padded on both sides; live data at [SPAD, SPAD+BTC).
// ---------------------------------------------------------------------------
__device__ float g_xr[BTC], g_xw[BTC], g_xk[BTC], g_xv[BTC], g_xa[BTC], g_xg[BTC];
__device__ float g_gate[BT*HH];
__device__ float g_k[BTC], g_vraw[BTC];
__device__ float g_hw[BT*64], g_ha[BT*64], g_hv[BT*32], g_hg[BT*128];
__device__ float g_a[BTC], g_g[BTC];
__device__ float g_r[BTC+2*SPAD], g_dec[BTC+2*SPAD], g_v[BTC+2*SPAD];
__device__ float g_kp[BTC+2*SPAD], g_aa[BTC+2*SPAD], g_bb[BTC+2*SPAD];
__device__ float g_yf8[BTC*8], g_yb8[BTC*8];   // per-octet partial y
__device__ float g_z[BTC];

// ---------------------------------------------------------------------------
// Kernel 1: token shift, six mixes, per-head gate
// ---------------------------------------------------------------------------
__global__ void prep_kernel(const float* __restrict__ x,
                            const float* __restrict__ mr, const float* __restrict__ mw,
                            const float* __restrict__ mk, const float* __restrict__ mv,
                            const float* __restrict__ ma, const float* __restrict__ mg,
                            const float* __restrict__ gate_w)
{
    int bt = blockIdx.x;
    int t  = bt & (TT - 1);
    int tid = threadIdx.x;
    int c  = tid * 4;
    size_t base = (size_t)bt * CC + c;

    float4 xc = *(const float4*)(x + base);
    float4 xp = make_float4(0.f, 0.f, 0.f, 0.f);
    if (t != 0) xp = *(const float4*)(x + base - CC);

    float4 xx;
    xx.x = xp.x - xc.x; xx.y = xp.y - xc.y; xx.z = xp.z - xc.z; xx.w = xp.w - xc.w;

#define MIXOUT(dst, mvptr)                                                    \
    { float4 m = *(const float4*)(mvptr + c); float4 o;                       \
      o.x = xc.x + xx.x * m.x; o.y = xc.y + xx.y * m.y;                       \
      o.z = xc.z + xx.z * m.z; o.w = xc.w + xx.w * m.w;                       \
      *(float4*)(dst + base) = o; }
    MIXOUT(g_xr, mr); MIXOUT(g_xw, mw); MIXOUT(g_xk, mk);
    MIXOUT(g_xv, mv); MIXOUT(g_xa, ma); MIXOUT(g_xg, mg);
#undef MIXOUT

    float4 gw = *(const float4*)(gate_w + c);
    float p = xx.x*gw.x + xx.y*gw.y + xx.z*gw.z + xx.w*gw.w;
    #pragma unroll
    for (int o = 1; o < 16; o <<= 1) p += __shfl_xor_sync(0xffffffffu, p, o);
    if ((tid & 15) == 0)
        g_gate[bt*HH + (tid >> 4)] = 1.f / (1.f + expf(-p));
}

// ---------------------------------------------------------------------------
// tf32 tensor-core GEMM: C = A[4096,512] @ W^T, W [512,512] row-major
// ---------------------------------------------------------------------------
struct QkvJobs {
    const float* A[3];
    const float* W[3];
    float*       C[3];
};

__device__ __forceinline__ uint32_t f2tf32(float x) {
    uint32_t r;
    asm("cvt.rna.tf32.f32 %0, %1;" : "=r"(r) : "f"(x));
    return r;
}

__device__ __forceinline__ void mma_tf32(float* d, const uint32_t* a, const uint32_t* b) {
    asm("mma.sync.aligned.m16n8k8.row.col.f32.tf32.tf32.f32 "
        "{%0,%1,%2,%3},{%4,%5,%6,%7},{%8,%9},{%0,%1,%2,%3};"
        : "+f"(d[0]), "+f"(d[1]), "+f"(d[2]), "+f"(d[3])
        : "r"(a[0]), "r"(a[1]), "r"(a[2]), "r"(a[3]), "r"(b[0]), "r"(b[1]));
}

__global__ __launch_bounds__(256, 2) void gemm_tf32_nt(QkvJobs J)
{
    const int K = 512, N = 512;
    const float* A = J.A[blockIdx.z];
    const float* W = J.W[blockIdx.z];
    float*       C = J.C[blockIdx.z];

    int m0 = blockIdx.y * 128;
    int n0 = blockIdx.x * 64;

    __shared__ uint32_t As[32][132];
    __shared__ uint32_t Bs[32][68];

    int tid  = threadIdx.x;
    int warp = tid >> 5, lane = tid & 31;
    int g = lane >> 2, c = lane & 3;
    int wm = warp & 3, wn = warp >> 2;

    float acc[2][4][4];
    #pragma unroll
    for (int mt = 0; mt < 2; mt++)
        #pragma unroll
        for (int nt = 0; nt < 4; nt++)
            #pragma unroll
            for (int r = 0; r < 4; r++) acc[mt][nt][r] = 0.f;

    for (int k0 = 0; k0 < K; k0 += 32) {
        #pragma unroll
        for (int it = 0; it < 4; it++) {
            int idx = tid + it * 256;
            int m = idx >> 3, kc = (idx & 7) * 4;
            float4 v = *(const float4*)(A + (size_t)(m0 + m) * K + k0 + kc);
            As[kc+0][m] = f2tf32(v.x);
            As[kc+1][m] = f2tf32(v.y);
            As[kc+2][m] = f2tf32(v.z);
            As[kc+3][m] = f2tf32(v.w);
        }
        #pragma unroll
        for (int it = 0; it < 2; it++) {
            int idx = tid + it * 256;
            int n = idx >> 3, kc = (idx & 7) * 4;
            float4 v = *(const float4*)(W + (size_t)(n0 + n) * K + k0 + kc);
            Bs[kc+0][n] = f2tf32(v.x);
            Bs[kc+1][n] = f2tf32(v.y);
            Bs[kc+2][n] = f2tf32(v.z);
            Bs[kc+3][n] = f2tf32(v.w);
        }
        __syncthreads();

        #pragma unroll
        for (int k8 = 0; k8 < 4; k8++) {
            int kr = k8 * 8;
            uint32_t a[2][4], b[4][2];
            #pragma unroll
            for (int mt = 0; mt < 2; mt++) {
                int mb = wm * 32 + mt * 16;
                a[mt][0] = As[kr + c    ][mb + g    ];
                a[mt][1] = As[kr + c    ][mb + g + 8];
                a[mt][2] = As[kr + c + 4][mb + g    ];
                a[mt][3] = As[kr + c + 4][mb + g + 8];
            }
            #pragma unroll
            for (int nt = 0; nt < 4; nt++) {
                int nb = wn * 32 + nt * 8;
                b[nt][0] = Bs[kr + c    ][nb + g];
                b[nt][1] = Bs[kr + c + 4][nb + g];
            }
            #pragma unroll
            for (int mt = 0; mt < 2; mt++)
                #pragma unroll
                for (int nt = 0; nt < 4; nt++)
                    mma_tf32(acc[mt][nt], a[mt], b[nt]);
        }
        __syncthreads();
    }

    #pragma unroll
    for (int mt = 0; mt < 2; mt++) {
        int row = m0 + wm * 32 + mt * 16 + g;
        #pragma unroll
        for (int nt = 0; nt < 4; nt++) {
            int col = n0 + wn * 32 + nt * 8 + 2 * c;
            float2 v0 = make_float2(acc[mt][nt][0], acc[mt][nt][1]);
            float2 v1 = make_float2(acc[mt][nt][2], acc[mt][nt][3]);
            *(float2*)(C + (size_t)row * N + col)       = v0;
            *(float2*)(C + (size_t)(row + 8) * N + col) = v1;
        }
    }
}

// ---------------------------------------------------------------------------
// Generic multi-job FFMA SGEMM (stage-1/2 MLPs stay fp32)
// ---------------------------------------------------------------------------
#define GBM 128
#define GBN 64
#define GBK 16

struct GemmJobs {
    int count;
    int tileStart[5];
    const float* A[4];
    const float* Bm[4];
    float*       Cm[4];
    int N[4];
    int K[4];
    int transb[4];
    int act[4];
    const float* bias[4];
    const float* aux1[4];
    const float* aux2[4];
};

__global__ __launch_bounds__(256, 2) void gemm_multi(GemmJobs J)
{
    __shared__ __align__(16) float As[GBK][GBM + 4];
    __shared__ __align__(16) float Bs[GBK][GBN + 4];

    int bx = blockIdx.x;
    int j = 0;
    while (bx >= J.tileStart[j + 1]) ++j;
    int n0 = (bx - J.tileStart[j]) * GBN;
    int m0 = blockIdx.y * GBM;

    const float* A = J.A[j];
    const float* B = J.Bm[j];
    float*       C = J.Cm[j];
    const int N = J.N[j];
    const int K = J.K[j];
    const int tb = J.transb[j];

    int tid = threadIdx.x;
    int tx = tid & 15, ty = tid >> 4;

    float acc[8][4];
    #pragma unroll
    for (int im = 0; im < 8; im++)
        #pragma unroll
        for (int in = 0; in < 4; in++) acc[im][in] = 0.f;

    for (int k0 = 0; k0 < K; k0 += GBK) {
        #pragma unroll
        for (int it = 0; it < 2; it++) {
            int lid = tid + it * 256;
            int row = lid >> 2, kc = lid & 3;
            float4 v = *(const float4*)(A + (size_t)(m0 + row) * K + k0 + kc * 4);
            As[kc*4+0][row] = v.x;
            As[kc*4+1][row] = v.y;
            As[kc*4+2][row] = v.z;
            As[kc*4+3][row] = v.w;
        }
        if (tb) {
            int row = tid >> 2, kc = tid & 3;
            float4 v = *(const float4*)(B + (size_t)(n0 + row) * K + k0 + kc * 4);
            Bs[kc*4+0][row] = v.x;
            Bs[kc*4+1][row] = v.y;
            Bs[kc*4+2][row] = v.z;
            Bs[kc*4+3][row] = v.w;
        } else {
            int kr = tid >> 4, c4 = (tid & 15) * 4;
            float4 v = make_float4(0.f, 0.f, 0.f, 0.f);
            if (n0 + c4 < N)
                v = *(const float4*)(B + (size_t)(k0 + kr) * N + n0 + c4);
            *(float4*)&Bs[kr][c4] = v;
        }
        __syncthreads();

        #pragma unroll
        for (int kk = 0; kk < GBK; kk++) {
            float4 bf = *(const float4*)&Bs[kk][tx * 4];
            float4 a0 = *(const float4*)&As[kk][ty * 8];
            float4 a1 = *(const float4*)&As[kk][ty * 8 + 4];
            float af[8] = {a0.x, a0.y, a0.z, a0.w, a1.x, a1.y, a1.z, a1.w};
            float bb2[4] = {bf.x, bf.y, bf.z, bf.w};
            #pragma unroll
            for (int im = 0; im < 8; im++)
                #pragma unroll
                for (int in = 0; in < 4; in++) acc[im][in] += af[im] * bb2[in];
        }
        __syncthreads();
    }

    const int act = J.act[j];
    const float* bias = J.bias[j];
    const float* aux1 = J.aux1[j];
    const float* aux2 = J.aux2[j];

    #pragma unroll
    for (int im = 0; im < 8; im++) {
        int row = m0 + ty * 8 + im;
        #pragma unroll
        for (int in = 0; in < 4; in++) {
            int col = n0 + tx * 4 + in;
            if (col < N) {
                size_t idx = (size_t)row * N + col;
                float v = acc[im][in];
                float o;
                if (act == 0) {
                    o = v;
                } else if (act == 1) {
                    o = tanhf(v);
                } else if (act == 2) {
                    float z = v + (bias ? bias[col] : 0.f);
                    o = 1.f / (1.f + expf(-z));
                } else if (act == 3) {
                    float z = v + bias[col];
                    float s = 1.f / (1.f + expf(-z));
                    o = expf(-0.60653065971263342f * s);
                } else {
                    float z = v + bias[col];
                    float s = 1.f / (1.f + expf(-z));
                    float vr = aux1[idx];
                    o = vr + (aux2[idx] - vr) * s;
                }
                C[idx] = o;
            }
        }
    }
}

// ---------------------------------------------------------------------------
// Kernel: post — kk normalization per head, k' update, aa=-kk, bb=kk*a
// Writes into padded arrays at +SPAD.
// ---------------------------------------------------------------------------
__global__ void post_kernel(const float* __restrict__ k_k, const float* __restrict__ k_a)
{
    int bt = blockIdx.x;
    int tid = threadIdx.x;
    int c = tid * 4;
    size_t base = (size_t)bt * CC + c;

    float4 kv = *(const float4*)(g_k + base);
    float4 av = *(const float4*)(g_a + base);
    float4 kkc = *(const float4*)(k_k + c);
    float4 kac = *(const float4*)(k_a + c);

    float4 kk;
    kk.x = kv.x * kkc.x; kk.y = kv.y * kkc.y; kk.z = kv.z * kkc.z; kk.w = kv.w * kkc.w;
    float ss = kk.x*kk.x + kk.y*kk.y + kk.z*kk.z + kk.w*kk.w;
    #pragma unroll
    for (int o = 1; o < 16; o <<= 1) ss += __shfl_xor_sync(0xffffffffu, ss, o);

    float nrm = sqrtf(ss);
    float inv = 1.f / fmaxf(nrm, 1e-12f);

    float4 aa, bb, kp;
    aa.x = -kk.x * inv; aa.y = -kk.y * inv; aa.z = -kk.z * inv; aa.w = -kk.w * inv;
    bb.x = kk.x * inv * av.x; bb.y = kk.y * inv * av.y;
    bb.z = kk.z * inv * av.z; bb.w = kk.w * inv * av.w;
    kp.x = kv.x * (1.f + (av.x - 1.f) * kac.x);
    kp.y = kv.y * (1.f + (av.y - 1.f) * kac.y);
    kp.z = kv.z * (1.f + (av.z - 1.f) * kac.z);
    kp.w = kv.w * (1.f + (av.w - 1.f) * kac.w);

    *(float4*)(g_aa + SPAD + base) = aa;
    *(float4*)(g_bb + SPAD + base) = bb;
    *(float4*)(g_kp + SPAD + base) = kp;
}

// ---------------------------------------------------------------------------
// Kernel: bidirectional WKV7 scan — branch-free inner loop.
// grid = 128 blocks (dir*64 + b*16 + h*2 + rowgroup), 256 threads.
// thread (i = rg*32 + tid>>3, q = tid&7) owns row i, cols [q*8, q*8+8).
// Unconditional depth-2 prefetch into padded arrays; y-reduction deferred to
// combine (partials stored per-octet, coalesced); only sa shuffles remain.
// ---------------------------------------------------------------------------
template<int CS, int NS>
__device__ __forceinline__ void scan_step(
    float (&S)[8],
    float (&RB)[2][8], float (&DB)[2][8], float (&KB)[2][8],
    float (&BF)[2][8], float (&AB)[2][8], float (&VB)[2],
    float& sa,
    const float*& pr2, const float*& pd2, const float*& pk2,
    const float*& pb2, const float*& pv2, const float*& pa3,
    float*& py8, int stride, int stride8)
{
    float y0 = 0.f, y1 = 0.f;
    float z0 = 0.f, z1 = 0.f;
    float Vv = VB[CS];
    #pragma unroll
    for (int j = 0; j < 4; j++) {
        float sj;
        sj = S[j]   * DB[CS][j]   + sa * BF[CS][j]   + Vv * KB[CS][j];
        S[j] = sj;    y0 += sj * RB[CS][j];    z0 += sj * AB[NS][j];
        sj = S[4+j] * DB[CS][4+j] + sa * BF[CS][4+j] + Vv * KB[CS][4+j];
        S[4+j] = sj;  y1 += sj * RB[CS][4+j];  z1 += sj * AB[NS][4+j];
    }
    float y   = y0 + y1;
    float sap = z0 + z1;

    // unconditional prefetch (padded arrays make over-reads safe)
    #pragma unroll
    for (int u = 0; u < 2; u++) {
        *(float4*)&RB[CS][u*4] = *(const float4*)(pr2 + u*4);
        *(float4*)&DB[CS][u*4] = *(const float4*)(pd2 + u*4);
        *(float4*)&KB[CS][u*4] = *(const float4*)(pk2 + u*4);
        *(float4*)&BF[CS][u*4] = *(const float4*)(pb2 + u*4);
        *(float4*)&AB[NS][u*4] = *(const float4*)(pa3 + u*4);
    }
    VB[CS] = *pv2;
    pr2 += stride; pd2 += stride; pk2 += stride; pb2 += stride;
    pv2 += stride; pa3 += stride;

    // sa reduction only (y deferred)
    sap += __shfl_xor_sync(0xffffffffu, sap, 1);
    sap += __shfl_xor_sync(0xffffffffu, sap, 2);
    sap += __shfl_xor_sync(0xffffffffu, sap, 4);

    *py8 = y;              // per-octet partial, coalesced 128B/warp
    py8 += stride8;
    sa = sap;
}

__global__ __launch_bounds__(256, 1) void scan_kernel()
{
    int bx = blockIdx.x;
    int dir = bx >> 6;
    int b   = (bx >> 4) & 3;
    int h   = (bx >> 1) & 7;
    int rg  = bx & 1;
    int tid = threadIdx.x;
    int i   = rg * 32 + (tid >> 3);
    int q   = tid & 7;
    int c0  = q * 8;

    int t0 = dir ? (TT - 1) : 0;
    int stride = dir ? -CC : CC;
    int stride8 = dir ? -(HH*512) : (HH*512);
    size_t off = SPAD + (size_t)(b * TT + t0) * CC + h * NN;

    const float* pr = g_r   + off + c0;
    const float* pd = g_dec + off + c0;
    const float* pk = g_kp  + off + c0;
    const float* pa = g_aa  + off + c0;
    const float* pb = g_bb  + off + c0;
    const float* pv = g_v   + off + i;
    float* py8 = (dir ? g_yb8 : g_yf8)
               + (size_t)(b * TT + t0) * (HH*512) + h * 512 + i * 8 + q;

    float S[8];
    #pragma unroll
    for (int j = 0; j < 8; j++) S[j] = 0.f;

    float RB[2][8], DB[2][8], KB[2][8], BF[2][8], AB[2][8], VB[2];

    #pragma unroll
    for (int u = 0; u < 2; u++) {
        *(float4*)&RB[0][u*4] = *(const float4*)(pr + u*4);
        *(float4*)&DB[0][u*4] = *(const float4*)(pd + u*4);
        *(float4*)&KB[0][u*4] = *(const float4*)(pk + u*4);
        *(float4*)&BF[0][u*4] = *(const float4*)(pb + u*4);
        *(float4*)&RB[1][u*4] = *(const float4*)(pr + stride + u*4);
        *(float4*)&DB[1][u*4] = *(const float4*)(pd + stride + u*4);
        *(float4*)&KB[1][u*4] = *(const float4*)(pk + stride + u*4);
        *(float4*)&BF[1][u*4] = *(const float4*)(pb + stride + u*4);
        *(float4*)&AB[1][u*4] = *(const float4*)(pa + stride + u*4);
        *(float4*)&AB[0][u*4] = *(const float4*)(pa + 2*stride + u*4);
    }
    VB[0] = *pv;
    VB[1] = *(pv + stride);

    const float* pr2 = pr + 2*stride;
    const float* pd2 = pd + 2*stride;
    const float* pk2 = pk + 2*stride;
    const float* pb2 = pb + 2*stride;
    const float* pv2 = pv + 2*stride;
    const float* pa3 = pa + 3*stride;

    float sa = 0.f;

    for (int t = 0; t < TT; t += 2) {
        scan_step<0,1>(S, RB, DB, KB, BF, AB, VB, sa,
                       pr2, pd2, pk2, pb2, pv2, pa3, py8, stride, stride8);
        scan_step<1,0>(S, RB, DB, KB, BF, AB, VB, sa,
                       pr2, pd2, pk2, pb2, pv2, pa3, py8, stride, stride8);
    }
}

// ---------------------------------------------------------------------------
// Kernel: combine — assemble y from octet partials, gate-mix, groupnorm,
// residual, * g
// ---------------------------------------------------------------------------
__global__ void combine_kernel(const float* __restrict__ r_k,
                               const float* __restrict__ ln_g,
                               const float* __restrict__ ln_b)
{
    int bt = blockIdx.x;
    int tid = threadIdx.x;
    int c = tid * 4;
    int h = tid >> 4;
    size_t base = (size_t)bt * CC + c;
    size_t base8 = (size_t)bt * (HH*512) + (size_t)c * 8;

    float gate = g_gate[bt * HH + h];

    float4 yf, yb;
    {
        float* pf = (float*)&yf;
        float* pb = (float*)&yb;
        #pragma unroll
        for (int e = 0; e < 4; e++) {
            float4 f0 = *(const float4*)(g_yf8 + base8 + e*8);
            float4 f1 = *(const float4*)(g_yf8 + base8 + e*8 + 4);
            float4 b0 = *(const float4*)(g_yb8 + base8 + e*8);
            float4 b1 = *(const float4*)(g_yb8 + base8 + e*8 + 4);
            pf[e] = ((f0.x+f0.y)+(f0.z+f0.w)) + ((f1.x+f1.y)+(f1.z+f1.w));
            pb[e] = ((b0.x+b0.y)+(b0.z+b0.w)) + ((b1.x+b1.y)+(b1.z+b1.w));
        }
    }

    float4 xo;
    xo.x = gate * yf.x + (1.f - gate) * yb.x;
    xo.y = gate * yf.y + (1.f - gate) * yb.y;
    xo.z = gate * yf.z + (1.f - gate) * yb.z;
    xo.w = gate * yf.w + (1.f - gate) * yb.w;

    float4 rv = *(const float4*)(g_r + SPAD + base);
    float4 kp = *(const float4*)(g_kp + SPAD + base);
    float4 vv = *(const float4*)(g_v + SPAD + base);
    float4 gv = *(const float4*)(g_g + base);
    float4 rk = *(const float4*)(r_k + c);

    float sum = xo.x + xo.y + xo.z + xo.w;
    float sq  = xo.x*xo.x + xo.y*xo.y + xo.z*xo.z + xo.w*xo.w;
    float sres = rv.x*kp.x*rk.x + rv.y*kp.y*rk.y + rv.z*kp.z*rk.z + rv.w*kp.w*rk.w;
    #pragma unroll
    for (int o = 1; o < 16; o <<= 1) {
        sum  += __shfl_xor_sync(0xffffffffu, sum, o);
        sq   += __shfl_xor_sync(0xffffffffu, sq, o);
        sres += __shfl_xor_sync(0xffffffffu, sres, o);
    }
    float mu = sum * (1.f / 64.f);
    float var = sq * (1.f / 64.f) - mu * mu;
    float rstd = rsqrtf(var + 0.00064f);

    float4 lg = *(const float4*)(ln_g + c);
    float4 lb = *(const float4*)(ln_b + c);

    float4 z;
    z.x = ((xo.x - mu) * rstd * lg.x + lb.x + sres * vv.x) * gv.x;
    z.y = ((xo.y - mu) * rstd * lg.y + lb.y + sres * vv.y) * gv.y;
    z.z = ((xo.z - mu) * rstd * lg.z + lb.z + sres * vv.z) * gv.z;
    z.w = ((xo.w - mu) * rstd * lg.w + lb.w + sres * vv.w) * gv.w;
    *(float4*)(g_z + base) = z;
}

// ---------------------------------------------------------------------------
// Host launcher
// ---------------------------------------------------------------------------
static float *P_xr, *P_xw, *P_xk, *P_xv, *P_xa, *P_xg;
static float *P_r, *P_k, *P_vraw;
static float *P_hw, *P_ha, *P_hv, *P_hg;
static float *P_dec, *P_a, *P_v, *P_g;
static float *P_z;
static bool s_init = false;

extern "C" void kernel_launch(void* const* d_in, const int* in_sizes, int n_in,
                              void* d_out, int out_size)
{
    const float* x       = (const float*)d_in[0];
    const float* v_first = (const float*)d_in[1];
    const float* x_r = (const float*)d_in[2];
    const float* x_w = (const float*)d_in[3];
    const float* x_k = (const float*)d_in[4];
    const float* x_v = (const float*)d_in[5];
    const float* x_a = (const float*)d_in[6];
    const float* x_g = (const float*)d_in[7];
    const float* w0  = (const float*)d_in[8];
    const float* w1  = (const float*)d_in[9];
    const float* w2  = (const float*)d_in[10];
    const float* a0  = (const float*)d_in[11];
    const float* a1  = (const float*)d_in[12];
    const float* a2  = (const float*)d_in[13];
    const float* v0  = (const float*)d_in[14];
    const float* v1  = (const float*)d_in[15];
    const float* v2  = (const float*)d_in[16];
    const float* g1  = (const float*)d_in[17];
    const float* g2  = (const float*)d_in[18];
    const float* k_k = (const float*)d_in[19];
    const float* k_a = (const float*)d_in[20];
    const float* r_k = (const float*)d_in[21];
    const float* gate_w = (const float*)d_in[22];
    const float* ln_g = (const float*)d_in[23];
    const float* ln_b = (const float*)d_in[24];
    const float* Wr = (const float*)d_in[25];
    const float* Wk = (const float*)d_in[26];
    const float* Wv = (const float*)d_in[27];
    const float* Wo = (const float*)d_in[28];
    float* out = (float*)d_out;

    if (!s_init) {
        cudaGetSymbolAddress((void**)&P_xr, g_xr);
        cudaGetSymbolAddress((void**)&P_xw, g_xw);
        cudaGetSymbolAddress((void**)&P_xk, g_xk);
        cudaGetSymbolAddress((void**)&P_xv, g_xv);
        cudaGetSymbolAddress((void**)&P_xa, g_xa);
        cudaGetSymbolAddress((void**)&P_xg, g_xg);
        cudaGetSymbolAddress((void**)&P_r, g_r);       P_r   += SPAD;
        cudaGetSymbolAddress((void**)&P_k, g_k);
        cudaGetSymbolAddress((void**)&P_vraw, g_vraw);
        cudaGetSymbolAddress((void**)&P_hw, g_hw);
        cudaGetSymbolAddress((void**)&P_ha, g_ha);
        cudaGetSymbolAddress((void**)&P_hv, g_hv);
        cudaGetSymbolAddress((void**)&P_hg, g_hg);
        cudaGetSymbolAddress((void**)&P_dec, g_dec);   P_dec += SPAD;
        cudaGetSymbolAddress((void**)&P_a, g_a);
        cudaGetSymbolAddress((void**)&P_v, g_v);       P_v   += SPAD;
        cudaGetSymbolAddress((void**)&P_g, g_g);
        cudaGetSymbolAddress((void**)&P_z, g_z);
        s_init = true;
    }

    // 1) token shift + mixes + gate
    prep_kernel<<<BT, 128>>>(x, x_r, x_w, x_k, x_v, x_a, x_g, gate_w);

    // 2) big QKV GEMMs — tf32 tensor cores
    {
        QkvJobs J;
        J.A[0] = P_xr; J.W[0] = Wr; J.C[0] = P_r;
        J.A[1] = P_xk; J.W[1] = Wk; J.C[1] = P_k;
        J.A[2] = P_xv; J.W[2] = Wv; J.C[2] = P_vraw;
        gemm_tf32_nt<<<dim3(8, 32, 3), 256>>>(J);
    }

    // 3) stage-1 hidden GEMMs (fp32 FFMA — decay path precision)
    {
        GemmJobs J = {};
        J.count = 4;
        J.tileStart[0] = 0; J.tileStart[1] = 1; J.tileStart[2] = 2; J.tileStart[3] = 3; J.tileStart[4] = 5;
        J.A[0] = P_xw; J.Bm[0] = w1; J.Cm[0] = P_hw; J.N[0] = 64;  J.K[0] = 512; J.transb[0] = 0; J.act[0] = 1;
        J.A[1] = P_xa; J.Bm[1] = a1; J.Cm[1] = P_ha; J.N[1] = 64;  J.K[1] = 512; J.transb[1] = 0; J.act[1] = 0;
        J.A[2] = x;    J.Bm[2] = v1; J.Cm[2] = P_hv; J.N[2] = 32;  J.K[2] = 512; J.transb[2] = 0; J.act[2] = 0;
        J.A[3] = P_xg; J.Bm[3] = g1; J.Cm[3] = P_hg; J.N[3] = 128; J.K[3] = 512; J.transb[3] = 0; J.act[3] = 2;
        for (int jj = 0; jj < 4; jj++) { J.bias[jj] = nullptr; J.aux1[jj] = nullptr; J.aux2[jj] = nullptr; }
        gemm_multi<<<dim3(5, 32), 256>>>(J);
    }

    // 4) stage-2 GEMMs with fused epilogues (fp32 FFMA)
    {
        GemmJobs J = {};
        J.count = 4;
        J.tileStart[0] = 0; J.tileStart[1] = 8; J.tileStart[2] = 16; J.tileStart[3] = 24; J.tileStart[4] = 32;
        J.A[0] = P_hw; J.Bm[0] = w2; J.Cm[0] = P_dec; J.N[0] = 512; J.K[0] = 64;  J.transb[0] = 0; J.act[0] = 3;
        J.bias[0] = w0; J.aux1[0] = nullptr; J.aux2[0] = nullptr;
        J.A[1] = P_ha; J.Bm[1] = a2; J.Cm[1] = P_a; J.N[1] = 512; J.K[1] = 64;  J.transb[1] = 0; J.act[1] = 2;
        J.bias[1] = a0; J.aux1[1] = nullptr; J.aux2[1] = nullptr;
        J.A[2] = P_hv; J.Bm[2] = v2; J.Cm[2] = P_v; J.N[2] = 512; J.K[2] = 32;  J.transb[2] = 0; J.act[2] = 4;
        J.bias[2] = v0; J.aux1[2] = P_vraw; J.aux2[2] = v_first;
        J.A[3] = P_hg; J.Bm[3] = g2; J.Cm[3] = P_g; J.N[3] = 512; J.K[3] = 128; J.transb[3] = 0; J.act[3] = 0;
        J.bias[3] = nullptr; J.aux1[3] = nullptr; J.aux2[3] = nullptr;
        gemm_multi<<<dim3(32, 32), 256>>>(J);
    }

    // 5) kk normalize, k', aa, bb
    post_kernel<<<BT, 128>>>(k_k, k_a);

    // 6) bidirectional WKV7 scan — branch-free
    scan_kernel<<<128, 256>>>();

    // 7) combine (+ octet reduction) + groupnorm + residual + *g
    combine_kernel<<<BT, 128>>>(r_k, ln_g, ln_b);

    // 8) out = z @ Wo^T — tf32 tensor cores
    {
        QkvJobs J;
        J.A[0] = P_z; J.W[0] = Wo; J.C[0] = out;
        J.A[1] = P_z; J.W[1] = Wo; J.C[1] = out;
        J.A[2] = P_z; J.W[2] = Wo; J.C[2] = out;
        gemm_tf32_nt<<<dim3(8, 32, 1), 256>>>(J);
    }

    // 9) v_first passthrough if the flattened output includes it
    if (out_size >= 2 * BTC) {
        cudaMemcpyAsync(out + BTC, v_first, (size_t)BTC * sizeof(float),
                        cudaMemcpyDeviceToDevice, 0);
    }
}

// round 8
// speedup vs baseline: 1.1896x; 1.1896x over previous
#include <cuda_runtime.h>
#include <cstdint>
#include <math.h>

// Problem sizes (fixed)
#define BB   4
#define TT   1024
#define CC   512
#define HH   8
#define NN   64
#define BT   (BB*TT)        // 4096
#define BTC  (BT*CC)        // 2097152
#define SPAD (4*CC)         // over-read guard for branch-free scan prefetch

typedef unsigned long long u64;

// ---------------------------------------------------------------------------
// Workspace (static __device__ arrays; no allocation at runtime)
// Scan operand arrays padded both sides; live data at [SPAD, SPAD+BTC).
// ---------------------------------------------------------------------------
__device__ float g_xr[BTC], g_xw[BTC], g_xk[BTC], g_xv[BTC], g_xa[BTC], g_xg[BTC];
__device__ float g_gate[BT*HH];
__device__ float g_k[BTC], g_vraw[BTC];
__device__ float g_hw[BT*64], g_ha[BT*64], g_hv[BT*32], g_hg[BT*128];
__device__ float g_a[BTC], g_g[BTC];
__device__ float g_r[BTC+2*SPAD], g_dec[BTC+2*SPAD], g_v[BTC+2*SPAD];
__device__ float g_kp[BTC+2*SPAD], g_aa[BTC+2*SPAD], g_bb[BTC+2*SPAD];
__device__ float g_yf[BTC], g_yb[BTC], g_z[BTC];

// ---------------------------------------------------------------------------
// f32x2 packed helpers (sm_100+)
// ---------------------------------------------------------------------------
__device__ __forceinline__ u64 fma2(u64 a, u64 b, u64 c) {
    u64 d; asm("fma.rn.f32x2 %0, %1, %2, %3;" : "=l"(d) : "l"(a), "l"(b), "l"(c));
    return d;
}
__device__ __forceinline__ u64 mul2(u64 a, u64 b) {
    u64 d; asm("mul.rn.f32x2 %0, %1, %2;" : "=l"(d) : "l"(a), "l"(b));
    return d;
}
__device__ __forceinline__ u64 pack2(float x) {
    u64 d; uint32_t r = __float_as_uint(x);
    asm("mov.b64 %0, {%1, %1};" : "=l"(d) : "r"(r));
    return d;
}
__device__ __forceinline__ float sum2(u64 a) {
    uint32_t lo, hi;
    asm("mov.b64 {%0, %1}, %2;" : "=r"(lo), "=r"(hi) : "l"(a));
    return __uint_as_float(lo) + __uint_as_float(hi);
}

// ---------------------------------------------------------------------------
// Kernel 1: token shift, six mixes, per-head gate
// ---------------------------------------------------------------------------
__global__ void prep_kernel(const float* __restrict__ x,
                            const float* __restrict__ mr, const float* __restrict__ mw,
                            const float* __restrict__ mk, const float* __restrict__ mv,
                            const float* __restrict__ ma, const float* __restrict__ mg,
                            const float* __restrict__ gate_w)
{
    int bt = blockIdx.x;
    int t  = bt & (TT - 1);
    int tid = threadIdx.x;
    int c  = tid * 4;
    size_t base = (size_t)bt * CC + c;

    float4 xc = *(const float4*)(x + base);
    float4 xp = make_float4(0.f, 0.f, 0.f, 0.f);
    if (t != 0) xp = *(const float4*)(x + base - CC);

    float4 xx;
    xx.x = xp.x - xc.x; xx.y = xp.y - xc.y; xx.z = xp.z - xc.z; xx.w = xp.w - xc.w;

#define MIXOUT(dst, mvptr)                                                    \
    { float4 m = *(const float4*)(mvptr + c); float4 o;                       \
      o.x = xc.x + xx.x * m.x; o.y = xc.y + xx.y * m.y;                       \
      o.z = xc.z + xx.z * m.z; o.w = xc.w + xx.w * m.w;                       \
      *(float4*)(dst + base) = o; }
    MIXOUT(g_xr, mr); MIXOUT(g_xw, mw); MIXOUT(g_xk, mk);
    MIXOUT(g_xv, mv); MIXOUT(g_xa, ma); MIXOUT(g_xg, mg);
#undef MIXOUT

    float4 gw = *(const float4*)(gate_w + c);
    float p = xx.x*gw.x + xx.y*gw.y + xx.z*gw.z + xx.w*gw.w;
    #pragma unroll
    for (int o = 1; o < 16; o <<= 1) p += __shfl_xor_sync(0xffffffffu, p, o);
    if ((tid & 15) == 0)
        g_gate[bt*HH + (tid >> 4)] = 1.f / (1.f + expf(-p));
}

// ---------------------------------------------------------------------------
// tf32 tensor-core GEMM: C = A[4096,512] @ W^T, W [512,512] row-major
// ---------------------------------------------------------------------------
struct QkvJobs {
    const float* A[3];
    const float* W[3];
    float*       C[3];
};

__device__ __forceinline__ uint32_t f2tf32(float x) {
    uint32_t r;
    asm("cvt.rna.tf32.f32 %0, %1;" : "=r"(r) : "f"(x));
    return r;
}

__device__ __forceinline__ void mma_tf32(float* d, const uint32_t* a, const uint32_t* b) {
    asm("mma.sync.aligned.m16n8k8.row.col.f32.tf32.tf32.f32 "
        "{%0,%1,%2,%3},{%4,%5,%6,%7},{%8,%9},{%0,%1,%2,%3};"
        : "+f"(d[0]), "+f"(d[1]), "+f"(d[2]), "+f"(d[3])
        : "r"(a[0]), "r"(a[1]), "r"(a[2]), "r"(a[3]), "r"(b[0]), "r"(b[1]));
}

__global__ __launch_bounds__(256, 2) void gemm_tf32_nt(QkvJobs J)
{
    const int K = 512, N = 512;
    const float* A = J.A[blockIdx.z];
    const float* W = J.W[blockIdx.z];
    float*       C = J.C[blockIdx.z];

    int m0 = blockIdx.y * 128;
    int n0 = blockIdx.x * 64;

    __shared__ uint32_t As[32][132];
    __shared__ uint32_t Bs[32][68];

    int tid  = threadIdx.x;
    int warp = tid >> 5, lane = tid & 31;
    int g = lane >> 2, c = lane & 3;
    int wm = warp & 3, wn = warp >> 2;

    float acc[2][4][4];
    #pragma unroll
    for (int mt = 0; mt < 2; mt++)
        #pragma unroll
        for (int nt = 0; nt < 4; nt++)
            #pragma unroll
            for (int r = 0; r < 4; r++) acc[mt][nt][r] = 0.f;

    for (int k0 = 0; k0 < K; k0 += 32) {
        #pragma unroll
        for (int it = 0; it < 4; it++) {
            int idx = tid + it * 256;
            int m = idx >> 3, kc = (idx & 7) * 4;
            float4 v = *(const float4*)(A + (size_t)(m0 + m) * K + k0 + kc);
            As[kc+0][m] = f2tf32(v.x);
            As[kc+1][m] = f2tf32(v.y);
            As[kc+2][m] = f2tf32(v.z);
            As[kc+3][m] = f2tf32(v.w);
        }
        #pragma unroll
        for (int it = 0; it < 2; it++) {
            int idx = tid + it * 256;
            int n = idx >> 3, kc = (idx & 7) * 4;
            float4 v = *(const float4*)(W + (size_t)(n0 + n) * K + k0 + kc);
            Bs[kc+0][n] = f2tf32(v.x);
            Bs[kc+1][n] = f2tf32(v.y);
            Bs[kc+2][n] = f2tf32(v.z);
            Bs[kc+3][n] = f2tf32(v.w);
        }
        __syncthreads();

        #pragma unroll
        for (int k8 = 0; k8 < 4; k8++) {
            int kr = k8 * 8;
            uint32_t a[2][4], b[4][2];
            #pragma unroll
            for (int mt = 0; mt < 2; mt++) {
                int mb = wm * 32 + mt * 16;
                a[mt][0] = As[kr + c    ][mb + g    ];
                a[mt][1] = As[kr + c    ][mb + g + 8];
                a[mt][2] = As[kr + c + 4][mb + g    ];
                a[mt][3] = As[kr + c + 4][mb + g + 8];
            }
            #pragma unroll
            for (int nt = 0; nt < 4; nt++) {
                int nb = wn * 32 + nt * 8;
                b[nt][0] = Bs[kr + c    ][nb + g];
                b[nt][1] = Bs[kr + c + 4][nb + g];
            }
            #pragma unroll
            for (int mt = 0; mt < 2; mt++)
                #pragma unroll
                for (int nt = 0; nt < 4; nt++)
                    mma_tf32(acc[mt][nt], a[mt], b[nt]);
        }
        __syncthreads();
    }

    #pragma unroll
    for (int mt = 0; mt < 2; mt++) {
        int row = m0 + wm * 32 + mt * 16 + g;
        #pragma unroll
        for (int nt = 0; nt < 4; nt++) {
            int col = n0 + wn * 32 + nt * 8 + 2 * c;
            float2 v0 = make_float2(acc[mt][nt][0], acc[mt][nt][1]);
            float2 v1 = make_float2(acc[mt][nt][2], acc[mt][nt][3]);
            *(float2*)(C + (size_t)row * N + col)       = v0;
            *(float2*)(C + (size_t)(row + 8) * N + col) = v1;
        }
    }
}

// ---------------------------------------------------------------------------
// Generic multi-job FFMA SGEMM (stage-1/2 MLPs stay fp32)
// ---------------------------------------------------------------------------
#define GBM 128
#define GBN 64
#define GBK 16

struct GemmJobs {
    int count;
    int tileStart[5];
    const float* A[4];
    const float* Bm[4];
    float*       Cm[4];
    int N[4];
    int K[4];
    int transb[4];
    int act[4];
    const float* bias[4];
    const float* aux1[4];
    const float* aux2[4];
};

__global__ __launch_bounds__(256, 2) void gemm_multi(GemmJobs J)
{
    __shared__ __align__(16) float As[GBK][GBM + 4];
    __shared__ __align__(16) float Bs[GBK][GBN + 4];

    int bx = blockIdx.x;
    int j = 0;
    while (bx >= J.tileStart[j + 1]) ++j;
    int n0 = (bx - J.tileStart[j]) * GBN;
    int m0 = blockIdx.y * GBM;

    const float* A = J.A[j];
    const float* B = J.Bm[j];
    float*       C = J.Cm[j];
    const int N = J.N[j];
    const int K = J.K[j];
    const int tb = J.transb[j];

    int tid = threadIdx.x;
    int tx = tid & 15, ty = tid >> 4;

    float acc[8][4];
    #pragma unroll
    for (int im = 0; im < 8; im++)
        #pragma unroll
        for (int in = 0; in < 4; in++) acc[im][in] = 0.f;

    for (int k0 = 0; k0 < K; k0 += GBK) {
        #pragma unroll
        for (int it = 0; it < 2; it++) {
            int lid = tid + it * 256;
            int row = lid >> 2, kc = lid & 3;
            float4 v = *(const float4*)(A + (size_t)(m0 + row) * K + k0 + kc * 4);
            As[kc*4+0][row] = v.x;
            As[kc*4+1][row] = v.y;
            As[kc*4+2][row] = v.z;
            As[kc*4+3][row] = v.w;
        }
        if (tb) {
            int row = tid >> 2, kc = tid & 3;
            float4 v = *(const float4*)(B + (size_t)(n0 + row) * K + k0 + kc * 4);
            Bs[kc*4+0][row] = v.x;
            Bs[kc*4+1][row] = v.y;
            Bs[kc*4+2][row] = v.z;
            Bs[kc*4+3][row] = v.w;
        } else {
            int kr = tid >> 4, c4 = (tid & 15) * 4;
            float4 v = make_float4(0.f, 0.f, 0.f, 0.f);
            if (n0 + c4 < N)
                v = *(const float4*)(B + (size_t)(k0 + kr) * N + n0 + c4);
            *(float4*)&Bs[kr][c4] = v;
        }
        __syncthreads();

        #pragma unroll
        for (int kk = 0; kk < GBK; kk++) {
            float4 bf = *(const float4*)&Bs[kk][tx * 4];
            float4 a0 = *(const float4*)&As[kk][ty * 8];
            float4 a1 = *(const float4*)&As[kk][ty * 8 + 4];
            float af[8] = {a0.x, a0.y, a0.z, a0.w, a1.x, a1.y, a1.z, a1.w};
            float bb2[4] = {bf.x, bf.y, bf.z, bf.w};
            #pragma unroll
            for (int im = 0; im < 8; im++)
                #pragma unroll
                for (int in = 0; in < 4; in++) acc[im][in] += af[im] * bb2[in];
        }
        __syncthreads();
    }

    const int act = J.act[j];
    const float* bias = J.bias[j];
    const float* aux1 = J.aux1[j];
    const float* aux2 = J.aux2[j];

    #pragma unroll
    for (int im = 0; im < 8; im++) {
        int row = m0 + ty * 8 + im;
        #pragma unroll
        for (int in = 0; in < 4; in++) {
            int col = n0 + tx * 4 + in;
            if (col < N) {
                size_t idx = (size_t)row * N + col;
                float v = acc[im][in];
                float o;
                if (act == 0) {
                    o = v;
                } else if (act == 1) {
                    o = tanhf(v);
                } else if (act == 2) {
                    float z = v + (bias ? bias[col] : 0.f);
                    o = 1.f / (1.f + expf(-z));
                } else if (act == 3) {
                    float z = v + bias[col];
                    float s = 1.f / (1.f + expf(-z));
                    o = expf(-0.60653065971263342f * s);
                } else {
                    float z = v + bias[col];
                    float s = 1.f / (1.f + expf(-z));
                    float vr = aux1[idx];
                    o = vr + (aux2[idx] - vr) * s;
                }
                C[idx] = o;
            }
        }
    }
}

// ---------------------------------------------------------------------------
// Kernel: post — kk normalization per head, k' update, aa=-kk, bb=kk*a
// ---------------------------------------------------------------------------
__global__ void post_kernel(const float* __restrict__ k_k, const float* __restrict__ k_a)
{
    int bt = blockIdx.x;
    int tid = threadIdx.x;
    int c = tid * 4;
    size_t base = (size_t)bt * CC + c;

    float4 kv = *(const float4*)(g_k + base);
    float4 av = *(const float4*)(g_a + base);
    float4 kkc = *(const float4*)(k_k + c);
    float4 kac = *(const float4*)(k_a + c);

    float4 kk;
    kk.x = kv.x * kkc.x; kk.y = kv.y * kkc.y; kk.z = kv.z * kkc.z; kk.w = kv.w * kkc.w;
    float ss = kk.x*kk.x + kk.y*kk.y + kk.z*kk.z + kk.w*kk.w;
    #pragma unroll
    for (int o = 1; o < 16; o <<= 1) ss += __shfl_xor_sync(0xffffffffu, ss, o);

    float nrm = sqrtf(ss);
    float inv = 1.f / fmaxf(nrm, 1e-12f);

    float4 aa, bb, kp;
    aa.x = -kk.x * inv; aa.y = -kk.y * inv; aa.z = -kk.z * inv; aa.w = -kk.w * inv;
    bb.x = kk.x * inv * av.x; bb.y = kk.y * inv * av.y;
    bb.z = kk.z * inv * av.z; bb.w = kk.w * inv * av.w;
    kp.x = kv.x * (1.f + (av.x - 1.f) * kac.x);
    kp.y = kv.y * (1.f + (av.y - 1.f) * kac.y);
    kp.z = kv.z * (1.f + (av.z - 1.f) * kac.z);
    kp.w = kv.w * (1.f + (av.w - 1.f) * kac.w);

    *(float4*)(g_aa + SPAD + base) = aa;
    *(float4*)(g_bb + SPAD + base) = bb;
    *(float4*)(g_kp + SPAD + base) = kp;
}

// ---------------------------------------------------------------------------
// Kernel: bidirectional WKV7 scan — 4 cols/thread, f32x2 packed math.
// grid = 128 blocks (dir*64 + b*16 + h*2 + rowgroup), 512 threads (16 warps,
// 4 warps/SMSP). thread (i = rg*32 + tid>>4, q = tid&15) owns row i,
// cols [q*4, q*4+4) as 2 packed f32x2 lanes. Branch-free depth-2 prefetch
// into padded arrays. 16-lane reductions: 4 shfl rounds, y & sa interleaved.
// ---------------------------------------------------------------------------
template<int CS, int NS>
__device__ __forceinline__ void scan_step(
    u64& S0, u64& S1,
    u64 (&R)[2][2], u64 (&D)[2][2], u64 (&Kk)[2][2],
    u64 (&Bf)[2][2], u64 (&Ab)[2][2], float (&Vb)[2],
    float& sa,
    const float*& pr2, const float*& pd2, const float*& pk2,
    const float*& pb2, const float*& pv2, const float*& pa3,
    float* py, int stride, int q)
{
    u64 sa2 = pack2(sa);
    u64 v2  = pack2(Vb[CS]);

    u64 t0 = fma2(sa2, Bf[CS][0], mul2(v2, Kk[CS][0]));
    S0 = fma2(S0, D[CS][0], t0);
    u64 t1 = fma2(sa2, Bf[CS][1], mul2(v2, Kk[CS][1]));
    S1 = fma2(S1, D[CS][1], t1);

    u64 y2 = fma2(S1, R[CS][1],  mul2(S0, R[CS][0]));
    u64 z2 = fma2(S1, Ab[NS][1], mul2(S0, Ab[NS][0]));
    float y   = sum2(y2);
    float sap = sum2(z2);

    // unconditional prefetch: streams for t+2 into slot CS, A for t+3 into NS
    {
        ulonglong2 rv = *(const ulonglong2*)pr2;
        ulonglong2 dv = *(const ulonglong2*)pd2;
        ulonglong2 kv = *(const ulonglong2*)pk2;
        ulonglong2 bv = *(const ulonglong2*)pb2;
        ulonglong2 av = *(const ulonglong2*)pa3;
        R[CS][0]  = rv.x; R[CS][1]  = rv.y;
        D[CS][0]  = dv.x; D[CS][1]  = dv.y;
        Kk[CS][0] = kv.x; Kk[CS][1] = kv.y;
        Bf[CS][0] = bv.x; Bf[CS][1] = bv.y;
        Ab[NS][0] = av.x; Ab[NS][1] = av.y;
        Vb[CS] = *pv2;
    }
    pr2 += stride; pd2 += stride; pk2 += stride; pb2 += stride;
    pv2 += stride; pa3 += stride;

    // interleaved 16-lane reductions
    y   += __shfl_xor_sync(0xffffffffu, y, 1);
    sap += __shfl_xor_sync(0xffffffffu, sap, 1);
    y   += __shfl_xor_sync(0xffffffffu, y, 2);
    sap += __shfl_xor_sync(0xffffffffu, sap, 2);
    y   += __shfl_xor_sync(0xffffffffu, y, 4);
    sap += __shfl_xor_sync(0xffffffffu, sap, 4);
    y   += __shfl_xor_sync(0xffffffffu, y, 8);
    sap += __shfl_xor_sync(0xffffffffu, sap, 8);

    if (q == 0) *py = y;
    sa = sap;
}

__global__ __launch_bounds__(512, 1) void scan_kernel()
{
    int bx = blockIdx.x;
    int dir = bx >> 6;
    int b   = (bx >> 4) & 3;
    int h   = (bx >> 1) & 7;
    int rg  = bx & 1;
    int tid = threadIdx.x;
    int i   = rg * 32 + (tid >> 4);
    int q   = tid & 15;
    int c0  = q * 4;

    int t0 = dir ? (TT - 1) : 0;
    int stride = dir ? -CC : CC;
    size_t off = SPAD + (size_t)(b * TT + t0) * CC + h * NN;

    const float* pr = g_r   + off + c0;
    const float* pd = g_dec + off + c0;
    const float* pk = g_kp  + off + c0;
    const float* pa = g_aa  + off + c0;
    const float* pb = g_bb  + off + c0;
    const float* pv = g_v   + off + i;
    float* py = (dir ? g_yb : g_yf) + (off - SPAD) + i;

    u64 S0 = 0, S1 = 0;
    u64 R[2][2], D[2][2], Kk[2][2], Bf[2][2], Ab[2][2];
    float Vb[2];

    // prologue: slot0 = t0, slot1 = t0+1; A[1] = a(t+1), A[0] = a(t+2)
    {
        ulonglong2 v;
        v = *(const ulonglong2*)pr;              R[0][0]=v.x;  R[0][1]=v.y;
        v = *(const ulonglong2*)(pr + stride);   R[1][0]=v.x;  R[1][1]=v.y;
        v = *(const ulonglong2*)pd;              D[0][0]=v.x;  D[0][1]=v.y;
        v = *(const ulonglong2*)(pd + stride);   D[1][0]=v.x;  D[1][1]=v.y;
        v = *(const ulonglong2*)pk;              Kk[0][0]=v.x; Kk[0][1]=v.y;
        v = *(const ulonglong2*)(pk + stride);   Kk[1][0]=v.x; Kk[1][1]=v.y;
        v = *(const ulonglong2*)pb;              Bf[0][0]=v.x; Bf[0][1]=v.y;
        v = *(const ulonglong2*)(pb + stride);   Bf[1][0]=v.x; Bf[1][1]=v.y;
        v = *(const ulonglong2*)(pa + stride);   Ab[1][0]=v.x; Ab[1][1]=v.y;
        v = *(const ulonglong2*)(pa + 2*stride); Ab[0][0]=v.x; Ab[0][1]=v.y;
    }
    Vb[0] = *pv;
    Vb[1] = *(pv + stride);

    const float* pr2 = pr + 2*stride;
    const float* pd2 = pd + 2*stride;
    const float* pk2 = pk + 2*stride;
    const float* pb2 = pb + 2*stride;
    const float* pv2 = pv + 2*stride;
    const float* pa3 = pa + 3*stride;

    float sa = 0.f;

    for (int t = 0; t < TT; t += 2) {
        scan_step<0,1>(S0, S1, R, D, Kk, Bf, Ab, Vb, sa,
                       pr2, pd2, pk2, pb2, pv2, pa3, py, stride, q);
        py += stride;
        scan_step<1,0>(S0, S1, R, D, Kk, Bf, Ab, Vb, sa,
                       pr2, pd2, pk2, pb2, pv2, pa3, py, stride, q);
        py += stride;
    }
}

// ---------------------------------------------------------------------------
// Kernel: combine — gate-mix fwd/bwd, groupnorm, residual, * g
// ---------------------------------------------------------------------------
__global__ void combine_kernel(const float* __restrict__ r_k,
                               const float* __restrict__ ln_g,
                               const float* __restrict__ ln_b)
{
    int bt = blockIdx.x;
    int tid = threadIdx.x;
    int c = tid * 4;
    int h = tid >> 4;
    size_t base = (size_t)bt * CC + c;

    float4 yf = *(const float4*)(g_yf + base);
    float4 yb = *(const float4*)(g_yb + base);
    float gate = g_gate[bt * HH + h];

    float4 xo;
    xo.x = gate * yf.x + (1.f - gate) * yb.x;
    xo.y = gate * yf.y + (1.f - gate) * yb.y;
    xo.z = gate * yf.z + (1.f - gate) * yb.z;
    xo.w = gate * yf.w + (1.f - gate) * yb.w;

    float4 rv = *(const float4*)(g_r + SPAD + base);
    float4 kp = *(const float4*)(g_kp + SPAD + base);
    float4 vv = *(const float4*)(g_v + SPAD + base);
    float4 gv = *(const float4*)(g_g + base);
    float4 rk = *(const float4*)(r_k + c);

    float sum = xo.x + xo.y + xo.z + xo.w;
    float sq  = xo.x*xo.x + xo.y*xo.y + xo.z*xo.z + xo.w*xo.w;
    float sres = rv.x*kp.x*rk.x + rv.y*kp.y*rk.y + rv.z*kp.z*rk.z + rv.w*kp.w*rk.w;
    #pragma unroll
    for (int o = 1; o < 16; o <<= 1) {
        sum  += __shfl_xor_sync(0xffffffffu, sum, o);
        sq   += __shfl_xor_sync(0xffffffffu, sq, o);
        sres += __shfl_xor_sync(0xffffffffu, sres, o);
    }
    float mu = sum * (1.f / 64.f);
    float var = sq * (1.f / 64.f) - mu * mu;
    float rstd = rsqrtf(var + 0.00064f);

    float4 lg = *(const float4*)(ln_g + c);
    float4 lb = *(const float4*)(ln_b + c);

    float4 z;
    z.x = ((xo.x - mu) * rstd * lg.x + lb.x + sres * vv.x) * gv.x;
    z.y = ((xo.y - mu) * rstd * lg.y + lb.y + sres * vv.y) * gv.y;
    z.z = ((xo.z - mu) * rstd * lg.z + lb.z + sres * vv.z) * gv.z;
    z.w = ((xo.w - mu) * rstd * lg.w + lb.w + sres * vv.w) * gv.w;
    *(float4*)(g_z + base) = z;
}

// ---------------------------------------------------------------------------
// Host launcher
// ---------------------------------------------------------------------------
static float *P_xr, *P_xw, *P_xk, *P_xv, *P_xa, *P_xg;
static float *P_r, *P_k, *P_vraw;
static float *P_hw, *P_ha, *P_hv, *P_hg;
static float *P_dec, *P_a, *P_v, *P_g;
static float *P_z;
static bool s_init = false;

extern "C" void kernel_launch(void* const* d_in, const int* in_sizes, int n_in,
                              void* d_out, int out_size)
{
    const float* x       = (const float*)d_in[0];
    const float* v_first = (const float*)d_in[1];
    const float* x_r = (const float*)d_in[2];
    const float* x_w = (const float*)d_in[3];
    const float* x_k = (const float*)d_in[4];
    const float* x_v = (const float*)d_in[5];
    const float* x_a = (const float*)d_in[6];
    const float* x_g = (const float*)d_in[7];
    const float* w0  = (const float*)d_in[8];
    const float* w1  = (const float*)d_in[9];
    const float* w2  = (const float*)d_in[10];
    const float* a0  = (const float*)d_in[11];
    const float* a1  = (const float*)d_in[12];
    const float* a2  = (const float*)d_in[13];
    const float* v0  = (const float*)d_in[14];
    const float* v1  = (const float*)d_in[15];
    const float* v2  = (const float*)d_in[16];
    const float* g1  = (const float*)d_in[17];
    const float* g2  = (const float*)d_in[18];
    const float* k_k = (const float*)d_in[19];
    const float* k_a = (const float*)d_in[20];
    const float* r_k = (const float*)d_in[21];
    const float* gate_w = (const float*)d_in[22];
    const float* ln_g = (const float*)d_in[23];
    const float* ln_b = (const float*)d_in[24];
    const float* Wr = (const float*)d_in[25];
    const float* Wk = (const float*)d_in[26];
    const float* Wv = (const float*)d_in[27];
    const float* Wo = (const float*)d_in[28];
    float* out = (float*)d_out;

    if (!s_init) {
        cudaGetSymbolAddress((void**)&P_xr, g_xr);
        cudaGetSymbolAddress((void**)&P_xw, g_xw);
        cudaGetSymbolAddress((void**)&P_xk, g_xk);
        cudaGetSymbolAddress((void**)&P_xv, g_xv);
        cudaGetSymbolAddress((void**)&P_xa, g_xa);
        cudaGetSymbolAddress((void**)&P_xg, g_xg);
        cudaGetSymbolAddress((void**)&P_r, g_r);       P_r   += SPAD;
        cudaGetSymbolAddress((void**)&P_k, g_k);
        cudaGetSymbolAddress((void**)&P_vraw, g_vraw);
        cudaGetSymbolAddress((void**)&P_hw, g_hw);
        cudaGetSymbolAddress((void**)&P_ha, g_ha);
        cudaGetSymbolAddress((void**)&P_hv, g_hv);
        cudaGetSymbolAddress((void**)&P_hg, g_hg);
        cudaGetSymbolAddress((void**)&P_dec, g_dec);   P_dec += SPAD;
        cudaGetSymbolAddress((void**)&P_a, g_a);
        cudaGetSymbolAddress((void**)&P_v, g_v);       P_v   += SPAD;
        cudaGetSymbolAddress((void**)&P_g, g_g);
        cudaGetSymbolAddress((void**)&P_z, g_z);
        s_init = true;
    }

    // 1) token shift + mixes + gate
    prep_kernel<<<BT, 128>>>(x, x_r, x_w, x_k, x_v, x_a, x_g, gate_w);

    // 2) big QKV GEMMs — tf32 tensor cores
    {
        QkvJobs J;
        J.A[0] = P_xr; J.W[0] = Wr; J.C[0] = P_r;
        J.A[1] = P_xk; J.W[1] = Wk; J.C[1] = P_k;
        J.A[2] = P_xv; J.W[2] = Wv; J.C[2] = P_vraw;
        gemm_tf32_nt<<<dim3(8, 32, 3), 256>>>(J);
    }

    // 3) stage-1 hidden GEMMs (fp32 FFMA — decay path precision)
    {
        GemmJobs J = {};
        J.count = 4;
        J.tileStart[0] = 0; J.tileStart[1] = 1; J.tileStart[2] = 2; J.tileStart[3] = 3; J.tileStart[4] = 5;
        J.A[0] = P_xw; J.Bm[0] = w1; J.Cm[0] = P_hw; J.N[0] = 64;  J.K[0] = 512; J.transb[0] = 0; J.act[0] = 1;
        J.A[1] = P_xa; J.Bm[1] = a1; J.Cm[1] = P_ha; J.N[1] = 64;  J.K[1] = 512; J.transb[1] = 0; J.act[1] = 0;
        J.A[2] = x;    J.Bm[2] = v1; J.Cm[2] = P_hv; J.N[2] = 32;  J.K[2] = 512; J.transb[2] = 0; J.act[2] = 0;
        J.A[3] = P_xg; J.Bm[3] = g1; J.Cm[3] = P_hg; J.N[3] = 128; J.K[3] = 512; J.transb[3] = 0; J.act[3] = 2;
        for (int jj = 0; jj < 4; jj++) { J.bias[jj] = nullptr; J.aux1[jj] = nullptr; J.aux2[jj] = nullptr; }
        gemm_multi<<<dim3(5, 32), 256>>>(J);
    }

    // 4) stage-2 GEMMs with fused epilogues (fp32 FFMA)
    {
        GemmJobs J = {};
        J.count = 4;
        J.tileStart[0] = 0; J.tileStart[1] = 8; J.tileStart[2] = 16; J.tileStart[3] = 24; J.tileStart[4] = 32;
        J.A[0] = P_hw; J.Bm[0] = w2; J.Cm[0] = P_dec; J.N[0] = 512; J.K[0] = 64;  J.transb[0] = 0; J.act[0] = 3;
        J.bias[0] = w0; J.aux1[0] = nullptr; J.aux2[0] = nullptr;
        J.A[1] = P_ha; J.Bm[1] = a2; J.Cm[1] = P_a; J.N[1] = 512; J.K[1] = 64;  J.transb[1] = 0; J.act[1] = 2;
        J.bias[1] = a0; J.aux1[1] = nullptr; J.aux2[1] = nullptr;
        J.A[2] = P_hv; J.Bm[2] = v2; J.Cm[2] = P_v; J.N[2] = 512; J.K[2] = 32;  J.transb[2] = 0; J.act[2] = 4;
        J.bias[2] = v0; J.aux1[2] = P_vraw; J.aux2[2] = v_first;
        J.A[3] = P_hg; J.Bm[3] = g2; J.Cm[3] = P_g; J.N[3] = 512; J.K[3] = 128; J.transb[3] = 0; J.act[3] = 0;
        J.bias[3] = nullptr; J.aux1[3] = nullptr; J.aux2[3] = nullptr;
        gemm_multi<<<dim3(32, 32), 256>>>(J);
    }

    // 5) kk normalize, k', aa, bb
    post_kernel<<<BT, 128>>>(k_k, k_a);

    // 6) bidirectional WKV7 scan — 128 blocks x 512 threads, f32x2
    scan_kernel<<<128, 512>>>();

    // 7) combine + groupnorm + residual + *g
    combine_kernel<<<BT, 128>>>(r_k, ln_g, ln_b);

    // 8) out = z @ Wo^T — tf32 tensor cores
    {
        QkvJobs J;
        J.A[0] = P_z; J.W[0] = Wo; J.C[0] = out;
        J.A[1] = P_z; J.W[1] = Wo; J.C[1] = out;
        J.A[2] = P_z; J.W[2] = Wo; J.C[2] = out;
        gemm_tf32_nt<<<dim3(8, 32, 1), 256>>>(J);
    }

    // 9) v_first passthrough if the flattened output includes it
    if (out_size >= 2 * BTC) {
        cudaMemcpyAsync(out + BTC, v_first, (size_t)BTC * sizeof(float),
                        cudaMemcpyDeviceToDevice, 0);
    }
}

// round 9
// speedup vs baseline: 1.2888x; 1.0833x over previous
#include <cuda_runtime.h>
#include <cstdint>
#include <math.h>

// Problem sizes (fixed)
#define BB   4
#define TT   1024
#define CC   512
#define HH   8
#define NN   64
#define BT   (BB*TT)        // 4096
#define BTC  (BT*CC)        // 2097152
#define SPAD (8*CC)         // over-read guard for branch-free depth-4 prefetch

typedef unsigned long long u64;

// ---------------------------------------------------------------------------
// Workspace (static __device__ arrays; no allocation at runtime)
// Scan operand arrays padded both sides; live data at [SPAD, SPAD+BTC).
// ---------------------------------------------------------------------------
__device__ float g_xr[BTC], g_xw[BTC], g_xk[BTC], g_xv[BTC], g_xa[BTC], g_xg[BTC];
__device__ float g_gate[BT*HH];
__device__ float g_k[BTC], g_vraw[BTC];
__device__ float g_hw[BT*64], g_ha[BT*64], g_hv[BT*32], g_hg[BT*128];
__device__ float g_a[BTC], g_g[BTC];
__device__ float g_r[BTC+2*SPAD], g_dec[BTC+2*SPAD], g_v[BTC+2*SPAD];
__device__ float g_kp[BTC+2*SPAD], g_aa[BTC+2*SPAD], g_bb[BTC+2*SPAD];
__device__ float g_yf[BTC], g_yb[BTC], g_z[BTC];

// ---------------------------------------------------------------------------
// f32x2 packed helpers (sm_100+)
// ---------------------------------------------------------------------------
__device__ __forceinline__ u64 fma2(u64 a, u64 b, u64 c) {
    u64 d; asm("fma.rn.f32x2 %0, %1, %2, %3;" : "=l"(d) : "l"(a), "l"(b), "l"(c));
    return d;
}
__device__ __forceinline__ u64 mul2(u64 a, u64 b) {
    u64 d; asm("mul.rn.f32x2 %0, %1, %2;" : "=l"(d) : "l"(a), "l"(b));
    return d;
}
__device__ __forceinline__ u64 pack2(float x) {
    u64 d; uint32_t r = __float_as_uint(x);
    asm("mov.b64 %0, {%1, %1};" : "=l"(d) : "r"(r));
    return d;
}
__device__ __forceinline__ float sum2(u64 a) {
    uint32_t lo, hi;
    asm("mov.b64 {%0, %1}, %2;" : "=r"(lo), "=r"(hi) : "l"(a));
    return __uint_as_float(lo) + __uint_as_float(hi);
}

// ---------------------------------------------------------------------------
// Kernel 1: token shift, six mixes, per-head gate
// ---------------------------------------------------------------------------
__global__ void prep_kernel(const float* __restrict__ x,
                            const float* __restrict__ mr, const float* __restrict__ mw,
                            const float* __restrict__ mk, const float* __restrict__ mv,
                            const float* __restrict__ ma, const float* __restrict__ mg,
                            const float* __restrict__ gate_w)
{
    int bt = blockIdx.x;
    int t  = bt & (TT - 1);
    int tid = threadIdx.x;
    int c  = tid * 4;
    size_t base = (size_t)bt * CC + c;

    float4 xc = *(const float4*)(x + base);
    float4 xp = make_float4(0.f, 0.f, 0.f, 0.f);
    if (t != 0) xp = *(const float4*)(x + base - CC);

    float4 xx;
    xx.x = xp.x - xc.x; xx.y = xp.y - xc.y; xx.z = xp.z - xc.z; xx.w = xp.w - xc.w;

#define MIXOUT(dst, mvptr)                                                    \
    { float4 m = *(const float4*)(mvptr + c); float4 o;                       \
      o.x = xc.x + xx.x * m.x; o.y = xc.y + xx.y * m.y;                       \
      o.z = xc.z + xx.z * m.z; o.w = xc.w + xx.w * m.w;                       \
      *(float4*)(dst + base) = o; }
    MIXOUT(g_xr, mr); MIXOUT(g_xw, mw); MIXOUT(g_xk, mk);
    MIXOUT(g_xv, mv); MIXOUT(g_xa, ma); MIXOUT(g_xg, mg);
#undef MIXOUT

    float4 gw = *(const float4*)(gate_w + c);
    float p = xx.x*gw.x + xx.y*gw.y + xx.z*gw.z + xx.w*gw.w;
    #pragma unroll
    for (int o = 1; o < 16; o <<= 1) p += __shfl_xor_sync(0xffffffffu, p, o);
    if ((tid & 15) == 0)
        g_gate[bt*HH + (tid >> 4)] = 1.f / (1.f + expf(-p));
}

// ---------------------------------------------------------------------------
// tf32 tensor-core GEMM: C = A[4096,512] @ W^T, W [512,512] row-major
// ---------------------------------------------------------------------------
struct QkvJobs {
    const float* A[3];
    const float* W[3];
    float*       C[3];
};

__device__ __forceinline__ uint32_t f2tf32(float x) {
    uint32_t r;
    asm("cvt.rna.tf32.f32 %0, %1;" : "=r"(r) : "f"(x));
    return r;
}

__device__ __forceinline__ void mma_tf32(float* d, const uint32_t* a, const uint32_t* b) {
    asm("mma.sync.aligned.m16n8k8.row.col.f32.tf32.tf32.f32 "
        "{%0,%1,%2,%3},{%4,%5,%6,%7},{%8,%9},{%0,%1,%2,%3};"
        : "+f"(d[0]), "+f"(d[1]), "+f"(d[2]), "+f"(d[3])
        : "r"(a[0]), "r"(a[1]), "r"(a[2]), "r"(a[3]), "r"(b[0]), "r"(b[1]));
}

__global__ __launch_bounds__(256, 2) void gemm_tf32_nt(QkvJobs J)
{
    const int K = 512, N = 512;
    const float* A = J.A[blockIdx.z];
    const float* W = J.W[blockIdx.z];
    float*       C = J.C[blockIdx.z];

    int m0 = blockIdx.y * 128;
    int n0 = blockIdx.x * 64;

    __shared__ uint32_t As[32][132];
    __shared__ uint32_t Bs[32][68];

    int tid  = threadIdx.x;
    int warp = tid >> 5, lane = tid & 31;
    int g = lane >> 2, c = lane & 3;
    int wm = warp & 3, wn = warp >> 2;

    float acc[2][4][4];
    #pragma unroll
    for (int mt = 0; mt < 2; mt++)
        #pragma unroll
        for (int nt = 0; nt < 4; nt++)
            #pragma unroll
            for (int r = 0; r < 4; r++) acc[mt][nt][r] = 0.f;

    for (int k0 = 0; k0 < K; k0 += 32) {
        #pragma unroll
        for (int it = 0; it < 4; it++) {
            int idx = tid + it * 256;
            int m = idx >> 3, kc = (idx & 7) * 4;
            float4 v = *(const float4*)(A + (size_t)(m0 + m) * K + k0 + kc);
            As[kc+0][m] = f2tf32(v.x);
            As[kc+1][m] = f2tf32(v.y);
            As[kc+2][m] = f2tf32(v.z);
            As[kc+3][m] = f2tf32(v.w);
        }
        #pragma unroll
        for (int it = 0; it < 2; it++) {
            int idx = tid + it * 256;
            int n = idx >> 3, kc = (idx & 7) * 4;
            float4 v = *(const float4*)(W + (size_t)(n0 + n) * K + k0 + kc);
            Bs[kc+0][n] = f2tf32(v.x);
            Bs[kc+1][n] = f2tf32(v.y);
            Bs[kc+2][n] = f2tf32(v.z);
            Bs[kc+3][n] = f2tf32(v.w);
        }
        __syncthreads();

        #pragma unroll
        for (int k8 = 0; k8 < 4; k8++) {
            int kr = k8 * 8;
            uint32_t a[2][4], b[4][2];
            #pragma unroll
            for (int mt = 0; mt < 2; mt++) {
                int mb = wm * 32 + mt * 16;
                a[mt][0] = As[kr + c    ][mb + g    ];
                a[mt][1] = As[kr + c    ][mb + g + 8];
                a[mt][2] = As[kr + c + 4][mb + g    ];
                a[mt][3] = As[kr + c + 4][mb + g + 8];
            }
            #pragma unroll
            for (int nt = 0; nt < 4; nt++) {
                int nb = wn * 32 + nt * 8;
                b[nt][0] = Bs[kr + c    ][nb + g];
                b[nt][1] = Bs[kr + c + 4][nb + g];
            }
            #pragma unroll
            for (int mt = 0; mt < 2; mt++)
                #pragma unroll
                for (int nt = 0; nt < 4; nt++)
                    mma_tf32(acc[mt][nt], a[mt], b[nt]);
        }
        __syncthreads();
    }

    #pragma unroll
    for (int mt = 0; mt < 2; mt++) {
        int row = m0 + wm * 32 + mt * 16 + g;
        #pragma unroll
        for (int nt = 0; nt < 4; nt++) {
            int col = n0 + wn * 32 + nt * 8 + 2 * c;
            float2 v0 = make_float2(acc[mt][nt][0], acc[mt][nt][1]);
            float2 v1 = make_float2(acc[mt][nt][2], acc[mt][nt][3]);
            *(float2*)(C + (size_t)row * N + col)       = v0;
            *(float2*)(C + (size_t)(row + 8) * N + col) = v1;
        }
    }
}

// ---------------------------------------------------------------------------
// Generic multi-job FFMA SGEMM (stage-1/2 MLPs stay fp32)
// ---------------------------------------------------------------------------
#define GBM 128
#define GBN 64
#define GBK 16

struct GemmJobs {
    int count;
    int tileStart[5];
    const float* A[4];
    const float* Bm[4];
    float*       Cm[4];
    int N[4];
    int K[4];
    int transb[4];
    int act[4];
    const float* bias[4];
    const float* aux1[4];
    const float* aux2[4];
};

__global__ __launch_bounds__(256, 2) void gemm_multi(GemmJobs J)
{
    __shared__ __align__(16) float As[GBK][GBM + 4];
    __shared__ __align__(16) float Bs[GBK][GBN + 4];

    int bx = blockIdx.x;
    int j = 0;
    while (bx >= J.tileStart[j + 1]) ++j;
    int n0 = (bx - J.tileStart[j]) * GBN;
    int m0 = blockIdx.y * GBM;

    const float* A = J.A[j];
    const float* B = J.Bm[j];
    float*       C = J.Cm[j];
    const int N = J.N[j];
    const int K = J.K[j];
    const int tb = J.transb[j];

    int tid = threadIdx.x;
    int tx = tid & 15, ty = tid >> 4;

    float acc[8][4];
    #pragma unroll
    for (int im = 0; im < 8; im++)
        #pragma unroll
        for (int in = 0; in < 4; in++) acc[im][in] = 0.f;

    for (int k0 = 0; k0 < K; k0 += GBK) {
        #pragma unroll
        for (int it = 0; it < 2; it++) {
            int lid = tid + it * 256;
            int row = lid >> 2, kc = lid & 3;
            float4 v = *(const float4*)(A + (size_t)(m0 + row) * K + k0 + kc * 4);
            As[kc*4+0][row] = v.x;
            As[kc*4+1][row] = v.y;
            As[kc*4+2][row] = v.z;
            As[kc*4+3][row] = v.w;
        }
        if (tb) {
            int row = tid >> 2, kc = tid & 3;
            float4 v = *(const float4*)(B + (size_t)(n0 + row) * K + k0 + kc * 4);
            Bs[kc*4+0][row] = v.x;
            Bs[kc*4+1][row] = v.y;
            Bs[kc*4+2][row] = v.z;
            Bs[kc*4+3][row] = v.w;
        } else {
            int kr = tid >> 4, c4 = (tid & 15) * 4;
            float4 v = make_float4(0.f, 0.f, 0.f, 0.f);
            if (n0 + c4 < N)
                v = *(const float4*)(B + (size_t)(k0 + kr) * N + n0 + c4);
            *(float4*)&Bs[kr][c4] = v;
        }
        __syncthreads();

        #pragma unroll
        for (int kk = 0; kk < GBK; kk++) {
            float4 bf = *(const float4*)&Bs[kk][tx * 4];
            float4 a0 = *(const float4*)&As[kk][ty * 8];
            float4 a1 = *(const float4*)&As[kk][ty * 8 + 4];
            float af[8] = {a0.x, a0.y, a0.z, a0.w, a1.x, a1.y, a1.z, a1.w};
            float bb2[4] = {bf.x, bf.y, bf.z, bf.w};
            #pragma unroll
            for (int im = 0; im < 8; im++)
                #pragma unroll
                for (int in = 0; in < 4; in++) acc[im][in] += af[im] * bb2[in];
        }
        __syncthreads();
    }

    const int act = J.act[j];
    const float* bias = J.bias[j];
    const float* aux1 = J.aux1[j];
    const float* aux2 = J.aux2[j];

    #pragma unroll
    for (int im = 0; im < 8; im++) {
        int row = m0 + ty * 8 + im;
        #pragma unroll
        for (int in = 0; in < 4; in++) {
            int col = n0 + tx * 4 + in;
            if (col < N) {
                size_t idx = (size_t)row * N + col;
                float v = acc[im][in];
                float o;
                if (act == 0) {
                    o = v;
                } else if (act == 1) {
                    o = tanhf(v);
                } else if (act == 2) {
                    float z = v + (bias ? bias[col] : 0.f);
                    o = 1.f / (1.f + expf(-z));
                } else if (act == 3) {
                    float z = v + bias[col];
                    float s = 1.f / (1.f + expf(-z));
                    o = expf(-0.60653065971263342f * s);
                } else {
                    float z = v + bias[col];
                    float s = 1.f / (1.f + expf(-z));
                    float vr = aux1[idx];
                    o = vr + (aux2[idx] - vr) * s;
                }
                C[idx] = o;
            }
        }
    }
}

// ---------------------------------------------------------------------------
// Kernel: post — kk normalization per head, k' update, aa=-kk, bb=kk*a
// ---------------------------------------------------------------------------
__global__ void post_kernel(const float* __restrict__ k_k, const float* __restrict__ k_a)
{
    int bt = blockIdx.x;
    int tid = threadIdx.x;
    int c = tid * 4;
    size_t base = (size_t)bt * CC + c;

    float4 kv = *(const float4*)(g_k + base);
    float4 av = *(const float4*)(g_a + base);
    float4 kkc = *(const float4*)(k_k + c);
    float4 kac = *(const float4*)(k_a + c);

    float4 kk;
    kk.x = kv.x * kkc.x; kk.y = kv.y * kkc.y; kk.z = kv.z * kkc.z; kk.w = kv.w * kkc.w;
    float ss = kk.x*kk.x + kk.y*kk.y + kk.z*kk.z + kk.w*kk.w;
    #pragma unroll
    for (int o = 1; o < 16; o <<= 1) ss += __shfl_xor_sync(0xffffffffu, ss, o);

    float nrm = sqrtf(ss);
    float inv = 1.f / fmaxf(nrm, 1e-12f);

    float4 aa, bb, kp;
    aa.x = -kk.x * inv; aa.y = -kk.y * inv; aa.z = -kk.z * inv; aa.w = -kk.w * inv;
    bb.x = kk.x * inv * av.x; bb.y = kk.y * inv * av.y;
    bb.z = kk.z * inv * av.z; bb.w = kk.w * inv * av.w;
    kp.x = kv.x * (1.f + (av.x - 1.f) * kac.x);
    kp.y = kv.y * (1.f + (av.y - 1.f) * kac.y);
    kp.z = kv.z * (1.f + (av.z - 1.f) * kac.z);
    kp.w = kv.w * (1.f + (av.w - 1.f) * kac.w);

    *(float4*)(g_aa + SPAD + base) = aa;
    *(float4*)(g_bb + SPAD + base) = bb;
    *(float4*)(g_kp + SPAD + base) = kp;
}

// ---------------------------------------------------------------------------
// Kernel: bidirectional WKV7 scan — 4 cols/thread, f32x2, DEPTH-4 prefetch.
// grid = 128 blocks (dir*64 + b*16 + h*2 + rowgroup), 512 threads (16 warps).
// thread (i = rg*32 + tid>>4, q = tid&15) owns row i, cols [q*4, q*4+4).
// Ring of 4 register buffers per stream; load-use distance = 4 steps so
// memory latency up to 4*T_step is covered. Branch-free via padded arrays.
// ---------------------------------------------------------------------------
template<int CS, int AS>
__device__ __forceinline__ void scan_step(
    u64& S0, u64& S1,
    u64 (&R)[4][2], u64 (&D)[4][2], u64 (&Kk)[4][2],
    u64 (&Bf)[4][2], u64 (&Ab)[4][2], float (&Vb)[4],
    float& sa,
    const float*& pr4, const float*& pd4, const float*& pk4,
    const float*& pb4, const float*& pv4, const float*& pa5,
    float* py, int stride, int q)
{
    u64 sa2 = pack2(sa);
    u64 v2  = pack2(Vb[CS]);

    u64 t0 = fma2(sa2, Bf[CS][0], mul2(v2, Kk[CS][0]));
    S0 = fma2(S0, D[CS][0], t0);
    u64 t1 = fma2(sa2, Bf[CS][1], mul2(v2, Kk[CS][1]));
    S1 = fma2(S1, D[CS][1], t1);

    u64 y2 = fma2(S1, R[CS][1],  mul2(S0, R[CS][0]));
    u64 z2 = fma2(S1, Ab[AS][1], mul2(S0, Ab[AS][0]));
    float y   = sum2(y2);
    float sap = sum2(z2);

    // unconditional prefetch: streams t+4 into just-freed slot CS,
    // A for t+5 into just-freed slot AS (padded arrays make this safe)
    {
        ulonglong2 rv = *(const ulonglong2*)pr4;
        ulonglong2 dv = *(const ulonglong2*)pd4;
        ulonglong2 kv = *(const ulonglong2*)pk4;
        ulonglong2 bv = *(const ulonglong2*)pb4;
        ulonglong2 av = *(const ulonglong2*)pa5;
        R[CS][0]  = rv.x; R[CS][1]  = rv.y;
        D[CS][0]  = dv.x; D[CS][1]  = dv.y;
        Kk[CS][0] = kv.x; Kk[CS][1] = kv.y;
        Bf[CS][0] = bv.x; Bf[CS][1] = bv.y;
        Ab[AS][0] = av.x; Ab[AS][1] = av.y;
        Vb[CS] = *pv4;
    }
    pr4 += stride; pd4 += stride; pk4 += stride; pb4 += stride;
    pv4 += stride; pa5 += stride;

    // interleaved 16-lane reductions
    y   += __shfl_xor_sync(0xffffffffu, y, 1);
    sap += __shfl_xor_sync(0xffffffffu, sap, 1);
    y   += __shfl_xor_sync(0xffffffffu, y, 2);
    sap += __shfl_xor_sync(0xffffffffu, sap, 2);
    y   += __shfl_xor_sync(0xffffffffu, y, 4);
    sap += __shfl_xor_sync(0xffffffffu, sap, 4);
    y   += __shfl_xor_sync(0xffffffffu, y, 8);
    sap += __shfl_xor_sync(0xffffffffu, sap, 8);

    if (q == 0) *py = y;
    sa = sap;
}

__global__ __launch_bounds__(512, 1) void scan_kernel()
{
    int bx = blockIdx.x;
    int dir = bx >> 6;
    int b   = (bx >> 4) & 3;
    int h   = (bx >> 1) & 7;
    int rg  = bx & 1;
    int tid = threadIdx.x;
    int i   = rg * 32 + (tid >> 4);
    int q   = tid & 15;
    int c0  = q * 4;

    int t0 = dir ? (TT - 1) : 0;
    int stride = dir ? -CC : CC;
    size_t off = SPAD + (size_t)(b * TT + t0) * CC + h * NN;

    const float* pr = g_r   + off + c0;
    const float* pd = g_dec + off + c0;
    const float* pk = g_kp  + off + c0;
    const float* pa = g_aa  + off + c0;
    const float* pb = g_bb  + off + c0;
    const float* pv = g_v   + off + i;
    float* py = (dir ? g_yb : g_yf) + (off - SPAD) + i;

    u64 S0 = 0, S1 = 0;
    u64 R[4][2], D[4][2], Kk[4][2], Bf[4][2], Ab[4][2];
    float Vb[4];

    // prologue: slots 0..3 = steps t0..t0+3; A slot (s+1)&3 = a(step s+1), s=0..3
    #pragma unroll
    for (int s = 0; s < 4; s++) {
        ulonglong2 v;
        v = *(const ulonglong2*)(pr + s*stride); R[s][0]=v.x;  R[s][1]=v.y;
        v = *(const ulonglong2*)(pd + s*stride); D[s][0]=v.x;  D[s][1]=v.y;
        v = *(const ulonglong2*)(pk + s*stride); Kk[s][0]=v.x; Kk[s][1]=v.y;
        v = *(const ulonglong2*)(pb + s*stride); Bf[s][0]=v.x; Bf[s][1]=v.y;
        v = *(const ulonglong2*)(pa + (s+1)*stride);
        Ab[(s+1)&3][0]=v.x; Ab[(s+1)&3][1]=v.y;
        Vb[s] = *(pv + s*stride);
    }

    const float* pr4 = pr + 4*stride;
    const float* pd4 = pd + 4*stride;
    const float* pk4 = pk + 4*stride;
    const float* pb4 = pb + 4*stride;
    const float* pv4 = pv + 4*stride;
    const float* pa5 = pa + 5*stride;

    float sa = 0.f;

    for (int t = 0; t < TT; t += 4) {
        scan_step<0,1>(S0, S1, R, D, Kk, Bf, Ab, Vb, sa,
                       pr4, pd4, pk4, pb4, pv4, pa5, py, stride, q);
        py += stride;
        scan_step<1,2>(S0, S1, R, D, Kk, Bf, Ab, Vb, sa,
                       pr4, pd4, pk4, pb4, pv4, pa5, py, stride, q);
        py += stride;
        scan_step<2,3>(S0, S1, R, D, Kk, Bf, Ab, Vb, sa,
                       pr4, pd4, pk4, pb4, pv4, pa5, py, stride, q);
        py += stride;
        scan_step<3,0>(S0, S1, R, D, Kk, Bf, Ab, Vb, sa,
                       pr4, pd4, pk4, pb4, pv4, pa5, py, stride, q);
        py += stride;
    }
}

// ---------------------------------------------------------------------------
// Kernel: combine — gate-mix fwd/bwd, groupnorm, residual, * g
// ---------------------------------------------------------------------------
__global__ void combine_kernel(const float* __restrict__ r_k,
                               const float* __restrict__ ln_g,
                               const float* __restrict__ ln_b)
{
    int bt = blockIdx.x;
    int tid = threadIdx.x;
    int c = tid * 4;
    int h = tid >> 4;
    size_t base = (size_t)bt * CC + c;

    float4 yf = *(const float4*)(g_yf + base);
    float4 yb = *(const float4*)(g_yb + base);
    float gate = g_gate[bt * HH + h];

    float4 xo;
    xo.x = gate * yf.x + (1.f - gate) * yb.x;
    xo.y = gate * yf.y + (1.f - gate) * yb.y;
    xo.z = gate * yf.z + (1.f - gate) * yb.z;
    xo.w = gate * yf.w + (1.f - gate) * yb.w;

    float4 rv = *(const float4*)(g_r + SPAD + base);
    float4 kp = *(const float4*)(g_kp + SPAD + base);
    float4 vv = *(const float4*)(g_v + SPAD + base);
    float4 gv = *(const float4*)(g_g + base);
    float4 rk = *(const float4*)(r_k + c);

    float sum = xo.x + xo.y + xo.z + xo.w;
    float sq  = xo.x*xo.x + xo.y*xo.y + xo.z*xo.z + xo.w*xo.w;
    float sres = rv.x*kp.x*rk.x + rv.y*kp.y*rk.y + rv.z*kp.z*rk.z + rv.w*kp.w*rk.w;
    #pragma unroll
    for (int o = 1; o < 16; o <<= 1) {
        sum  += __shfl_xor_sync(0xffffffffu, sum, o);
        sq   += __shfl_xor_sync(0xffffffffu, sq, o);
        sres += __shfl_xor_sync(0xffffffffu, sres, o);
    }
    float mu = sum * (1.f / 64.f);
    float var = sq * (1.f / 64.f) - mu * mu;
    float rstd = rsqrtf(var + 0.00064f);

    float4 lg = *(const float4*)(ln_g + c);
    float4 lb = *(const float4*)(ln_b + c);

    float4 z;
    z.x = ((xo.x - mu) * rstd * lg.x + lb.x + sres * vv.x) * gv.x;
    z.y = ((xo.y - mu) * rstd * lg.y + lb.y + sres * vv.y) * gv.y;
    z.z = ((xo.z - mu) * rstd * lg.z + lb.z + sres * vv.z) * gv.z;
    z.w = ((xo.w - mu) * rstd * lg.w + lb.w + sres * vv.w) * gv.w;
    *(float4*)(g_z + base) = z;
}

// ---------------------------------------------------------------------------
// Host launcher
// ---------------------------------------------------------------------------
static float *P_xr, *P_xw, *P_xk, *P_xv, *P_xa, *P_xg;
static float *P_r, *P_k, *P_vraw;
static float *P_hw, *P_ha, *P_hv, *P_hg;
static float *P_dec, *P_a, *P_v, *P_g;
static float *P_z;
static bool s_init = false;

extern "C" void kernel_launch(void* const* d_in, const int* in_sizes, int n_in,
                              void* d_out, int out_size)
{
    const float* x       = (const float*)d_in[0];
    const float* v_first = (const float*)d_in[1];
    const float* x_r = (const float*)d_in[2];
    const float* x_w = (const float*)d_in[3];
    const float* x_k = (const float*)d_in[4];
    const float* x_v = (const float*)d_in[5];
    const float* x_a = (const float*)d_in[6];
    const float* x_g = (const float*)d_in[7];
    const float* w0  = (const float*)d_in[8];
    const float* w1  = (const float*)d_in[9];
    const float* w2  = (const float*)d_in[10];
    const float* a0  = (const float*)d_in[11];
    const float* a1  = (const float*)d_in[12];
    const float* a2  = (const float*)d_in[13];
    const float* v0  = (const float*)d_in[14];
    const float* v1  = (const float*)d_in[15];
    const float* v2  = (const float*)d_in[16];
    const float* g1  = (const float*)d_in[17];
    const float* g2  = (const float*)d_in[18];
    const float* k_k = (const float*)d_in[19];
    const float* k_a = (const float*)d_in[20];
    const float* r_k = (const float*)d_in[21];
    const float* gate_w = (const float*)d_in[22];
    const float* ln_g = (const float*)d_in[23];
    const float* ln_b = (const float*)d_in[24];
    const float* Wr = (const float*)d_in[25];
    const float* Wk = (const float*)d_in[26];
    const float* Wv = (const float*)d_in[27];
    const float* Wo = (const float*)d_in[28];
    float* out = (float*)d_out;

    if (!s_init) {
        cudaGetSymbolAddress((void**)&P_xr, g_xr);
        cudaGetSymbolAddress((void**)&P_xw, g_xw);
        cudaGetSymbolAddress((void**)&P_xk, g_xk);
        cudaGetSymbolAddress((void**)&P_xv, g_xv);
        cudaGetSymbolAddress((void**)&P_xa, g_xa);
        cudaGetSymbolAddress((void**)&P_xg, g_xg);
        cudaGetSymbolAddress((void**)&P_r, g_r);       P_r   += SPAD;
        cudaGetSymbolAddress((void**)&P_k, g_k);
        cudaGetSymbolAddress((void**)&P_vraw, g_vraw);
        cudaGetSymbolAddress((void**)&P_hw, g_hw);
        cudaGetSymbolAddress((void**)&P_ha, g_ha);
        cudaGetSymbolAddress((void**)&P_hv, g_hv);
        cudaGetSymbolAddress((void**)&P_hg, g_hg);
        cudaGetSymbolAddress((void**)&P_dec, g_dec);   P_dec += SPAD;
        cudaGetSymbolAddress((void**)&P_a, g_a);
        cudaGetSymbolAddress((void**)&P_v, g_v);       P_v   += SPAD;
        cudaGetSymbolAddress((void**)&P_g, g_g);
        cudaGetSymbolAddress((void**)&P_z, g_z);
        s_init = true;
    }

    // 1) token shift + mixes + gate
    prep_kernel<<<BT, 128>>>(x, x_r, x_w, x_k, x_v, x_a, x_g, gate_w);

    // 2) big QKV GEMMs — tf32 tensor cores
    {
        QkvJobs J;
        J.A[0] = P_xr; J.W[0] = Wr; J.C[0] = P_r;
        J.A[1] = P_xk; J.W[1] = Wk; J.C[1] = P_k;
        J.A[2] = P_xv; J.W[2] = Wv; J.C[2] = P_vraw;
        gemm_tf32_nt<<<dim3(8, 32, 3), 256>>>(J);
    }

    // 3) stage-1 hidden GEMMs (fp32 FFMA — decay path precision)
    {
        GemmJobs J = {};
        J.count = 4;
        J.tileStart[0] = 0; J.tileStart[1] = 1; J.tileStart[2] = 2; J.tileStart[3] = 3; J.tileStart[4] = 5;
        J.A[0] = P_xw; J.Bm[0] = w1; J.Cm[0] = P_hw; J.N[0] = 64;  J.K[0] = 512; J.transb[0] = 0; J.act[0] = 1;
        J.A[1] = P_xa; J.Bm[1] = a1; J.Cm[1] = P_ha; J.N[1] = 64;  J.K[1] = 512; J.transb[1] = 0; J.act[1] = 0;
        J.A[2] = x;    J.Bm[2] = v1; J.Cm[2] = P_hv; J.N[2] = 32;  J.K[2] = 512; J.transb[2] = 0; J.act[2] = 0;
        J.A[3] = P_xg; J.Bm[3] = g1; J.Cm[3] = P_hg; J.N[3] = 128; J.K[3] = 512; J.transb[3] = 0; J.act[3] = 2;
        for (int jj = 0; jj < 4; jj++) { J.bias[jj] = nullptr; J.aux1[jj] = nullptr; J.aux2[jj] = nullptr; }
        gemm_multi<<<dim3(5, 32), 256>>>(J);
    }

    // 4) stage-2 GEMMs with fused epilogues (fp32 FFMA)
    {
        GemmJobs J = {};
        J.count = 4;
        J.tileStart[0] = 0; J.tileStart[1] = 8; J.tileStart[2] = 16; J.tileStart[3] = 24; J.tileStart[4] = 32;
        J.A[0] = P_hw; J.Bm[0] = w2; J.Cm[0] = P_dec; J.N[0] = 512; J.K[0] = 64;  J.transb[0] = 0; J.act[0] = 3;
        J.bias[0] = w0; J.aux1[0] = nullptr; J.aux2[0] = nullptr;
        J.A[1] = P_ha; J.Bm[1] = a2; J.Cm[1] = P_a; J.N[1] = 512; J.K[1] = 64;  J.transb[1] = 0; J.act[1] = 2;
        J.bias[1] = a0; J.aux1[1] = nullptr; J.aux2[1] = nullptr;
        J.A[2] = P_hv; J.Bm[2] = v2; J.Cm[2] = P_v; J.N[2] = 512; J.K[2] = 32;  J.transb[2] = 0; J.act[2] = 4;
        J.bias[2] = v0; J.aux1[2] = P_vraw; J.aux2[2] = v_first;
        J.A[3] = P_hg; J.Bm[3] = g2; J.Cm[3] = P_g; J.N[3] = 512; J.K[3] = 128; J.transb[3] = 0; J.act[3] = 0;
        J.bias[3] = nullptr; J.aux1[3] = nullptr; J.aux2[3] = nullptr;
        gemm_multi<<<dim3(32, 32), 256>>>(J);
    }

    // 5) kk normalize, k', aa, bb
    post_kernel<<<BT, 128>>>(k_k, k_a);

    // 6) bidirectional WKV7 scan — depth-4 prefetch
    scan_kernel<<<128, 512>>>();

    // 7) combine + groupnorm + residual + *g
    combine_kernel<<<BT, 128>>>(r_k, ln_g, ln_b);

    // 8) out = z @ Wo^T — tf32 tensor cores
    {
        QkvJobs J;
        J.A[0] = P_z; J.W[0] = Wo; J.C[0] = out;
        J.A[1] = P_z; J.W[1] = Wo; J.C[1] = out;
        J.A[2] = P_z; J.W[2] = Wo; J.C[2] = out;
        gemm_tf32_nt<<<dim3(8, 32, 1), 256>>>(J);
    }

    // 9) v_first passthrough if the flattened output includes it
    if (out_size >= 2 * BTC) {
        cudaMemcpyAsync(out + BTC, v_first, (size_t)BTC * sizeof(float),
                        cudaMemcpyDeviceToDevice, 0);
    }
}

// round 11
// speedup vs baseline: 1.3295x; 1.0316x over previous
#include <cuda_runtime.h>
#include <cstdint>
#include <math.h>

// Problem sizes (fixed)
#define BB   4
#define TT   1024
#define CC   512
#define HH   8
#define NN   64
#define BT   (BB*TT)        // 4096
#define BTC  (BT*CC)        // 2097152
#define SPAD (10*CC)        // over-read guard for branch-free prefetch + drain
#define BKPAD (16*HH)

typedef unsigned long long u64;

// ---------------------------------------------------------------------------
// Workspace (static __device__ arrays; no allocation at runtime)
// Padded arrays: live data at [SPAD, SPAD+BTC).
// ---------------------------------------------------------------------------
__device__ float g_xr[BTC], g_xw[BTC], g_xk[BTC], g_xv[BTC], g_xa[BTC], g_xg[BTC];
__device__ float g_gate[BT*HH];
__device__ float g_k[BTC], g_vraw[BTC];
__device__ float g_hw[BT*64], g_ha[BT*64], g_hv[BT*32], g_hg[BT*128];
__device__ float g_a[BTC], g_g[BTC];
__device__ float g_r[BTC+2*SPAD], g_dec[BTC+2*SPAD], g_v[BTC+2*SPAD];
__device__ float g_kp[BTC+2*SPAD], g_aa[BTC+2*SPAD], g_bb[BTC+2*SPAD];
__device__ float g_af[BTC+2*SPAD], g_ab[BTC+2*SPAD];      // A' = dec_prev ∘ aa
__device__ float2 g_bkf[BT*HH + 2*BKPAD], g_bkb[BT*HH + 2*BKPAD]; // (beta,kappa)
__device__ float g_yf[BTC+2*SPAD], g_yb[BTC+2*SPAD];
__device__ float g_z[BTC];

// ---------------------------------------------------------------------------
// f32x2 packed helpers (sm_100+)
// ---------------------------------------------------------------------------
__device__ __forceinline__ u64 fma2(u64 a, u64 b, u64 c) {
    u64 d; asm("fma.rn.f32x2 %0, %1, %2, %3;" : "=l"(d) : "l"(a), "l"(b), "l"(c));
    return d;
}
__device__ __forceinline__ u64 mul2(u64 a, u64 b) {
    u64 d; asm("mul.rn.f32x2 %0, %1, %2;" : "=l"(d) : "l"(a), "l"(b));
    return d;
}
__device__ __forceinline__ u64 pack2(float x) {
    u64 d; uint32_t r = __float_as_uint(x);
    asm("mov.b64 %0, {%1, %1};" : "=l"(d) : "r"(r));
    return d;
}
__device__ __forceinline__ float sum2(u64 a) {
    uint32_t lo, hi;
    asm("mov.b64 {%0, %1}, %2;" : "=r"(lo), "=r"(hi) : "l"(a));
    return __uint_as_float(lo) + __uint_as_float(hi);
}

// ---------------------------------------------------------------------------
// Kernel 1: token shift, six mixes, per-head gate
// ---------------------------------------------------------------------------
__global__ void prep_kernel(const float* __restrict__ x,
                            const float* __restrict__ mr, const float* __restrict__ mw,
                            const float* __restrict__ mk, const float* __restrict__ mv,
                            const float* __restrict__ ma, const float* __restrict__ mg,
                            const float* __restrict__ gate_w)
{
    int bt = blockIdx.x;
    int t  = bt & (TT - 1);
    int tid = threadIdx.x;
    int c  = tid * 4;
    size_t base = (size_t)bt * CC + c;

    float4 xc = *(const float4*)(x + base);
    float4 xp = make_float4(0.f, 0.f, 0.f, 0.f);
    if (t != 0) xp = *(const float4*)(x + base - CC);

    float4 xx;
    xx.x = xp.x - xc.x; xx.y = xp.y - xc.y; xx.z = xp.z - xc.z; xx.w = xp.w - xc.w;

#define MIXOUT(dst, mvptr)                                                    \
    { float4 m = *(const float4*)(mvptr + c); float4 o;                       \
      o.x = xc.x + xx.x * m.x; o.y = xc.y + xx.y * m.y;                       \
      o.z = xc.z + xx.z * m.z; o.w = xc.w + xx.w * m.w;                       \
      *(float4*)(dst + base) = o; }
    MIXOUT(g_xr, mr); MIXOUT(g_xw, mw); MIXOUT(g_xk, mk);
    MIXOUT(g_xv, mv); MIXOUT(g_xa, ma); MIXOUT(g_xg, mg);
#undef MIXOUT

    float4 gw = *(const float4*)(gate_w + c);
    float p = xx.x*gw.x + xx.y*gw.y + xx.z*gw.z + xx.w*gw.w;
    #pragma unroll
    for (int o = 1; o < 16; o <<= 1) p += __shfl_xor_sync(0xffffffffu, p, o);
    if ((tid & 15) == 0)
        g_gate[bt*HH + (tid >> 4)] = 1.f / (1.f + expf(-p));
}

// ---------------------------------------------------------------------------
// tf32 tensor-core GEMM: C = A[4096,512] @ W^T, W [512,512] row-major
// ---------------------------------------------------------------------------
struct QkvJobs {
    const float* A[3];
    const float* W[3];
    float*       C[3];
};

__device__ __forceinline__ uint32_t f2tf32(float x) {
    uint32_t r;
    asm("cvt.rna.tf32.f32 %0, %1;" : "=r"(r) : "f"(x));
    return r;
}

__device__ __forceinline__ void mma_tf32(float* d, const uint32_t* a, const uint32_t* b) {
    asm("mma.sync.aligned.m16n8k8.row.col.f32.tf32.tf32.f32 "
        "{%0,%1,%2,%3},{%4,%5,%6,%7},{%8,%9},{%0,%1,%2,%3};"
        : "+f"(d[0]), "+f"(d[1]), "+f"(d[2]), "+f"(d[3])
        : "r"(a[0]), "r"(a[1]), "r"(a[2]), "r"(a[3]), "r"(b[0]), "r"(b[1]));
}

__global__ __launch_bounds__(256, 2) void gemm_tf32_nt(QkvJobs J)
{
    const int K = 512, N = 512;
    const float* A = J.A[blockIdx.z];
    const float* W = J.W[blockIdx.z];
    float*       C = J.C[blockIdx.z];

    int m0 = blockIdx.y * 128;
    int n0 = blockIdx.x * 64;

    __shared__ uint32_t As[32][132];
    __shared__ uint32_t Bs[32][68];

    int tid  = threadIdx.x;
    int warp = tid >> 5, lane = tid & 31;
    int g = lane >> 2, c = lane & 3;
    int wm = warp & 3, wn = warp >> 2;

    float acc[2][4][4];
    #pragma unroll
    for (int mt = 0; mt < 2; mt++)
        #pragma unroll
        for (int nt = 0; nt < 4; nt++)
            #pragma unroll
            for (int r = 0; r < 4; r++) acc[mt][nt][r] = 0.f;

    for (int k0 = 0; k0 < K; k0 += 32) {
        #pragma unroll
        for (int it = 0; it < 4; it++) {
            int idx = tid + it * 256;
            int m = idx >> 3, kc = (idx & 7) * 4;
            float4 v = *(const float4*)(A + (size_t)(m0 + m) * K + k0 + kc);
            As[kc+0][m] = f2tf32(v.x);
            As[kc+1][m] = f2tf32(v.y);
            As[kc+2][m] = f2tf32(v.z);
            As[kc+3][m] = f2tf32(v.w);
        }
        #pragma unroll
        for (int it = 0; it < 2; it++) {
            int idx = tid + it * 256;
            int n = idx >> 3, kc = (idx & 7) * 4;
            float4 v = *(const float4*)(W + (size_t)(n0 + n) * K + k0 + kc);
            Bs[kc+0][n] = f2tf32(v.x);
            Bs[kc+1][n] = f2tf32(v.y);
            Bs[kc+2][n] = f2tf32(v.z);
            Bs[kc+3][n] = f2tf32(v.w);
        }
        __syncthreads();

        #pragma unroll
        for (int k8 = 0; k8 < 4; k8++) {
            int kr = k8 * 8;
            uint32_t a[2][4], b[4][2];
            #pragma unroll
            for (int mt = 0; mt < 2; mt++) {
                int mb = wm * 32 + mt * 16;
                a[mt][0] = As[kr + c    ][mb + g    ];
                a[mt][1] = As[kr + c    ][mb + g + 8];
                a[mt][2] = As[kr + c + 4][mb + g    ];
                a[mt][3] = As[kr + c + 4][mb + g + 8];
            }
            #pragma unroll
            for (int nt = 0; nt < 4; nt++) {
                int nb = wn * 32 + nt * 8;
                b[nt][0] = Bs[kr + c    ][nb + g];
                b[nt][1] = Bs[kr + c + 4][nb + g];
            }
            #pragma unroll
            for (int mt = 0; mt < 2; mt++)
                #pragma unroll
                for (int nt = 0; nt < 4; nt++)
                    mma_tf32(acc[mt][nt], a[mt], b[nt]);
        }
        __syncthreads();
    }

    #pragma unroll
    for (int mt = 0; mt < 2; mt++) {
        int row = m0 + wm * 32 + mt * 16 + g;
        #pragma unroll
        for (int nt = 0; nt < 4; nt++) {
            int col = n0 + wn * 32 + nt * 8 + 2 * c;
            float2 v0 = make_float2(acc[mt][nt][0], acc[mt][nt][1]);
            float2 v1 = make_float2(acc[mt][nt][2], acc[mt][nt][3]);
            *(float2*)(C + (size_t)row * N + col)       = v0;
            *(float2*)(C + (size_t)(row + 8) * N + col) = v1;
        }
    }
}

// ---------------------------------------------------------------------------
// Generic multi-job FFMA SGEMM (stage-1/2 MLPs stay fp32)
// ---------------------------------------------------------------------------
#define GBM 128
#define GBN 64
#define GBK 16

struct GemmJobs {
    int count;
    int tileStart[5];
    const float* A[4];
    const float* Bm[4];
    float*       Cm[4];
    int N[4];
    int K[4];
    int transb[4];
    int act[4];
    const float* bias[4];
    const float* aux1[4];
    const float* aux2[4];
};

__global__ __launch_bounds__(256, 2) void gemm_multi(GemmJobs J)
{
    __shared__ __align__(16) float As[GBK][GBM + 4];
    __shared__ __align__(16) float Bs[GBK][GBN + 4];

    int bx = blockIdx.x;
    int j = 0;
    while (bx >= J.tileStart[j + 1]) ++j;
    int n0 = (bx - J.tileStart[j]) * GBN;
    int m0 = blockIdx.y * GBM;

    const float* A = J.A[j];
    const float* B = J.Bm[j];
    float*       C = J.Cm[j];
    const int N = J.N[j];
    const int K = J.K[j];
    const int tb = J.transb[j];

    int tid = threadIdx.x;
    int tx = tid & 15, ty = tid >> 4;

    float acc[8][4];
    #pragma unroll
    for (int im = 0; im < 8; im++)
        #pragma unroll
        for (int in = 0; in < 4; in++) acc[im][in] = 0.f;

    for (int k0 = 0; k0 < K; k0 += GBK) {
        #pragma unroll
        for (int it = 0; it < 2; it++) {
            int lid = tid + it * 256;
            int row = lid >> 2, kc = lid & 3;
            float4 v = *(const float4*)(A + (size_t)(m0 + row) * K + k0 + kc * 4);
            As[kc*4+0][row] = v.x;
            As[kc*4+1][row] = v.y;
            As[kc*4+2][row] = v.z;
            As[kc*4+3][row] = v.w;
        }
        if (tb) {
            int row = tid >> 2, kc = tid & 3;
            float4 v = *(const float4*)(B + (size_t)(n0 + row) * K + k0 + kc * 4);
            Bs[kc*4+0][row] = v.x;
            Bs[kc*4+1][row] = v.y;
            Bs[kc*4+2][row] = v.z;
            Bs[kc*4+3][row] = v.w;
        } else {
            int kr = tid >> 4, c4 = (tid & 15) * 4;
            float4 v = make_float4(0.f, 0.f, 0.f, 0.f);
            if (n0 + c4 < N)
                v = *(const float4*)(B + (size_t)(k0 + kr) * N + n0 + c4);
            *(float4*)&Bs[kr][c4] = v;
        }
        __syncthreads();

        #pragma unroll
        for (int kk = 0; kk < GBK; kk++) {
            float4 bf = *(const float4*)&Bs[kk][tx * 4];
            float4 a0 = *(const float4*)&As[kk][ty * 8];
            float4 a1 = *(const float4*)&As[kk][ty * 8 + 4];
            float af[8] = {a0.x, a0.y, a0.z, a0.w, a1.x, a1.y, a1.z, a1.w};
            float bb2[4] = {bf.x, bf.y, bf.z, bf.w};
            #pragma unroll
            for (int im = 0; im < 8; im++)
                #pragma unroll
                for (int in = 0; in < 4; in++) acc[im][in] += af[im] * bb2[in];
        }
        __syncthreads();
    }

    const int act = J.act[j];
    const float* bias = J.bias[j];
    const float* aux1 = J.aux1[j];
    const float* aux2 = J.aux2[j];

    #pragma unroll
    for (int im = 0; im < 8; im++) {
        int row = m0 + ty * 8 + im;
        #pragma unroll
        for (int in = 0; in < 4; in++) {
            int col = n0 + tx * 4 + in;
            if (col < N) {
                size_t idx = (size_t)row * N + col;
                float v = acc[im][in];
                float o;
                if (act == 0) {
                    o = v;
                } else if (act == 1) {
                    o = tanhf(v);
                } else if (act == 2) {
                    float z = v + (bias ? bias[col] : 0.f);
                    o = 1.f / (1.f + expf(-z));
                } else if (act == 3) {
                    float z = v + bias[col];
                    float s = 1.f / (1.f + expf(-z));
                    o = expf(-0.60653065971263342f * s);
                } else {
                    float z = v + bias[col];
                    float s = 1.f / (1.f + expf(-z));
                    float vr = aux1[idx];
                    o = vr + (aux2[idx] - vr) * s;
                }
                C[idx] = o;
            }
        }
    }
}

// ---------------------------------------------------------------------------
// Kernel: post — kk normalization per head, k' update, aa=-kk, bb=kk*a
// ---------------------------------------------------------------------------
__global__ void post_kernel(const float* __restrict__ k_k, const float* __restrict__ k_a)
{
    int bt = blockIdx.x;
    int tid = threadIdx.x;
    int c = tid * 4;
    size_t base = (size_t)bt * CC + c;

    float4 kv = *(const float4*)(g_k + base);
    float4 av = *(const float4*)(g_a + base);
    float4 kkc = *(const float4*)(k_k + c);
    float4 kac = *(const float4*)(k_a + c);

    float4 kk;
    kk.x = kv.x * kkc.x; kk.y = kv.y * kkc.y; kk.z = kv.z * kkc.z; kk.w = kv.w * kkc.w;
    float ss = kk.x*kk.x + kk.y*kk.y + kk.z*kk.z + kk.w*kk.w;
    #pragma unroll
    for (int o = 1; o < 16; o <<= 1) ss += __shfl_xor_sync(0xffffffffu, ss, o);

    float nrm = sqrtf(ss);
    float inv = 1.f / fmaxf(nrm, 1e-12f);

    float4 aa, bb, kp;
    aa.x = -kk.x * inv; aa.y = -kk.y * inv; aa.z = -kk.z * inv; aa.w = -kk.w * inv;
    bb.x = kk.x * inv * av.x; bb.y = kk.y * inv * av.y;
    bb.z = kk.z * inv * av.z; bb.w = kk.w * inv * av.w;
    kp.x = kv.x * (1.f + (av.x - 1.f) * kac.x);
    kp.y = kv.y * (1.f + (av.y - 1.f) * kac.y);
    kp.z = kv.z * (1.f + (av.z - 1.f) * kac.z);
    kp.w = kv.w * (1.f + (av.w - 1.f) * kac.w);

    *(float4*)(g_aa + SPAD + base) = aa;
    *(float4*)(g_bb + SPAD + base) = bb;
    *(float4*)(g_kp + SPAD + base) = kp;
}

// ---------------------------------------------------------------------------
// Kernel: prep2 — precompute A' streams and (beta,kappa) scalar streams.
// fwd:  A'_f[t] = dec[t-1]∘aa[t],  beta_f[t]=bb[t-1]·aa[t], kappa_f[t]=kp[t-1]·aa[t]
// bwd:  A'_b[t] = dec[t+1]∘aa[t],  beta_b[t]=bb[t+1]·aa[t], kappa_b[t]=kp[t+1]·aa[t]
// Boundaries (t=0 fwd / t=T-1 bwd) are zeros.
// ---------------------------------------------------------------------------
__global__ void prep2_kernel()
{
    int bt = blockIdx.x;
    int t  = bt & (TT - 1);
    int tid = threadIdx.x;
    int c = tid * 4;
    int h = tid >> 4;
    size_t base = SPAD + (size_t)bt * CC + c;

    float4 av = *(const float4*)(g_aa + base);
    float4 z4 = make_float4(0.f, 0.f, 0.f, 0.f);
    float4 dp = z4, bp = z4, kpv = z4, dn = z4, bn = z4, kn = z4;
    if (t != 0) {
        dp  = *(const float4*)(g_dec + base - CC);
        bp  = *(const float4*)(g_bb  + base - CC);
        kpv = *(const float4*)(g_kp  + base - CC);
    }
    if (t != TT - 1) {
        dn = *(const float4*)(g_dec + base + CC);
        bn = *(const float4*)(g_bb  + base + CC);
        kn = *(const float4*)(g_kp  + base + CC);
    }

    float4 af, ab;
    af.x = dp.x*av.x; af.y = dp.y*av.y; af.z = dp.z*av.z; af.w = dp.w*av.w;
    ab.x = dn.x*av.x; ab.y = dn.y*av.y; ab.z = dn.z*av.z; ab.w = dn.w*av.w;
    *(float4*)(g_af + base) = af;
    *(float4*)(g_ab + base) = ab;

    float bf_ = bp.x*av.x + bp.y*av.y + bp.z*av.z + bp.w*av.w;
    float kf_ = kpv.x*av.x + kpv.y*av.y + kpv.z*av.z + kpv.w*av.w;
    float bb_ = bn.x*av.x + bn.y*av.y + bn.z*av.z + bn.w*av.w;
    float kb_ = kn.x*av.x + kn.y*av.y + kn.z*av.z + kn.w*av.w;
    #pragma unroll
    for (int o = 1; o < 16; o <<= 1) {
        bf_ += __shfl_xor_sync(0xffffffffu, bf_, o);
        kf_ += __shfl_xor_sync(0xffffffffu, kf_, o);
        bb_ += __shfl_xor_sync(0xffffffffu, bb_, o);
        kb_ += __shfl_xor_sync(0xffffffffu, kb_, o);
    }
    if ((tid & 15) == 0) {
        g_bkf[BKPAD + bt*HH + h] = make_float2(bf_, kf_);
        g_bkb[BKPAD + bt*HH + h] = make_float2(bb_, kb_);
    }
}

// ---------------------------------------------------------------------------
// Kernel: bidirectional WKV7 scan — decoupled sa reduction (2-step slack),
// 2 rows/thread, 4 cols/row, f32x2, depth-4 prefetch, branch-free + drain.
// The lagged y-store is PREDICATED on the store position being inside the
// sequence: only steps 2..TT+1 actually store (fixes cross-sequence leak).
// ---------------------------------------------------------------------------
template<int CS>
__device__ __forceinline__ void scan_step(
    int tstep,
    u64& S0a, u64& S1a, u64& S0b, u64& S1b,
    u64 (&R)[4][2], u64 (&D)[4][2], u64 (&K)[4][2],
    u64 (&B)[4][2], u64 (&A2)[4][2],
    float (&V0)[4], float (&V1)[4], float2 (&BK)[4],
    float (&zf0)[2], float (&zf1)[2], float (&yf0)[2], float (&yf1)[2],
    float& sa_prev0, float& sa_prev1, float& vprev0, float& vprev1,
    const float*& pr4, const float*& pd4, const float*& pk4,
    const float*& pb4, const float*& pA6,
    const float*& pv04, const float*& pv14, const float2*& pbk4,
    float* py0, float* py1, int stride, int sbk, int q)
{
    constexpr int P = CS & 1;

    // (1) assemble sa_t from z reduced two steps ago + scalar fixup
    float2 bk = BK[CS];
    float sa0 = fmaf(vprev0, bk.y, fmaf(sa_prev0, bk.x, zf0[P]));
    float sa1 = fmaf(vprev1, bk.y, fmaf(sa_prev1, bk.x, zf1[P]));

    // (2) lagged store of y_{t-2} — only when the target is in-sequence
    if (q == 0 && (unsigned)(tstep - 2) < (unsigned)TT) {
        *py0 = yf0[P]; *py1 = yf1[P];
    }

    // (3) update S, partials
    u64 sa20 = pack2(sa0), sa21 = pack2(sa1);
    float v0s = V0[CS], v1s = V1[CS];
    u64 v20 = pack2(v0s), v21 = pack2(v1s);
    S0a = fma2(S0a, D[CS][0], fma2(sa20, B[CS][0], mul2(v20, K[CS][0])));
    S1a = fma2(S1a, D[CS][1], fma2(sa20, B[CS][1], mul2(v20, K[CS][1])));
    S0b = fma2(S0b, D[CS][0], fma2(sa21, B[CS][0], mul2(v21, K[CS][0])));
    S1b = fma2(S1b, D[CS][1], fma2(sa21, B[CS][1], mul2(v21, K[CS][1])));

    float ya = sum2(fma2(S1a, R[CS][1],  mul2(S0a, R[CS][0])));
    float za = sum2(fma2(S1a, A2[CS][1], mul2(S0a, A2[CS][0])));
    float yb = sum2(fma2(S1b, R[CS][1],  mul2(S0b, R[CS][0])));
    float zb = sum2(fma2(S1b, A2[CS][1], mul2(S0b, A2[CS][0])));

    // (4) carry scalars
    sa_prev0 = sa0; sa_prev1 = sa1; vprev0 = v0s; vprev1 = v1s;

    // (5) refill slot CS (unconditional; padded arrays)
    {
        ulonglong2 rv = *(const ulonglong2*)pr4;
        ulonglong2 dv = *(const ulonglong2*)pd4;
        ulonglong2 kv = *(const ulonglong2*)pk4;
        ulonglong2 bv = *(const ulonglong2*)pb4;
        ulonglong2 av = *(const ulonglong2*)pA6;
        R[CS][0]  = rv.x; R[CS][1]  = rv.y;
        D[CS][0]  = dv.x; D[CS][1]  = dv.y;
        K[CS][0]  = kv.x; K[CS][1]  = kv.y;
        B[CS][0]  = bv.x; B[CS][1]  = bv.y;
        A2[CS][0] = av.x; A2[CS][1] = av.y;
        V0[CS] = *pv04;
        V1[CS] = *pv14;
        BK[CS] = *pbk4;
    }
    pr4 += stride; pd4 += stride; pk4 += stride; pb4 += stride;
    pA6 += stride; pv04 += stride; pv14 += stride; pbk4 += sbk;

    // (6) interleaved 16-lane reductions — consumed at t+2
    #pragma unroll
    for (int o = 1; o < 16; o <<= 1) {
        ya += __shfl_xor_sync(0xffffffffu, ya, o);
        za += __shfl_xor_sync(0xffffffffu, za, o);
        yb += __shfl_xor_sync(0xffffffffu, yb, o);
        zb += __shfl_xor_sync(0xffffffffu, zb, o);
    }
    yf0[P] = ya; zf0[P] = za; yf1[P] = yb; zf1[P] = zb;
}

__global__ __launch_bounds__(256, 1) void scan_kernel()
{
    int bx = blockIdx.x;
    int dir = bx >> 6;
    int b   = (bx >> 4) & 3;
    int h   = (bx >> 1) & 7;
    int rg  = bx & 1;
    int tid = threadIdx.x;
    int rp  = tid >> 4;
    int q   = tid & 15;
    int c0  = q * 4;
    int i0  = rg * 32 + rp;
    int i1  = i0 + 16;

    int t0 = dir ? (TT - 1) : 0;
    int stride = dir ? -CC : CC;
    int sbk = dir ? -HH : HH;
    size_t off = SPAD + (size_t)(b * TT + t0) * CC + h * NN;

    const float* pr = g_r   + off + c0;
    const float* pd = g_dec + off + c0;
    const float* pk = g_kp  + off + c0;
    const float* pb = g_bb  + off + c0;
    const float* pA = (dir ? g_ab : g_af) + off + c0;
    const float* pv0 = g_v + off + i0;
    const float* pv1 = g_v + off + i1;
    const float2* pbk = (dir ? g_bkb : g_bkf) + BKPAD + (size_t)(b * TT + t0) * HH + h;

    float* ybase = (dir ? g_yb : g_yf);
    float* py0 = ybase + off + i0 - 2*stride;
    float* py1 = ybase + off + i1 - 2*stride;

    u64 S0a = 0, S1a = 0, S0b = 0, S1b = 0;
    u64 R[4][2], D[4][2], K[4][2], B[4][2], A2[4][2];
    float V0[4], V1[4];
    float2 BK[4];

    // prologue: slots s=0..3 hold step-s data; A2[s] = A'[s+2]; BK[s] = bk[s]
    #pragma unroll
    for (int s = 0; s < 4; s++) {
        ulonglong2 v;
        v = *(const ulonglong2*)(pr + s*stride);     R[s][0]=v.x;  R[s][1]=v.y;
        v = *(const ulonglong2*)(pd + s*stride);     D[s][0]=v.x;  D[s][1]=v.y;
        v = *(const ulonglong2*)(pk + s*stride);     K[s][0]=v.x;  K[s][1]=v.y;
        v = *(const ulonglong2*)(pb + s*stride);     B[s][0]=v.x;  B[s][1]=v.y;
        v = *(const ulonglong2*)(pA + (s+2)*stride); A2[s][0]=v.x; A2[s][1]=v.y;
        V0[s] = *(pv0 + s*stride);
        V1[s] = *(pv1 + s*stride);
        BK[s] = *(pbk + s*sbk);
    }

    const float* pr4  = pr + 4*stride;
    const float* pd4  = pd + 4*stride;
    const float* pk4  = pk + 4*stride;
    const float* pb4  = pb + 4*stride;
    const float* pA6  = pA + 6*stride;
    const float* pv04 = pv0 + 4*stride;
    const float* pv14 = pv1 + 4*stride;
    const float2* pbk4 = pbk + 4*sbk;

    // priming: z_{-2}=z_{-1}=0, sa_{-1}=0, v_{-1}=0 make steps 0,1 exact
    float zf0[2] = {0.f, 0.f}, zf1[2] = {0.f, 0.f};
    float yf0[2] = {0.f, 0.f}, yf1[2] = {0.f, 0.f};
    float sa_prev0 = 0.f, sa_prev1 = 0.f, vprev0 = 0.f, vprev1 = 0.f;

    // main loop + 4 drain iterations (stores lag by 2; guard keeps them in-seq)
    for (int t = 0; t < TT + 4; t += 4) {
        scan_step<0>(t+0, S0a,S1a,S0b,S1b, R,D,K,B,A2, V0,V1,BK, zf0,zf1,yf0,yf1,
                     sa_prev0,sa_prev1,vprev0,vprev1,
                     pr4,pd4,pk4,pb4,pA6,pv04,pv14,pbk4, py0,py1, stride,sbk,q);
        py0 += stride; py1 += stride;
        scan_step<1>(t+1, S0a,S1a,S0b,S1b, R,D,K,B,A2, V0,V1,BK, zf0,zf1,yf0,yf1,
                     sa_prev0,sa_prev1,vprev0,vprev1,
                     pr4,pd4,pk4,pb4,pA6,pv04,pv14,pbk4, py0,py1, stride,sbk,q);
        py0 += stride; py1 += stride;
        scan_step<2>(t+2, S0a,S1a,S0b,S1b, R,D,K,B,A2, V0,V1,BK, zf0,zf1,yf0,yf1,
                     sa_prev0,sa_prev1,vprev0,vprev1,
                     pr4,pd4,pk4,pb4,pA6,pv04,pv14,pbk4, py0,py1, stride,sbk,q);
        py0 += stride; py1 += stride;
        scan_step<3>(t+3, S0a,S1a,S0b,S1b, R,D,K,B,A2, V0,V1,BK, zf0,zf1,yf0,yf1,
                     sa_prev0,sa_prev1,vprev0,vprev1,
                     pr4,pd4,pk4,pb4,pA6,pv04,pv14,pbk4, py0,py1, stride,sbk,q);
        py0 += stride; py1 += stride;
    }
}

// ---------------------------------------------------------------------------
// Kernel: combine — gate-mix fwd/bwd, groupnorm, residual, * g
// ---------------------------------------------------------------------------
__global__ void combine_kernel(const float* __restrict__ r_k,
                               const float* __restrict__ ln_g,
                               const float* __restrict__ ln_b)
{
    int bt = blockIdx.x;
    int tid = threadIdx.x;
    int c = tid * 4;
    int h = tid >> 4;
    size_t base = (size_t)bt * CC + c;

    float4 yf = *(const float4*)(g_yf + SPAD + base);
    float4 yb = *(const float4*)(g_yb + SPAD + base);
    float gate = g_gate[bt * HH + h];

    float4 xo;
    xo.x = gate * yf.x + (1.f - gate) * yb.x;
    xo.y = gate * yf.y + (1.f - gate) * yb.y;
    xo.z = gate * yf.z + (1.f - gate) * yb.z;
    xo.w = gate * yf.w + (1.f - gate) * yb.w;

    float4 rv = *(const float4*)(g_r + SPAD + base);
    float4 kp = *(const float4*)(g_kp + SPAD + base);
    float4 vv = *(const float4*)(g_v + SPAD + base);
    float4 gv = *(const float4*)(g_g + base);
    float4 rk = *(const float4*)(r_k + c);

    float sum = xo.x + xo.y + xo.z + xo.w;
    float sq  = xo.x*xo.x + xo.y*xo.y + xo.z*xo.z + xo.w*xo.w;
    float sres = rv.x*kp.x*rk.x + rv.y*kp.y*rk.y + rv.z*kp.z*rk.z + rv.w*kp.w*rk.w;
    #pragma unroll
    for (int o = 1; o < 16; o <<= 1) {
        sum  += __shfl_xor_sync(0xffffffffu, sum, o);
        sq   += __shfl_xor_sync(0xffffffffu, sq, o);
        sres += __shfl_xor_sync(0xffffffffu, sres, o);
    }
    float mu = sum * (1.f / 64.f);
    float var = sq * (1.f / 64.f) - mu * mu;
    float rstd = rsqrtf(var + 0.00064f);

    float4 lg = *(const float4*)(ln_g + c);
    float4 lb = *(const float4*)(ln_b + c);

    float4 z;
    z.x = ((xo.x - mu) * rstd * lg.x + lb.x + sres * vv.x) * gv.x;
    z.y = ((xo.y - mu) * rstd * lg.y + lb.y + sres * vv.y) * gv.y;
    z.z = ((xo.z - mu) * rstd * lg.z + lb.z + sres * vv.z) * gv.z;
    z.w = ((xo.w - mu) * rstd * lg.w + lb.w + sres * vv.w) * gv.w;
    *(float4*)(g_z + base) = z;
}

// ---------------------------------------------------------------------------
// Host launcher
// ---------------------------------------------------------------------------
static float *P_xr, *P_xw, *P_xk, *P_xv, *P_xa, *P_xg;
static float *P_r, *P_k, *P_vraw;
static float *P_hw, *P_ha, *P_hv, *P_hg;
static float *P_dec, *P_a, *P_v, *P_g;
static float *P_z;
static bool s_init = false;

extern "C" void kernel_launch(void* const* d_in, const int* in_sizes, int n_in,
                              void* d_out, int out_size)
{
    const float* x       = (const float*)d_in[0];
    const float* v_first = (const float*)d_in[1];
    const float* x_r = (const float*)d_in[2];
    const float* x_w = (const float*)d_in[3];
    const float* x_k = (const float*)d_in[4];
    const float* x_v = (const float*)d_in[5];
    const float* x_a = (const float*)d_in[6];
    const float* x_g = (const float*)d_in[7];
    const float* w0  = (const float*)d_in[8];
    const float* w1  = (const float*)d_in[9];
    const float* w2  = (const float*)d_in[10];
    const float* a0  = (const float*)d_in[11];
    const float* a1  = (const float*)d_in[12];
    const float* a2  = (const float*)d_in[13];
    const float* v0  = (const float*)d_in[14];
    const float* v1  = (const float*)d_in[15];
    const float* v2  = (const float*)d_in[16];
    const float* g1  = (const float*)d_in[17];
    const float* g2  = (const float*)d_in[18];
    const float* k_k = (const float*)d_in[19];
    const float* k_a = (const float*)d_in[20];
    const float* r_k = (const float*)d_in[21];
    const float* gate_w = (const float*)d_in[22];
    const float* ln_g = (const float*)d_in[23];
    const float* ln_b = (const float*)d_in[24];
    const float* Wr = (const float*)d_in[25];
    const float* Wk = (const float*)d_in[26];
    const float* Wv = (const float*)d_in[27];
    const float* Wo = (const float*)d_in[28];
    float* out = (float*)d_out;

    if (!s_init) {
        cudaGetSymbolAddress((void**)&P_xr, g_xr);
        cudaGetSymbolAddress((void**)&P_xw, g_xw);
        cudaGetSymbolAddress((void**)&P_xk, g_xk);
        cudaGetSymbolAddress((void**)&P_xv, g_xv);
        cudaGetSymbolAddress((void**)&P_xa, g_xa);
        cudaGetSymbolAddress((void**)&P_xg, g_xg);
        cudaGetSymbolAddress((void**)&P_r, g_r);       P_r   += SPAD;
        cudaGetSymbolAddress((void**)&P_k, g_k);
        cudaGetSymbolAddress((void**)&P_vraw, g_vraw);
        cudaGetSymbolAddress((void**)&P_hw, g_hw);
        cudaGetSymbolAddress((void**)&P_ha, g_ha);
        cudaGetSymbolAddress((void**)&P_hv, g_hv);
        cudaGetSymbolAddress((void**)&P_hg, g_hg);
        cudaGetSymbolAddress((void**)&P_dec, g_dec);   P_dec += SPAD;
        cudaGetSymbolAddress((void**)&P_a, g_a);
        cudaGetSymbolAddress((void**)&P_v, g_v);       P_v   += SPAD;
        cudaGetSymbolAddress((void**)&P_g, g_g);
        cudaGetSymbolAddress((void**)&P_z, g_z);
        s_init = true;
    }

    // 1) token shift + mixes + gate
    prep_kernel<<<BT, 128>>>(x, x_r, x_w, x_k, x_v, x_a, x_g, gate_w);

    // 2) big QKV GEMMs — tf32 tensor cores
    {
        QkvJobs J;
        J.A[0] = P_xr; J.W[0] = Wr; J.C[0] = P_r;
        J.A[1] = P_xk; J.W[1] = Wk; J.C[1] = P_k;
        J.A[2] = P_xv; J.W[2] = Wv; J.C[2] = P_vraw;
        gemm_tf32_nt<<<dim3(8, 32, 3), 256>>>(J);
    }

    // 3) stage-1 hidden GEMMs (fp32 FFMA — decay path precision)
    {
        GemmJobs J = {};
        J.count = 4;
        J.tileStart[0] = 0; J.tileStart[1] = 1; J.tileStart[2] = 2; J.tileStart[3] = 3; J.tileStart[4] = 5;
        J.A[0] = P_xw; J.Bm[0] = w1; J.Cm[0] = P_hw; J.N[0] = 64;  J.K[0] = 512; J.transb[0] = 0; J.act[0] = 1;
        J.A[1] = P_xa; J.Bm[1] = a1; J.Cm[1] = P_ha; J.N[1] = 64;  J.K[1] = 512; J.transb[1] = 0; J.act[1] = 0;
        J.A[2] = x;    J.Bm[2] = v1; J.Cm[2] = P_hv; J.N[2] = 32;  J.K[2] = 512; J.transb[2] = 0; J.act[2] = 0;
        J.A[3] = P_xg; J.Bm[3] = g1; J.Cm[3] = P_hg; J.N[3] = 128; J.K[3] = 512; J.transb[3] = 0; J.act[3] = 2;
        for (int jj = 0; jj < 4; jj++) { J.bias[jj] = nullptr; J.aux1[jj] = nullptr; J.aux2[jj] = nullptr; }
        gemm_multi<<<dim3(5, 32), 256>>>(J);
    }

    // 4) stage-2 GEMMs with fused epilogues (fp32 FFMA)
    {
        GemmJobs J = {};
        J.count = 4;
        J.tileStart[0] = 0; J.tileStart[1] = 8; J.tileStart[2] = 16; J.tileStart[3] = 24; J.tileStart[4] = 32;
        J.A[0] = P_hw; J.Bm[0] = w2; J.Cm[0] = P_dec; J.N[0] = 512; J.K[0] = 64;  J.transb[0] = 0; J.act[0] = 3;
        J.bias[0] = w0; J.aux1[0] = nullptr; J.aux2[0] = nullptr;
        J.A[1] = P_ha; J.Bm[1] = a2; J.Cm[1] = P_a; J.N[1] = 512; J.K[1] = 64;  J.transb[1] = 0; J.act[1] = 2;
        J.bias[1] = a0; J.aux1[1] = nullptr; J.aux2[1] = nullptr;
        J.A[2] = P_hv; J.Bm[2] = v2; J.Cm[2] = P_v; J.N[2] = 512; J.K[2] = 32;  J.transb[2] = 0; J.act[2] = 4;
        J.bias[2] = v0; J.aux1[2] = P_vraw; J.aux2[2] = v_first;
        J.A[3] = P_hg; J.Bm[3] = g2; J.Cm[3] = P_g; J.N[3] = 512; J.K[3] = 128; J.transb[3] = 0; J.act[3] = 0;
        J.bias[3] = nullptr; J.aux1[3] = nullptr; J.aux2[3] = nullptr;
        gemm_multi<<<dim3(32, 32), 256>>>(J);
    }

    // 5) kk normalize, k', aa, bb
    post_kernel<<<BT, 128>>>(k_k, k_a);

    // 5b) A' streams + (beta,kappa) scalars
    prep2_kernel<<<BT, 128>>>();

    // 6) bidirectional WKV7 scan — decoupled reduction (store leak fixed)
    scan_kernel<<<128, 256>>>();

    // 7) combine + groupnorm + residual + *g
    combine_kernel<<<BT, 128>>>(r_k, ln_g, ln_b);

    // 8) out = z @ Wo^T — tf32 tensor cores
    {
        QkvJobs J;
        J.A[0] = P_z; J.W[0] = Wo; J.C[0] = out;
        J.A[1] = P_z; J.W[1] = Wo; J.C[1] = out;
        J.A[2] = P_z; J.W[2] = Wo; J.C[2] = out;
        gemm_tf32_nt<<<dim3(8, 32, 1), 256>>>(J);
    }

    // 9) v_first passthrough if the flattened output includes it
    if (out_size >= 2 * BTC) {
        cudaMemcpyAsync(out + BTC, v_first, (size_t)BTC * sizeof(float),
                        cudaMemcpyDeviceToDevice, 0);
    }
}

// round 12
// speedup vs baseline: 1.3365x; 1.0053x over previous
#include <cuda_runtime.h>
#include <cstdint>
#include <math.h>

// Problem sizes (fixed)
#define BB   4
#define TT   1024
#define CC   512
#define HH   8
#define NN   64
#define BT   (BB*TT)        // 4096
#define BTC  (BT*CC)        // 2097152
#define SPAD (10*CC)        // over-read guard for branch-free prefetch + drain
#define BKPAD (16*HH)

typedef unsigned long long u64;

// ---------------------------------------------------------------------------
// Workspace (static __device__ arrays; no allocation at runtime)
// Padded arrays: live data at [SPAD, SPAD+BTC).
// ---------------------------------------------------------------------------
__device__ float g_gate[BT*HH];
__device__ float g_k[BTC], g_vraw[BTC];
__device__ float g_hw[BT*64], g_ha[BT*64], g_hv[BT*32], g_hg[BT*128];
__device__ float g_a[BTC], g_g[BTC];
__device__ float g_r[BTC+2*SPAD], g_dec[BTC+2*SPAD], g_v[BTC+2*SPAD];
__device__ float g_kp[BTC+2*SPAD], g_aa[BTC+2*SPAD], g_bb[BTC+2*SPAD];
__device__ float g_af[BTC+2*SPAD], g_ab[BTC+2*SPAD];      // A' = dec_prev ∘ aa
__device__ float2 g_bkf[BT*HH + 2*BKPAD], g_bkb[BT*HH + 2*BKPAD]; // (beta,kappa)
__device__ float g_yf[BTC+2*SPAD], g_yb[BTC+2*SPAD];
__device__ float g_z[BTC];

// ---------------------------------------------------------------------------
// f32x2 packed helpers (sm_100+)
// ---------------------------------------------------------------------------
__device__ __forceinline__ u64 fma2(u64 a, u64 b, u64 c) {
    u64 d; asm("fma.rn.f32x2 %0, %1, %2, %3;" : "=l"(d) : "l"(a), "l"(b), "l"(c));
    return d;
}
__device__ __forceinline__ u64 mul2(u64 a, u64 b) {
    u64 d; asm("mul.rn.f32x2 %0, %1, %2;" : "=l"(d) : "l"(a), "l"(b));
    return d;
}
__device__ __forceinline__ u64 pack2(float x) {
    u64 d; uint32_t r = __float_as_uint(x);
    asm("mov.b64 %0, {%1, %1};" : "=l"(d) : "r"(r));
    return d;
}
__device__ __forceinline__ float sum2(u64 a) {
    uint32_t lo, hi;
    asm("mov.b64 {%0, %1}, %2;" : "=r"(lo), "=r"(hi) : "l"(a));
    return __uint_as_float(lo) + __uint_as_float(hi);
}

// ---------------------------------------------------------------------------
// Kernel 1: per-head gate only (mixes fused into GEMM loaders)
// ---------------------------------------------------------------------------
__global__ void gate_kernel(const float* __restrict__ x,
                            const float* __restrict__ gate_w)
{
    int bt = blockIdx.x;
    int t  = bt & (TT - 1);
    int tid = threadIdx.x;
    int c  = tid * 4;
    size_t base = (size_t)bt * CC + c;

    float4 xc = *(const float4*)(x + base);
    float4 xp = make_float4(0.f, 0.f, 0.f, 0.f);
    if (t != 0) xp = *(const float4*)(x + base - CC);

    float4 gw = *(const float4*)(gate_w + c);
    float p = (xp.x - xc.x)*gw.x + (xp.y - xc.y)*gw.y
            + (xp.z - xc.z)*gw.z + (xp.w - xc.w)*gw.w;
    #pragma unroll
    for (int o = 1; o < 16; o <<= 1) p += __shfl_xor_sync(0xffffffffu, p, o);
    if ((tid & 15) == 0)
        g_gate[bt*HH + (tid >> 4)] = 1.f / (1.f + expf(-p));
}

// ---------------------------------------------------------------------------
// Fused mixed-A load helper: a[row][k] = x[row][k] + (x[row-1][k]-x[row][k])*mix[k]
// (row-1 in token space; zero at t==0). mix==null -> plain load.
// ---------------------------------------------------------------------------
__device__ __forceinline__ float4 load_mixed(const float* __restrict__ A,
                                             const float* __restrict__ mix,
                                             int row, int kc, int K)
{
    const float* ap = A + (size_t)row * K + kc;
    float4 xc = *(const float4*)ap;
    if (mix == nullptr) return xc;
    float4 xp = make_float4(0.f, 0.f, 0.f, 0.f);
    if (row & (TT - 1)) xp = *(const float4*)(ap - CC);
    float4 mx = *(const float4*)(mix + kc);
    float4 o;
    o.x = xc.x + (xp.x - xc.x) * mx.x;
    o.y = xc.y + (xp.y - xc.y) * mx.y;
    o.z = xc.z + (xp.z - xc.z) * mx.z;
    o.w = xc.w + (xp.w - xc.w) * mx.w;
    return o;
}

// ---------------------------------------------------------------------------
// tf32 tensor-core GEMM: C = mixA(x)[4096,512] @ W^T, W [512,512] row-major
// ---------------------------------------------------------------------------
struct QkvJobs {
    const float* A[3];
    const float* W[3];
    float*       C[3];
    const float* mix[3];
};

__device__ __forceinline__ uint32_t f2tf32(float x) {
    uint32_t r;
    asm("cvt.rna.tf32.f32 %0, %1;" : "=r"(r) : "f"(x));
    return r;
}

__device__ __forceinline__ void mma_tf32(float* d, const uint32_t* a, const uint32_t* b) {
    asm("mma.sync.aligned.m16n8k8.row.col.f32.tf32.tf32.f32 "
        "{%0,%1,%2,%3},{%4,%5,%6,%7},{%8,%9},{%0,%1,%2,%3};"
        : "+f"(d[0]), "+f"(d[1]), "+f"(d[2]), "+f"(d[3])
        : "r"(a[0]), "r"(a[1]), "r"(a[2]), "r"(a[3]), "r"(b[0]), "r"(b[1]));
}

__global__ __launch_bounds__(256, 2) void gemm_tf32_nt(QkvJobs J)
{
    const int K = 512, N = 512;
    const float* A = J.A[blockIdx.z];
    const float* W = J.W[blockIdx.z];
    float*       C = J.C[blockIdx.z];
    const float* mix = J.mix[blockIdx.z];

    int m0 = blockIdx.y * 128;
    int n0 = blockIdx.x * 64;

    __shared__ uint32_t As[32][132];
    __shared__ uint32_t Bs[32][68];

    int tid  = threadIdx.x;
    int warp = tid >> 5, lane = tid & 31;
    int g = lane >> 2, c = lane & 3;
    int wm = warp & 3, wn = warp >> 2;

    float acc[2][4][4];
    #pragma unroll
    for (int mt = 0; mt < 2; mt++)
        #pragma unroll
        for (int nt = 0; nt < 4; nt++)
            #pragma unroll
            for (int r = 0; r < 4; r++) acc[mt][nt][r] = 0.f;

    for (int k0 = 0; k0 < K; k0 += 32) {
        #pragma unroll
        for (int it = 0; it < 4; it++) {
            int idx = tid + it * 256;
            int m = idx >> 3, kc = (idx & 7) * 4;
            float4 v = load_mixed(A, mix, m0 + m, k0 + kc, K);
            As[kc+0][m] = f2tf32(v.x);
            As[kc+1][m] = f2tf32(v.y);
            As[kc+2][m] = f2tf32(v.z);
            As[kc+3][m] = f2tf32(v.w);
        }
        #pragma unroll
        for (int it = 0; it < 2; it++) {
            int idx = tid + it * 256;
            int n = idx >> 3, kc = (idx & 7) * 4;
            float4 v = *(const float4*)(W + (size_t)(n0 + n) * K + k0 + kc);
            Bs[kc+0][n] = f2tf32(v.x);
            Bs[kc+1][n] = f2tf32(v.y);
            Bs[kc+2][n] = f2tf32(v.z);
            Bs[kc+3][n] = f2tf32(v.w);
        }
        __syncthreads();

        #pragma unroll
        for (int k8 = 0; k8 < 4; k8++) {
            int kr = k8 * 8;
            uint32_t a[2][4], b[4][2];
            #pragma unroll
            for (int mt = 0; mt < 2; mt++) {
                int mb = wm * 32 + mt * 16;
                a[mt][0] = As[kr + c    ][mb + g    ];
                a[mt][1] = As[kr + c    ][mb + g + 8];
                a[mt][2] = As[kr + c + 4][mb + g    ];
                a[mt][3] = As[kr + c + 4][mb + g + 8];
            }
            #pragma unroll
            for (int nt = 0; nt < 4; nt++) {
                int nb = wn * 32 + nt * 8;
                b[nt][0] = Bs[kr + c    ][nb + g];
                b[nt][1] = Bs[kr + c + 4][nb + g];
            }
            #pragma unroll
            for (int mt = 0; mt < 2; mt++)
                #pragma unroll
                for (int nt = 0; nt < 4; nt++)
                    mma_tf32(acc[mt][nt], a[mt], b[nt]);
        }
        __syncthreads();
    }

    #pragma unroll
    for (int mt = 0; mt < 2; mt++) {
        int row = m0 + wm * 32 + mt * 16 + g;
        #pragma unroll
        for (int nt = 0; nt < 4; nt++) {
            int col = n0 + wn * 32 + nt * 8 + 2 * c;
            float2 v0 = make_float2(acc[mt][nt][0], acc[mt][nt][1]);
            float2 v1 = make_float2(acc[mt][nt][2], acc[mt][nt][3]);
            *(float2*)(C + (size_t)row * N + col)       = v0;
            *(float2*)(C + (size_t)(row + 8) * N + col) = v1;
        }
    }
}

// ---------------------------------------------------------------------------
// Generic multi-job FFMA SGEMM (stage-1/2 MLPs stay fp32); fused-mix A loads
// ---------------------------------------------------------------------------
#define GBM 128
#define GBN 64
#define GBK 16

struct GemmJobs {
    int count;
    int tileStart[5];
    const float* A[4];
    const float* Bm[4];
    float*       Cm[4];
    int N[4];
    int K[4];
    int transb[4];
    int act[4];
    const float* bias[4];
    const float* aux1[4];
    const float* aux2[4];
    const float* mix[4];
};

__global__ __launch_bounds__(256, 2) void gemm_multi(GemmJobs J)
{
    __shared__ __align__(16) float As[GBK][GBM + 4];
    __shared__ __align__(16) float Bs[GBK][GBN + 4];

    int bx = blockIdx.x;
    int j = 0;
    while (bx >= J.tileStart[j + 1]) ++j;
    int n0 = (bx - J.tileStart[j]) * GBN;
    int m0 = blockIdx.y * GBM;

    const float* A = J.A[j];
    const float* B = J.Bm[j];
    float*       C = J.Cm[j];
    const int N = J.N[j];
    const int K = J.K[j];
    const int tb = J.transb[j];
    const float* mix = J.mix[j];

    int tid = threadIdx.x;
    int tx = tid & 15, ty = tid >> 4;

    float acc[8][4];
    #pragma unroll
    for (int im = 0; im < 8; im++)
        #pragma unroll
        for (int in = 0; in < 4; in++) acc[im][in] = 0.f;

    for (int k0 = 0; k0 < K; k0 += GBK) {
        #pragma unroll
        for (int it = 0; it < 2; it++) {
            int lid = tid + it * 256;
            int row = lid >> 2, kc = lid & 3;
            float4 v = load_mixed(A, mix, m0 + row, k0 + kc * 4, K);
            As[kc*4+0][row] = v.x;
            As[kc*4+1][row] = v.y;
            As[kc*4+2][row] = v.z;
            As[kc*4+3][row] = v.w;
        }
        if (tb) {
            int row = tid >> 2, kc = tid & 3;
            float4 v = *(const float4*)(B + (size_t)(n0 + row) * K + k0 + kc * 4);
            Bs[kc*4+0][row] = v.x;
            Bs[kc*4+1][row] = v.y;
            Bs[kc*4+2][row] = v.z;
            Bs[kc*4+3][row] = v.w;
        } else {
            int kr = tid >> 4, c4 = (tid & 15) * 4;
            float4 v = make_float4(0.f, 0.f, 0.f, 0.f);
            if (n0 + c4 < N)
                v = *(const float4*)(B + (size_t)(k0 + kr) * N + n0 + c4);
            *(float4*)&Bs[kr][c4] = v;
        }
        __syncthreads();

        #pragma unroll
        for (int kk = 0; kk < GBK; kk++) {
            float4 bf = *(const float4*)&Bs[kk][tx * 4];
            float4 a0 = *(const float4*)&As[kk][ty * 8];
            float4 a1 = *(const float4*)&As[kk][ty * 8 + 4];
            float af[8] = {a0.x, a0.y, a0.z, a0.w, a1.x, a1.y, a1.z, a1.w};
            float bb2[4] = {bf.x, bf.y, bf.z, bf.w};
            #pragma unroll
            for (int im = 0; im < 8; im++)
                #pragma unroll
                for (int in = 0; in < 4; in++) acc[im][in] += af[im] * bb2[in];
        }
        __syncthreads();
    }

    const int act = J.act[j];
    const float* bias = J.bias[j];
    const float* aux1 = J.aux1[j];
    const float* aux2 = J.aux2[j];

    #pragma unroll
    for (int im = 0; im < 8; im++) {
        int row = m0 + ty * 8 + im;
        #pragma unroll
        for (int in = 0; in < 4; in++) {
            int col = n0 + tx * 4 + in;
            if (col < N) {
                size_t idx = (size_t)row * N + col;
                float v = acc[im][in];
                float o;
                if (act == 0) {
                    o = v;
                } else if (act == 1) {
                    o = tanhf(v);
                } else if (act == 2) {
                    float z = v + (bias ? bias[col] : 0.f);
                    o = 1.f / (1.f + expf(-z));
                } else if (act == 3) {
                    float z = v + bias[col];
                    float s = 1.f / (1.f + expf(-z));
                    o = expf(-0.60653065971263342f * s);
                } else {
                    float z = v + bias[col];
                    float s = 1.f / (1.f + expf(-z));
                    float vr = aux1[idx];
                    o = vr + (aux2[idx] - vr) * s;
                }
                C[idx] = o;
            }
        }
    }
}

// ---------------------------------------------------------------------------
// Kernel: post — kk normalization per head, k' update, aa=-kk, bb=kk*a
// ---------------------------------------------------------------------------
__global__ void post_kernel(const float* __restrict__ k_k, const float* __restrict__ k_a)
{
    int bt = blockIdx.x;
    int tid = threadIdx.x;
    int c = tid * 4;
    size_t base = (size_t)bt * CC + c;

    float4 kv = *(const float4*)(g_k + base);
    float4 av = *(const float4*)(g_a + base);
    float4 kkc = *(const float4*)(k_k + c);
    float4 kac = *(const float4*)(k_a + c);

    float4 kk;
    kk.x = kv.x * kkc.x; kk.y = kv.y * kkc.y; kk.z = kv.z * kkc.z; kk.w = kv.w * kkc.w;
    float ss = kk.x*kk.x + kk.y*kk.y + kk.z*kk.z + kk.w*kk.w;
    #pragma unroll
    for (int o = 1; o < 16; o <<= 1) ss += __shfl_xor_sync(0xffffffffu, ss, o);

    float nrm = sqrtf(ss);
    float inv = 1.f / fmaxf(nrm, 1e-12f);

    float4 aa, bb, kp;
    aa.x = -kk.x * inv; aa.y = -kk.y * inv; aa.z = -kk.z * inv; aa.w = -kk.w * inv;
    bb.x = kk.x * inv * av.x; bb.y = kk.y * inv * av.y;
    bb.z = kk.z * inv * av.z; bb.w = kk.w * inv * av.w;
    kp.x = kv.x * (1.f + (av.x - 1.f) * kac.x);
    kp.y = kv.y * (1.f + (av.y - 1.f) * kac.y);
    kp.z = kv.z * (1.f + (av.z - 1.f) * kac.z);
    kp.w = kv.w * (1.f + (av.w - 1.f) * kac.w);

    *(float4*)(g_aa + SPAD + base) = aa;
    *(float4*)(g_bb + SPAD + base) = bb;
    *(float4*)(g_kp + SPAD + base) = kp;
}

// ---------------------------------------------------------------------------
// Kernel: prep2 — precompute A' streams and (beta,kappa) scalar streams.
// ---------------------------------------------------------------------------
__global__ void prep2_kernel()
{
    int bt = blockIdx.x;
    int t  = bt & (TT - 1);
    int tid = threadIdx.x;
    int c = tid * 4;
    int h = tid >> 4;
    size_t base = SPAD + (size_t)bt * CC + c;

    float4 av = *(const float4*)(g_aa + base);
    float4 z4 = make_float4(0.f, 0.f, 0.f, 0.f);
    float4 dp = z4, bp = z4, kpv = z4, dn = z4, bn = z4, kn = z4;
    if (t != 0) {
        dp  = *(const float4*)(g_dec + base - CC);
        bp  = *(const float4*)(g_bb  + base - CC);
        kpv = *(const float4*)(g_kp  + base - CC);
    }
    if (t != TT - 1) {
        dn = *(const float4*)(g_dec + base + CC);
        bn = *(const float4*)(g_bb  + base + CC);
        kn = *(const float4*)(g_kp  + base + CC);
    }

    float4 af, ab;
    af.x = dp.x*av.x; af.y = dp.y*av.y; af.z = dp.z*av.z; af.w = dp.w*av.w;
    ab.x = dn.x*av.x; ab.y = dn.y*av.y; ab.z = dn.z*av.z; ab.w = dn.w*av.w;
    *(float4*)(g_af + base) = af;
    *(float4*)(g_ab + base) = ab;

    float bf_ = bp.x*av.x + bp.y*av.y + bp.z*av.z + bp.w*av.w;
    float kf_ = kpv.x*av.x + kpv.y*av.y + kpv.z*av.z + kpv.w*av.w;
    float bb_ = bn.x*av.x + bn.y*av.y + bn.z*av.z + bn.w*av.w;
    float kb_ = kn.x*av.x + kn.y*av.y + kn.z*av.z + kn.w*av.w;
    #pragma unroll
    for (int o = 1; o < 16; o <<= 1) {
        bf_ += __shfl_xor_sync(0xffffffffu, bf_, o);
        kf_ += __shfl_xor_sync(0xffffffffu, kf_, o);
        bb_ += __shfl_xor_sync(0xffffffffu, bb_, o);
        kb_ += __shfl_xor_sync(0xffffffffu, kb_, o);
    }
    if ((tid & 15) == 0) {
        g_bkf[BKPAD + bt*HH + h] = make_float2(bf_, kf_);
        g_bkb[BKPAD + bt*HH + h] = make_float2(bb_, kb_);
    }
}

// ---------------------------------------------------------------------------
// Kernel: bidirectional WKV7 scan — decoupled sa reduction (2-step slack),
// 2 rows/thread, 4 cols/row, f32x2, depth-4 prefetch, branch-free + drain.
// Lagged y-store predicated to in-sequence positions.
// ---------------------------------------------------------------------------
template<int CS>
__device__ __forceinline__ void scan_step(
    int tstep,
    u64& S0a, u64& S1a, u64& S0b, u64& S1b,
    u64 (&R)[4][2], u64 (&D)[4][2], u64 (&K)[4][2],
    u64 (&B)[4][2], u64 (&A2)[4][2],
    float (&V0)[4], float (&V1)[4], float2 (&BK)[4],
    float (&zf0)[2], float (&zf1)[2], float (&yf0)[2], float (&yf1)[2],
    float& sa_prev0, float& sa_prev1, float& vprev0, float& vprev1,
    const float*& pr4, const float*& pd4, const float*& pk4,
    const float*& pb4, const float*& pA6,
    const float*& pv04, const float*& pv14, const float2*& pbk4,
    float* py0, float* py1, int stride, int sbk, int q)
{
    constexpr int P = CS & 1;

    float2 bk = BK[CS];
    float sa0 = fmaf(vprev0, bk.y, fmaf(sa_prev0, bk.x, zf0[P]));
    float sa1 = fmaf(vprev1, bk.y, fmaf(sa_prev1, bk.x, zf1[P]));

    if (q == 0 && (unsigned)(tstep - 2) < (unsigned)TT) {
        *py0 = yf0[P]; *py1 = yf1[P];
    }

    u64 sa20 = pack2(sa0), sa21 = pack2(sa1);
    float v0s = V0[CS], v1s = V1[CS];
    u64 v20 = pack2(v0s), v21 = pack2(v1s);
    S0a = fma2(S0a, D[CS][0], fma2(sa20, B[CS][0], mul2(v20, K[CS][0])));
    S1a = fma2(S1a, D[CS][1], fma2(sa20, B[CS][1], mul2(v20, K[CS][1])));
    S0b = fma2(S0b, D[CS][0], fma2(sa21, B[CS][0], mul2(v21, K[CS][0])));
    S1b = fma2(S1b, D[CS][1], fma2(sa21, B[CS][1], mul2(v21, K[CS][1])));

    float ya = sum2(fma2(S1a, R[CS][1],  mul2(S0a, R[CS][0])));
    float za = sum2(fma2(S1a, A2[CS][1], mul2(S0a, A2[CS][0])));
    float yb = sum2(fma2(S1b, R[CS][1],  mul2(S0b, R[CS][0])));
    float zb = sum2(fma2(S1b, A2[CS][1], mul2(S0b, A2[CS][0])));

    sa_prev0 = sa0; sa_prev1 = sa1; vprev0 = v0s; vprev1 = v1s;

    {
        ulonglong2 rv = *(const ulonglong2*)pr4;
        ulonglong2 dv = *(const ulonglong2*)pd4;
        ulonglong2 kv = *(const ulonglong2*)pk4;
        ulonglong2 bv = *(const ulonglong2*)pb4;
        ulonglong2 av = *(const ulonglong2*)pA6;
        R[CS][0]  = rv.x; R[CS][1]  = rv.y;
        D[CS][0]  = dv.x; D[CS][1]  = dv.y;
        K[CS][0]  = kv.x; K[CS][1]  = kv.y;
        B[CS][0]  = bv.x; B[CS][1]  = bv.y;
        A2[CS][0] = av.x; A2[CS][1] = av.y;
        V0[CS] = *pv04;
        V1[CS] = *pv14;
        BK[CS] = *pbk4;
    }
    pr4 += stride; pd4 += stride; pk4 += stride; pb4 += stride;
    pA6 += stride; pv04 += stride; pv14 += stride; pbk4 += sbk;

    #pragma unroll
    for (int o = 1; o < 16; o <<= 1) {
        ya += __shfl_xor_sync(0xffffffffu, ya, o);
        za += __shfl_xor_sync(0xffffffffu, za, o);
        yb += __shfl_xor_sync(0xffffffffu, yb, o);
        zb += __shfl_xor_sync(0xffffffffu, zb, o);
    }
    yf0[P] = ya; zf0[P] = za; yf1[P] = yb; zf1[P] = zb;
}

__global__ __launch_bounds__(256, 1) void scan_kernel()
{
    int bx = blockIdx.x;
    int dir = bx >> 6;
    int b   = (bx >> 4) & 3;
    int h   = (bx >> 1) & 7;
    int rg  = bx & 1;
    int tid = threadIdx.x;
    int rp  = tid >> 4;
    int q   = tid & 15;
    int c0  = q * 4;
    int i0  = rg * 32 + rp;
    int i1  = i0 + 16;

    int t0 = dir ? (TT - 1) : 0;
    int stride = dir ? -CC : CC;
    int sbk = dir ? -HH : HH;
    size_t off = SPAD + (size_t)(b * TT + t0) * CC + h * NN;

    const float* pr = g_r   + off + c0;
    const float* pd = g_dec + off + c0;
    const float* pk = g_kp  + off + c0;
    const float* pb = g_bb  + off + c0;
    const float* pA = (dir ? g_ab : g_af) + off + c0;
    const float* pv0 = g_v + off + i0;
    const float* pv1 = g_v + off + i1;
    const float2* pbk = (dir ? g_bkb : g_bkf) + BKPAD + (size_t)(b * TT + t0) * HH + h;

    float* ybase = (dir ? g_yb : g_yf);
    float* py0 = ybase + off + i0 - 2*stride;
    float* py1 = ybase + off + i1 - 2*stride;

    u64 S0a = 0, S1a = 0, S0b = 0, S1b = 0;
    u64 R[4][2], D[4][2], K[4][2], B[4][2], A2[4][2];
    float V0[4], V1[4];
    float2 BK[4];

    #pragma unroll
    for (int s = 0; s < 4; s++) {
        ulonglong2 v;
        v = *(const ulonglong2*)(pr + s*stride);     R[s][0]=v.x;  R[s][1]=v.y;
        v = *(const ulonglong2*)(pd + s*stride);     D[s][0]=v.x;  D[s][1]=v.y;
        v = *(const ulonglong2*)(pk + s*stride);     K[s][0]=v.x;  K[s][1]=v.y;
        v = *(const ulonglong2*)(pb + s*stride);     B[s][0]=v.x;  B[s][1]=v.y;
        v = *(const ulonglong2*)(pA + (s+2)*stride); A2[s][0]=v.x; A2[s][1]=v.y;
        V0[s] = *(pv0 + s*stride);
        V1[s] = *(pv1 + s*stride);
        BK[s] = *(pbk + s*sbk);
    }

    const float* pr4  = pr + 4*stride;
    const float* pd4  = pd + 4*stride;
    const float* pk4  = pk + 4*stride;
    const float* pb4  = pb + 4*stride;
    const float* pA6  = pA + 6*stride;
    const float* pv04 = pv0 + 4*stride;
    const float* pv14 = pv1 + 4*stride;
    const float2* pbk4 = pbk + 4*sbk;

    float zf0[2] = {0.f, 0.f}, zf1[2] = {0.f, 0.f};
    float yf0[2] = {0.f, 0.f}, yf1[2] = {0.f, 0.f};
    float sa_prev0 = 0.f, sa_prev1 = 0.f, vprev0 = 0.f, vprev1 = 0.f;

    for (int t = 0; t < TT + 4; t += 4) {
        scan_step<0>(t+0, S0a,S1a,S0b,S1b, R,D,K,B,A2, V0,V1,BK, zf0,zf1,yf0,yf1,
                     sa_prev0,sa_prev1,vprev0,vprev1,
                     pr4,pd4,pk4,pb4,pA6,pv04,pv14,pbk4, py0,py1, stride,sbk,q);
        py0 += stride; py1 += stride;
        scan_step<1>(t+1, S0a,S1a,S0b,S1b, R,D,K,B,A2, V0,V1,BK, zf0,zf1,yf0,yf1,
                     sa_prev0,sa_prev1,vprev0,vprev1,
                     pr4,pd4,pk4,pb4,pA6,pv04,pv14,pbk4, py0,py1, stride,sbk,q);
        py0 += stride; py1 += stride;
        scan_step<2>(t+2, S0a,S1a,S0b,S1b, R,D,K,B,A2, V0,V1,BK, zf0,zf1,yf0,yf1,
                     sa_prev0,sa_prev1,vprev0,vprev1,
                     pr4,pd4,pk4,pb4,pA6,pv04,pv14,pbk4, py0,py1, stride,sbk,q);
        py0 += stride; py1 += stride;
        scan_step<3>(t+3, S0a,S1a,S0b,S1b, R,D,K,B,A2, V0,V1,BK, zf0,zf1,yf0,yf1,
                     sa_prev0,sa_prev1,vprev0,vprev1,
                     pr4,pd4,pk4,pb4,pA6,pv04,pv14,pbk4, py0,py1, stride,sbk,q);
        py0 += stride; py1 += stride;
    }
}

// ---------------------------------------------------------------------------
// Kernel: combine — gate-mix fwd/bwd, groupnorm, residual, * g
// ---------------------------------------------------------------------------
__global__ void combine_kernel(const float* __restrict__ r_k,
                               const float* __restrict__ ln_g,
                               const float* __restrict__ ln_b)
{
    int bt = blockIdx.x;
    int tid = threadIdx.x;
    int c = tid * 4;
    int h = tid >> 4;
    size_t base = (size_t)bt * CC + c;

    float4 yf = *(const float4*)(g_yf + SPAD + base);
    float4 yb = *(const float4*)(g_yb + SPAD + base);
    float gate = g_gate[bt * HH + h];

    float4 xo;
    xo.x = gate * yf.x + (1.f - gate) * yb.x;
    xo.y = gate * yf.y + (1.f - gate) * yb.y;
    xo.z = gate * yf.z + (1.f - gate) * yb.z;
    xo.w = gate * yf.w + (1.f - gate) * yb.w;

    float4 rv = *(const float4*)(g_r + SPAD + base);
    float4 kp = *(const float4*)(g_kp + SPAD + base);
    float4 vv = *(const float4*)(g_v + SPAD + base);
    float4 gv = *(const float4*)(g_g + base);
    float4 rk = *(const float4*)(r_k + c);

    float sum = xo.x + xo.y + xo.z + xo.w;
    float sq  = xo.x*xo.x + xo.y*xo.y + xo.z*xo.z + xo.w*xo.w;
    float sres = rv.x*kp.x*rk.x + rv.y*kp.y*rk.y + rv.z*kp.z*rk.z + rv.w*kp.w*rk.w;
    #pragma unroll
    for (int o = 1; o < 16; o <<= 1) {
        sum  += __shfl_xor_sync(0xffffffffu, sum, o);
        sq   += __shfl_xor_sync(0xffffffffu, sq, o);
        sres += __shfl_xor_sync(0xffffffffu, sres, o);
    }
    float mu = sum * (1.f / 64.f);
    float var = sq * (1.f / 64.f) - mu * mu;
    float rstd = rsqrtf(var + 0.00064f);

    float4 lg = *(const float4*)(ln_g + c);
    float4 lb = *(const float4*)(ln_b + c);

    float4 z;
    z.x = ((xo.x - mu) * rstd * lg.x + lb.x + sres * vv.x) * gv.x;
    z.y = ((xo.y - mu) * rstd * lg.y + lb.y + sres * vv.y) * gv.y;
    z.z = ((xo.z - mu) * rstd * lg.z + lb.z + sres * vv.z) * gv.z;
    z.w = ((xo.w - mu) * rstd * lg.w + lb.w + sres * vv.w) * gv.w;
    *(float4*)(g_z + base) = z;
}

// ---------------------------------------------------------------------------
// Host launcher
// ---------------------------------------------------------------------------
static float *P_r, *P_k, *P_vraw;
static float *P_hw, *P_ha, *P_hv, *P_hg;
static float *P_dec, *P_a, *P_v, *P_g;
static float *P_z;
static bool s_init = false;

extern "C" void kernel_launch(void* const* d_in, const int* in_sizes, int n_in,
                              void* d_out, int out_size)
{
    const float* x       = (const float*)d_in[0];
    const float* v_first = (const float*)d_in[1];
    const float* x_r = (const float*)d_in[2];
    const float* x_w = (const float*)d_in[3];
    const float* x_k = (const float*)d_in[4];
    const float* x_v = (const float*)d_in[5];
    const float* x_a = (const float*)d_in[6];
    const float* x_g = (const float*)d_in[7];
    const float* w0  = (const float*)d_in[8];
    const float* w1  = (const float*)d_in[9];
    const float* w2  = (const float*)d_in[10];
    const float* a0  = (const float*)d_in[11];
    const float* a1  = (const float*)d_in[12];
    const float* a2  = (const float*)d_in[13];
    const float* v0  = (const float*)d_in[14];
    const float* v1  = (const float*)d_in[15];
    const float* v2  = (const float*)d_in[16];
    const float* g1  = (const float*)d_in[17];
    const float* g2  = (const float*)d_in[18];
    const float* k_k = (const float*)d_in[19];
    const float* k_a = (const float*)d_in[20];
    const float* r_k = (const float*)d_in[21];
    const float* gate_w = (const float*)d_in[22];
    const float* ln_g = (const float*)d_in[23];
    const float* ln_b = (const float*)d_in[24];
    const float* Wr = (const float*)d_in[25];
    const float* Wk = (const float*)d_in[26];
    const float* Wv = (const float*)d_in[27];
    const float* Wo = (const float*)d_in[28];
    float* out = (float*)d_out;

    if (!s_init) {
        cudaGetSymbolAddress((void**)&P_r, g_r);       P_r   += SPAD;
        cudaGetSymbolAddress((void**)&P_k, g_k);
        cudaGetSymbolAddress((void**)&P_vraw, g_vraw);
        cudaGetSymbolAddress((void**)&P_hw, g_hw);
        cudaGetSymbolAddress((void**)&P_ha, g_ha);
        cudaGetSymbolAddress((void**)&P_hv, g_hv);
        cudaGetSymbolAddress((void**)&P_hg, g_hg);
        cudaGetSymbolAddress((void**)&P_dec, g_dec);   P_dec += SPAD;
        cudaGetSymbolAddress((void**)&P_a, g_a);
        cudaGetSymbolAddress((void**)&P_v, g_v);       P_v   += SPAD;
        cudaGetSymbolAddress((void**)&P_g, g_g);
        cudaGetSymbolAddress((void**)&P_z, g_z);
        s_init = true;
    }

    // 1) per-head gate (mixes now fused into GEMM loaders)
    gate_kernel<<<BT, 128>>>(x, gate_w);

    // 2) big QKV GEMMs — tf32 tensor cores with fused token-shift mixing
    {
        QkvJobs J;
        J.A[0] = x; J.W[0] = Wr; J.C[0] = P_r;    J.mix[0] = x_r;
        J.A[1] = x; J.W[1] = Wk; J.C[1] = P_k;    J.mix[1] = x_k;
        J.A[2] = x; J.W[2] = Wv; J.C[2] = P_vraw; J.mix[2] = x_v;
        gemm_tf32_nt<<<dim3(8, 32, 3), 256>>>(J);
    }

    // 3) stage-1 hidden GEMMs (fp32 FFMA) with fused mixing
    {
        GemmJobs J = {};
        J.count = 4;
        J.tileStart[0] = 0; J.tileStart[1] = 1; J.tileStart[2] = 2; J.tileStart[3] = 3; J.tileStart[4] = 5;
        J.A[0] = x; J.Bm[0] = w1; J.Cm[0] = P_hw; J.N[0] = 64;  J.K[0] = 512; J.transb[0] = 0; J.act[0] = 1; J.mix[0] = x_w;
        J.A[1] = x; J.Bm[1] = a1; J.Cm[1] = P_ha; J.N[1] = 64;  J.K[1] = 512; J.transb[1] = 0; J.act[1] = 0; J.mix[1] = x_a;
        J.A[2] = x; J.Bm[2] = v1; J.Cm[2] = P_hv; J.N[2] = 32;  J.K[2] = 512; J.transb[2] = 0; J.act[2] = 0; J.mix[2] = nullptr;
        J.A[3] = x; J.Bm[3] = g1; J.Cm[3] = P_hg; J.N[3] = 128; J.K[3] = 512; J.transb[3] = 0; J.act[3] = 2; J.mix[3] = x_g;
        for (int jj = 0; jj < 4; jj++) { J.bias[jj] = nullptr; J.aux1[jj] = nullptr; J.aux2[jj] = nullptr; }
        gemm_multi<<<dim3(5, 32), 256>>>(J);
    }

    // 4) stage-2 GEMMs with fused epilogues (fp32 FFMA)
    {
        GemmJobs J = {};
        J.count = 4;
        J.tileStart[0] = 0; J.tileStart[1] = 8; J.tileStart[2] = 16; J.tileStart[3] = 24; J.tileStart[4] = 32;
        J.A[0] = P_hw; J.Bm[0] = w2; J.Cm[0] = P_dec; J.N[0] = 512; J.K[0] = 64;  J.transb[0] = 0; J.act[0] = 3;
        J.bias[0] = w0; J.aux1[0] = nullptr; J.aux2[0] = nullptr; J.mix[0] = nullptr;
        J.A[1] = P_ha; J.Bm[1] = a2; J.Cm[1] = P_a; J.N[1] = 512; J.K[1] = 64;  J.transb[1] = 0; J.act[1] = 2;
        J.bias[1] = a0; J.aux1[1] = nullptr; J.aux2[1] = nullptr; J.mix[1] = nullptr;
        J.A[2] = P_hv; J.Bm[2] = v2; J.Cm[2] = P_v; J.N[2] = 512; J.K[2] = 32;  J.transb[2] = 0; J.act[2] = 4;
        J.bias[2] = v0; J.aux1[2] = P_vraw; J.aux2[2] = v_first; J.mix[2] = nullptr;
        J.A[3] = P_hg; J.Bm[3] = g2; J.Cm[3] = P_g; J.N[3] = 512; J.K[3] = 128; J.transb[3] = 0; J.act[3] = 0;
        J.bias[3] = nullptr; J.aux1[3] = nullptr; J.aux2[3] = nullptr; J.mix[3] = nullptr;
        gemm_multi<<<dim3(32, 32), 256>>>(J);
    }

    // 5) kk normalize, k', aa, bb
    post_kernel<<<BT, 128>>>(k_k, k_a);

    // 5b) A' streams + (beta,kappa) scalars
    prep2_kernel<<<BT, 128>>>();

    // 6) bidirectional WKV7 scan — decoupled reduction
    scan_kernel<<<128, 256>>>();

    // 7) combine + groupnorm + residual + *g
    combine_kernel<<<BT, 128>>>(r_k, ln_g, ln_b);

    // 8) out = z @ Wo^T — tf32 tensor cores (no mixing)
    {
        QkvJobs J;
        J.A[0] = P_z; J.W[0] = Wo; J.C[0] = out; J.mix[0] = nullptr;
        J.A[1] = P_z; J.W[1] = Wo; J.C[1] = out; J.mix[1] = nullptr;
        J.A[2] = P_z; J.W[2] = Wo; J.C[2] = out; J.mix[2] = nullptr;
        gemm_tf32_nt<<<dim3(8, 32, 1), 256>>>(J);
    }

    // 9) v_first passthrough if the flattened output includes it
    if (out_size >= 2 * BTC) {
        cudaMemcpyAsync(out + BTC, v_first, (size_t)BTC * sizeof(float),
                        cudaMemcpyDeviceToDevice, 0);
    }
}

// round 13
// speedup vs baseline: 1.3574x; 1.0156x over previous
#include <cuda_runtime.h>
#include <cstdint>
#include <math.h>

// Problem sizes (fixed)
#define BB   4
#define TT   1024
#define CC   512
#define HH   8
#define NN   64
#define BT   (BB*TT)        // 4096
#define BTC  (BT*CC)        // 2097152
#define SPAD (10*CC)        // over-read guard for branch-free prefetch + drain
#define BKPAD (16*HH)

typedef unsigned long long u64;

// ---------------------------------------------------------------------------
// Workspace (static __device__ arrays; no allocation at runtime)
// Padded arrays: live data at [SPAD, SPAD+BTC).
// ---------------------------------------------------------------------------
__device__ float g_gate[BT*HH];
__device__ float g_k[BTC], g_vraw[BTC];
__device__ float g_hw[BT*64], g_ha[BT*64], g_hv[BT*32], g_hg[BT*128];
__device__ float g_a[BTC], g_g[BTC];
__device__ float g_r[BTC+2*SPAD], g_dec[BTC+2*SPAD], g_v[BTC+2*SPAD];
__device__ float g_kp[BTC+2*SPAD], g_aa[BTC+2*SPAD], g_bb[BTC+2*SPAD];
__device__ float g_af[BTC+2*SPAD], g_ab[BTC+2*SPAD];      // A' = dec_prev ∘ aa
__device__ float2 g_bkf[BT*HH + 2*BKPAD], g_bkb[BT*HH + 2*BKPAD]; // (beta,kappa)
__device__ float g_yf[BTC+2*SPAD], g_yb[BTC+2*SPAD];
__device__ float g_z[BTC];

// ---------------------------------------------------------------------------
// f32x2 packed helpers (sm_100+)
// ---------------------------------------------------------------------------
__device__ __forceinline__ u64 fma2(u64 a, u64 b, u64 c) {
    u64 d; asm("fma.rn.f32x2 %0, %1, %2, %3;" : "=l"(d) : "l"(a), "l"(b), "l"(c));
    return d;
}
__device__ __forceinline__ u64 mul2(u64 a, u64 b) {
    u64 d; asm("mul.rn.f32x2 %0, %1, %2;" : "=l"(d) : "l"(a), "l"(b));
    return d;
}
__device__ __forceinline__ u64 pack2(float x) {
    u64 d; uint32_t r = __float_as_uint(x);
    asm("mov.b64 %0, {%1, %1};" : "=l"(d) : "r"(r));
    return d;
}
__device__ __forceinline__ float sum2(u64 a) {
    uint32_t lo, hi;
    asm("mov.b64 {%0, %1}, %2;" : "=r"(lo), "=r"(hi) : "l"(a));
    return __uint_as_float(lo) + __uint_as_float(hi);
}

// ---------------------------------------------------------------------------
// Kernel 1: per-head gate only (mixes fused into GEMM loaders)
// ---------------------------------------------------------------------------
__global__ void gate_kernel(const float* __restrict__ x,
                            const float* __restrict__ gate_w)
{
    int bt = blockIdx.x;
    int t  = bt & (TT - 1);
    int tid = threadIdx.x;
    int c  = tid * 4;
    size_t base = (size_t)bt * CC + c;

    float4 xc = *(const float4*)(x + base);
    float4 xp = make_float4(0.f, 0.f, 0.f, 0.f);
    if (t != 0) xp = *(const float4*)(x + base - CC);

    float4 gw = *(const float4*)(gate_w + c);
    float p = (xp.x - xc.x)*gw.x + (xp.y - xc.y)*gw.y
            + (xp.z - xc.z)*gw.z + (xp.w - xc.w)*gw.w;
    #pragma unroll
    for (int o = 1; o < 16; o <<= 1) p += __shfl_xor_sync(0xffffffffu, p, o);
    if ((tid & 15) == 0)
        g_gate[bt*HH + (tid >> 4)] = 1.f / (1.f + expf(-p));
}

// ---------------------------------------------------------------------------
// Fused mixed-A load helper
// ---------------------------------------------------------------------------
__device__ __forceinline__ float4 load_mixed(const float* __restrict__ A,
                                             const float* __restrict__ mix,
                                             int row, int kc, int K)
{
    const float* ap = A + (size_t)row * K + kc;
    float4 xc = *(const float4*)ap;
    if (mix == nullptr) return xc;
    float4 xp = make_float4(0.f, 0.f, 0.f, 0.f);
    if (row & (TT - 1)) xp = *(const float4*)(ap - CC);
    float4 mx = *(const float4*)(mix + kc);
    float4 o;
    o.x = xc.x + (xp.x - xc.x) * mx.x;
    o.y = xc.y + (xp.y - xc.y) * mx.y;
    o.z = xc.z + (xp.z - xc.z) * mx.z;
    o.w = xc.w + (xp.w - xc.w) * mx.w;
    return o;
}

// ---------------------------------------------------------------------------
// tf32 tensor-core GEMM: C = mixA(x)[4096,512] @ W^T, W [512,512] row-major
// Smem padded to 136/72 (mod 32 = 8) -> conflict-free fragment loads.
// ---------------------------------------------------------------------------
struct QkvJobs {
    const float* A[3];
    const float* W[3];
    float*       C[3];
    const float* mix[3];
};

__device__ __forceinline__ uint32_t f2tf32(float x) {
    uint32_t r;
    asm("cvt.rna.tf32.f32 %0, %1;" : "=r"(r) : "f"(x));
    return r;
}

__device__ __forceinline__ void mma_tf32(float* d, const uint32_t* a, const uint32_t* b) {
    asm("mma.sync.aligned.m16n8k8.row.col.f32.tf32.tf32.f32 "
        "{%0,%1,%2,%3},{%4,%5,%6,%7},{%8,%9},{%0,%1,%2,%3};"
        : "+f"(d[0]), "+f"(d[1]), "+f"(d[2]), "+f"(d[3])
        : "r"(a[0]), "r"(a[1]), "r"(a[2]), "r"(a[3]), "r"(b[0]), "r"(b[1]));
}

__global__ __launch_bounds__(256, 2) void gemm_tf32_nt(QkvJobs J)
{
    const int K = 512, N = 512;
    const float* A = J.A[blockIdx.z];
    const float* W = J.W[blockIdx.z];
    float*       C = J.C[blockIdx.z];
    const float* mix = J.mix[blockIdx.z];

    int m0 = blockIdx.y * 128;
    int n0 = blockIdx.x * 64;

    __shared__ uint32_t As[32][136];   // 136 % 32 == 8 -> conflict-free
    __shared__ uint32_t Bs[32][72];    // 72 % 32 == 8  -> conflict-free

    int tid  = threadIdx.x;
    int warp = tid >> 5, lane = tid & 31;
    int g = lane >> 2, c = lane & 3;
    int wm = warp & 3, wn = warp >> 2;

    float acc[2][4][4];
    #pragma unroll
    for (int mt = 0; mt < 2; mt++)
        #pragma unroll
        for (int nt = 0; nt < 4; nt++)
            #pragma unroll
            for (int r = 0; r < 4; r++) acc[mt][nt][r] = 0.f;

    for (int k0 = 0; k0 < K; k0 += 32) {
        #pragma unroll
        for (int it = 0; it < 4; it++) {
            int idx = tid + it * 256;
            int m = idx >> 3, kc = (idx & 7) * 4;
            float4 v = load_mixed(A, mix, m0 + m, k0 + kc, K);
            As[kc+0][m] = f2tf32(v.x);
            As[kc+1][m] = f2tf32(v.y);
            As[kc+2][m] = f2tf32(v.z);
            As[kc+3][m] = f2tf32(v.w);
        }
        #pragma unroll
        for (int it = 0; it < 2; it++) {
            int idx = tid + it * 256;
            int n = idx >> 3, kc = (idx & 7) * 4;
            float4 v = *(const float4*)(W + (size_t)(n0 + n) * K + k0 + kc);
            Bs[kc+0][n] = f2tf32(v.x);
            Bs[kc+1][n] = f2tf32(v.y);
            Bs[kc+2][n] = f2tf32(v.z);
            Bs[kc+3][n] = f2tf32(v.w);
        }
        __syncthreads();

        #pragma unroll
        for (int k8 = 0; k8 < 4; k8++) {
            int kr = k8 * 8;
            uint32_t a[2][4], b[4][2];
            #pragma unroll
            for (int mt = 0; mt < 2; mt++) {
                int mb = wm * 32 + mt * 16;
                a[mt][0] = As[kr + c    ][mb + g    ];
                a[mt][1] = As[kr + c    ][mb + g + 8];
                a[mt][2] = As[kr + c + 4][mb + g    ];
                a[mt][3] = As[kr + c + 4][mb + g + 8];
            }
            #pragma unroll
            for (int nt = 0; nt < 4; nt++) {
                int nb = wn * 32 + nt * 8;
                b[nt][0] = Bs[kr + c    ][nb + g];
                b[nt][1] = Bs[kr + c + 4][nb + g];
            }
            #pragma unroll
            for (int mt = 0; mt < 2; mt++)
                #pragma unroll
                for (int nt = 0; nt < 4; nt++)
                    mma_tf32(acc[mt][nt], a[mt], b[nt]);
        }
        __syncthreads();
    }

    #pragma unroll
    for (int mt = 0; mt < 2; mt++) {
        int row = m0 + wm * 32 + mt * 16 + g;
        #pragma unroll
        for (int nt = 0; nt < 4; nt++) {
            int col = n0 + wn * 32 + nt * 8 + 2 * c;
            float2 v0 = make_float2(acc[mt][nt][0], acc[mt][nt][1]);
            float2 v1 = make_float2(acc[mt][nt][2], acc[mt][nt][3]);
            *(float2*)(C + (size_t)row * N + col)       = v0;
            *(float2*)(C + (size_t)(row + 8) * N + col) = v1;
        }
    }
}

// ---------------------------------------------------------------------------
// Generic multi-job FFMA SGEMM (stage-1/2 MLPs stay fp32); fused-mix A loads
// ---------------------------------------------------------------------------
#define GBM 128
#define GBN 64
#define GBK 16

struct GemmJobs {
    int count;
    int tileStart[5];
    const float* A[4];
    const float* Bm[4];
    float*       Cm[4];
    int N[4];
    int K[4];
    int transb[4];
    int act[4];
    const float* bias[4];
    const float* aux1[4];
    const float* aux2[4];
    const float* mix[4];
};

__global__ __launch_bounds__(256, 2) void gemm_multi(GemmJobs J)
{
    __shared__ __align__(16) float As[GBK][GBM + 4];
    __shared__ __align__(16) float Bs[GBK][GBN + 4];

    int bx = blockIdx.x;
    int j = 0;
    while (bx >= J.tileStart[j + 1]) ++j;
    int n0 = (bx - J.tileStart[j]) * GBN;
    int m0 = blockIdx.y * GBM;

    const float* A = J.A[j];
    const float* B = J.Bm[j];
    float*       C = J.Cm[j];
    const int N = J.N[j];
    const int K = J.K[j];
    const int tb = J.transb[j];
    const float* mix = J.mix[j];

    int tid = threadIdx.x;
    int tx = tid & 15, ty = tid >> 4;

    float acc[8][4];
    #pragma unroll
    for (int im = 0; im < 8; im++)
        #pragma unroll
        for (int in = 0; in < 4; in++) acc[im][in] = 0.f;

    for (int k0 = 0; k0 < K; k0 += GBK) {
        #pragma unroll
        for (int it = 0; it < 2; it++) {
            int lid = tid + it * 256;
            int row = lid >> 2, kc = lid & 3;
            float4 v = load_mixed(A, mix, m0 + row, k0 + kc * 4, K);
            As[kc*4+0][row] = v.x;
            As[kc*4+1][row] = v.y;
            As[kc*4+2][row] = v.z;
            As[kc*4+3][row] = v.w;
        }
        if (tb) {
            int row = tid >> 2, kc = tid & 3;
            float4 v = *(const float4*)(B + (size_t)(n0 + row) * K + k0 + kc * 4);
            Bs[kc*4+0][row] = v.x;
            Bs[kc*4+1][row] = v.y;
            Bs[kc*4+2][row] = v.z;
            Bs[kc*4+3][row] = v.w;
        } else {
            int kr = tid >> 4, c4 = (tid & 15) * 4;
            float4 v = make_float4(0.f, 0.f, 0.f, 0.f);
            if (n0 + c4 < N)
                v = *(const float4*)(B + (size_t)(k0 + kr) * N + n0 + c4);
            *(float4*)&Bs[kr][c4] = v;
        }
        __syncthreads();

        #pragma unroll
        for (int kk = 0; kk < GBK; kk++) {
            float4 bf = *(const float4*)&Bs[kk][tx * 4];
            float4 a0 = *(const float4*)&As[kk][ty * 8];
            float4 a1 = *(const float4*)&As[kk][ty * 8 + 4];
            float af[8] = {a0.x, a0.y, a0.z, a0.w, a1.x, a1.y, a1.z, a1.w};
            float bb2[4] = {bf.x, bf.y, bf.z, bf.w};
            #pragma unroll
            for (int im = 0; im < 8; im++)
                #pragma unroll
                for (int in = 0; in < 4; in++) acc[im][in] += af[im] * bb2[in];
        }
        __syncthreads();
    }

    const int act = J.act[j];
    const float* bias = J.bias[j];
    const float* aux1 = J.aux1[j];
    const float* aux2 = J.aux2[j];

    #pragma unroll
    for (int im = 0; im < 8; im++) {
        int row = m0 + ty * 8 + im;
        #pragma unroll
        for (int in = 0; in < 4; in++) {
            int col = n0 + tx * 4 + in;
            if (col < N) {
                size_t idx = (size_t)row * N + col;
                float v = acc[im][in];
                float o;
                if (act == 0) {
                    o = v;
                } else if (act == 1) {
                    o = tanhf(v);
                } else if (act == 2) {
                    float z = v + (bias ? bias[col] : 0.f);
                    o = 1.f / (1.f + expf(-z));
                } else if (act == 3) {
                    float z = v + bias[col];
                    float s = 1.f / (1.f + expf(-z));
                    o = expf(-0.60653065971263342f * s);
                } else {
                    float z = v + bias[col];
                    float s = 1.f / (1.f + expf(-z));
                    float vr = aux1[idx];
                    o = vr + (aux2[idx] - vr) * s;
                }
                C[idx] = o;
            }
        }
    }
}

// ---------------------------------------------------------------------------
// Kernel: post — kk normalization per head, k' update, aa=-kk, bb=kk*a
// ---------------------------------------------------------------------------
__global__ void post_kernel(const float* __restrict__ k_k, const float* __restrict__ k_a)
{
    int bt = blockIdx.x;
    int tid = threadIdx.x;
    int c = tid * 4;
    size_t base = (size_t)bt * CC + c;

    float4 kv = *(const float4*)(g_k + base);
    float4 av = *(const float4*)(g_a + base);
    float4 kkc = *(const float4*)(k_k + c);
    float4 kac = *(const float4*)(k_a + c);

    float4 kk;
    kk.x = kv.x * kkc.x; kk.y = kv.y * kkc.y; kk.z = kv.z * kkc.z; kk.w = kv.w * kkc.w;
    float ss = kk.x*kk.x + kk.y*kk.y + kk.z*kk.z + kk.w*kk.w;
    #pragma unroll
    for (int o = 1; o < 16; o <<= 1) ss += __shfl_xor_sync(0xffffffffu, ss, o);

    float nrm = sqrtf(ss);
    float inv = 1.f / fmaxf(nrm, 1e-12f);

    float4 aa, bb, kp;
    aa.x = -kk.x * inv; aa.y = -kk.y * inv; aa.z = -kk.z * inv; aa.w = -kk.w * inv;
    bb.x = kk.x * inv * av.x; bb.y = kk.y * inv * av.y;
    bb.z = kk.z * inv * av.z; bb.w = kk.w * inv * av.w;
    kp.x = kv.x * (1.f + (av.x - 1.f) * kac.x);
    kp.y = kv.y * (1.f + (av.y - 1.f) * kac.y);
    kp.z = kv.z * (1.f + (av.z - 1.f) * kac.z);
    kp.w = kv.w * (1.f + (av.w - 1.f) * kac.w);

    *(float4*)(g_aa + SPAD + base) = aa;
    *(float4*)(g_bb + SPAD + base) = bb;
    *(float4*)(g_kp + SPAD + base) = kp;
}

// ---------------------------------------------------------------------------
// Kernel: prep2 — precompute A' streams and (beta,kappa) scalar streams.
// ---------------------------------------------------------------------------
__global__ void prep2_kernel()
{
    int bt = blockIdx.x;
    int t  = bt & (TT - 1);
    int tid = threadIdx.x;
    int c = tid * 4;
    int h = tid >> 4;
    size_t base = SPAD + (size_t)bt * CC + c;

    float4 av = *(const float4*)(g_aa + base);
    float4 z4 = make_float4(0.f, 0.f, 0.f, 0.f);
    float4 dp = z4, bp = z4, kpv = z4, dn = z4, bn = z4, kn = z4;
    if (t != 0) {
        dp  = *(const float4*)(g_dec + base - CC);
        bp  = *(const float4*)(g_bb  + base - CC);
        kpv = *(const float4*)(g_kp  + base - CC);
    }
    if (t != TT - 1) {
        dn = *(const float4*)(g_dec + base + CC);
        bn = *(const float4*)(g_bb  + base + CC);
        kn = *(const float4*)(g_kp  + base + CC);
    }

    float4 af, ab;
    af.x = dp.x*av.x; af.y = dp.y*av.y; af.z = dp.z*av.z; af.w = dp.w*av.w;
    ab.x = dn.x*av.x; ab.y = dn.y*av.y; ab.z = dn.z*av.z; ab.w = dn.w*av.w;
    *(float4*)(g_af + base) = af;
    *(float4*)(g_ab + base) = ab;

    float bf_ = bp.x*av.x + bp.y*av.y + bp.z*av.z + bp.w*av.w;
    float kf_ = kpv.x*av.x + kpv.y*av.y + kpv.z*av.z + kpv.w*av.w;
    float bb_ = bn.x*av.x + bn.y*av.y + bn.z*av.z + bn.w*av.w;
    float kb_ = kn.x*av.x + kn.y*av.y + kn.z*av.z + kn.w*av.w;
    #pragma unroll
    for (int o = 1; o < 16; o <<= 1) {
        bf_ += __shfl_xor_sync(0xffffffffu, bf_, o);
        kf_ += __shfl_xor_sync(0xffffffffu, kf_, o);
        bb_ += __shfl_xor_sync(0xffffffffu, bb_, o);
        kb_ += __shfl_xor_sync(0xffffffffu, kb_, o);
    }
    if ((tid & 15) == 0) {
        g_bkf[BKPAD + bt*HH + h] = make_float2(bf_, kf_);
        g_bkb[BKPAD + bt*HH + h] = make_float2(bb_, kb_);
    }
}

// ---------------------------------------------------------------------------
// Kernel: bidirectional WKV7 scan — decoupled sa reduction (2-step slack),
// 16-row groups (grid 256 x 128 thr, ~2 blocks/SM), 2 rows/thread,
// 4 cols/row, f32x2, depth-4 prefetch, branch-free + drain.
// Lagged y-store predicated to in-sequence positions.
// ---------------------------------------------------------------------------
template<int CS>
__device__ __forceinline__ void scan_step(
    int tstep,
    u64& S0a, u64& S1a, u64& S0b, u64& S1b,
    u64 (&R)[4][2], u64 (&D)[4][2], u64 (&K)[4][2],
    u64 (&B)[4][2], u64 (&A2)[4][2],
    float (&V0)[4], float (&V1)[4], float2 (&BK)[4],
    float (&zf0)[2], float (&zf1)[2], float (&yf0)[2], float (&yf1)[2],
    float& sa_prev0, float& sa_prev1, float& vprev0, float& vprev1,
    const float*& pr4, const float*& pd4, const float*& pk4,
    const float*& pb4, const float*& pA6,
    const float*& pv04, const float*& pv14, const float2*& pbk4,
    float* py0, float* py1, int stride, int sbk, int q)
{
    constexpr int P = CS & 1;

    float2 bk = BK[CS];
    float sa0 = fmaf(vprev0, bk.y, fmaf(sa_prev0, bk.x, zf0[P]));
    float sa1 = fmaf(vprev1, bk.y, fmaf(sa_prev1, bk.x, zf1[P]));

    if (q == 0 && (unsigned)(tstep - 2) < (unsigned)TT) {
        *py0 = yf0[P]; *py1 = yf1[P];
    }

    u64 sa20 = pack2(sa0), sa21 = pack2(sa1);
    float v0s = V0[CS], v1s = V1[CS];
    u64 v20 = pack2(v0s), v21 = pack2(v1s);
    S0a = fma2(S0a, D[CS][0], fma2(sa20, B[CS][0], mul2(v20, K[CS][0])));
    S1a = fma2(S1a, D[CS][1], fma2(sa20, B[CS][1], mul2(v20, K[CS][1])));
    S0b = fma2(S0b, D[CS][0], fma2(sa21, B[CS][0], mul2(v21, K[CS][0])));
    S1b = fma2(S1b, D[CS][1], fma2(sa21, B[CS][1], mul2(v21, K[CS][1])));

    float ya = sum2(fma2(S1a, R[CS][1],  mul2(S0a, R[CS][0])));
    float za = sum2(fma2(S1a, A2[CS][1], mul2(S0a, A2[CS][0])));
    float yb = sum2(fma2(S1b, R[CS][1],  mul2(S0b, R[CS][0])));
    float zb = sum2(fma2(S1b, A2[CS][1], mul2(S0b, A2[CS][0])));

    sa_prev0 = sa0; sa_prev1 = sa1; vprev0 = v0s; vprev1 = v1s;

    {
        ulonglong2 rv = *(const ulonglong2*)pr4;
        ulonglong2 dv = *(const ulonglong2*)pd4;
        ulonglong2 kv = *(const ulonglong2*)pk4;
        ulonglong2 bv = *(const ulonglong2*)pb4;
        ulonglong2 av = *(const ulonglong2*)pA6;
        R[CS][0]  = rv.x; R[CS][1]  = rv.y;
        D[CS][0]  = dv.x; D[CS][1]  = dv.y;
        K[CS][0]  = kv.x; K[CS][1]  = kv.y;
        B[CS][0]  = bv.x; B[CS][1]  = bv.y;
        A2[CS][0] = av.x; A2[CS][1] = av.y;
        V0[CS] = *pv04;
        V1[CS] = *pv14;
        BK[CS] = *pbk4;
    }
    pr4 += stride; pd4 += stride; pk4 += stride; pb4 += stride;
    pA6 += stride; pv04 += stride; pv14 += stride; pbk4 += sbk;

    #pragma unroll
    for (int o = 1; o < 16; o <<= 1) {
        ya += __shfl_xor_sync(0xffffffffu, ya, o);
        za += __shfl_xor_sync(0xffffffffu, za, o);
        yb += __shfl_xor_sync(0xffffffffu, yb, o);
        zb += __shfl_xor_sync(0xffffffffu, zb, o);
    }
    yf0[P] = ya; zf0[P] = za; yf1[P] = yb; zf1[P] = zb;
}

__global__ __launch_bounds__(128, 2) void scan_kernel()
{
    int bx = blockIdx.x;
    int dir = bx >> 7;
    int b   = (bx >> 5) & 3;
    int h   = (bx >> 2) & 7;
    int rg  = bx & 3;
    int tid = threadIdx.x;
    int rp  = tid >> 4;          // 0..7
    int q   = tid & 15;
    int c0  = q * 4;
    int i0  = rg * 16 + rp;
    int i1  = i0 + 8;

    int t0 = dir ? (TT - 1) : 0;
    int stride = dir ? -CC : CC;
    int sbk = dir ? -HH : HH;
    size_t off = SPAD + (size_t)(b * TT + t0) * CC + h * NN;

    const float* pr = g_r   + off + c0;
    const float* pd = g_dec + off + c0;
    const float* pk = g_kp  + off + c0;
    const float* pb = g_bb  + off + c0;
    const float* pA = (dir ? g_ab : g_af) + off + c0;
    const float* pv0 = g_v + off + i0;
    const float* pv1 = g_v + off + i1;
    const float2* pbk = (dir ? g_bkb : g_bkf) + BKPAD + (size_t)(b * TT + t0) * HH + h;

    float* ybase = (dir ? g_yb : g_yf);
    float* py0 = ybase + off + i0 - 2*stride;
    float* py1 = ybase + off + i1 - 2*stride;

    u64 S0a = 0, S1a = 0, S0b = 0, S1b = 0;
    u64 R[4][2], D[4][2], K[4][2], B[4][2], A2[4][2];
    float V0[4], V1[4];
    float2 BK[4];

    #pragma unroll
    for (int s = 0; s < 4; s++) {
        ulonglong2 v;
        v = *(const ulonglong2*)(pr + s*stride);     R[s][0]=v.x;  R[s][1]=v.y;
        v = *(const ulonglong2*)(pd + s*stride);     D[s][0]=v.x;  D[s][1]=v.y;
        v = *(const ulonglong2*)(pk + s*stride);     K[s][0]=v.x;  K[s][1]=v.y;
        v = *(const ulonglong2*)(pb + s*stride);     B[s][0]=v.x;  B[s][1]=v.y;
        v = *(const ulonglong2*)(pA + (s+2)*stride); A2[s][0]=v.x; A2[s][1]=v.y;
        V0[s] = *(pv0 + s*stride);
        V1[s] = *(pv1 + s*stride);
        BK[s] = *(pbk + s*sbk);
    }

    const float* pr4  = pr + 4*stride;
    const float* pd4  = pd + 4*stride;
    const float* pk4  = pk + 4*stride;
    const float* pb4  = pb + 4*stride;
    const float* pA6  = pA + 6*stride;
    const float* pv04 = pv0 + 4*stride;
    const float* pv14 = pv1 + 4*stride;
    const float2* pbk4 = pbk + 4*sbk;

    float zf0[2] = {0.f, 0.f}, zf1[2] = {0.f, 0.f};
    float yf0[2] = {0.f, 0.f}, yf1[2] = {0.f, 0.f};
    float sa_prev0 = 0.f, sa_prev1 = 0.f, vprev0 = 0.f, vprev1 = 0.f;

    for (int t = 0; t < TT + 4; t += 4) {
        scan_step<0>(t+0, S0a,S1a,S0b,S1b, R,D,K,B,A2, V0,V1,BK, zf0,zf1,yf0,yf1,
                     sa_prev0,sa_prev1,vprev0,vprev1,
                     pr4,pd4,pk4,pb4,pA6,pv04,pv14,pbk4, py0,py1, stride,sbk,q);
        py0 += stride; py1 += stride;
        scan_step<1>(t+1, S0a,S1a,S0b,S1b, R,D,K,B,A2, V0,V1,BK, zf0,zf1,yf0,yf1,
                     sa_prev0,sa_prev1,vprev0,vprev1,
                     pr4,pd4,pk4,pb4,pA6,pv04,pv14,pbk4, py0,py1, stride,sbk,q);
        py0 += stride; py1 += stride;
        scan_step<2>(t+2, S0a,S1a,S0b,S1b, R,D,K,B,A2, V0,V1,BK, zf0,zf1,yf0,yf1,
                     sa_prev0,sa_prev1,vprev0,vprev1,
                     pr4,pd4,pk4,pb4,pA6,pv04,pv14,pbk4, py0,py1, stride,sbk,q);
        py0 += stride; py1 += stride;
        scan_step<3>(t+3, S0a,S1a,S0b,S1b, R,D,K,B,A2, V0,V1,BK, zf0,zf1,yf0,yf1,
                     sa_prev0,sa_prev1,vprev0,vprev1,
                     pr4,pd4,pk4,pb4,pA6,pv04,pv14,pbk4, py0,py1, stride,sbk,q);
        py0 += stride; py1 += stride;
    }
}

// ---------------------------------------------------------------------------
// Kernel: combine — gate-mix fwd/bwd, groupnorm, residual, * g
// ---------------------------------------------------------------------------
__global__ void combine_kernel(const float* __restrict__ r_k,
                               const float* __restrict__ ln_g,
                               const float* __restrict__ ln_b)
{
    int bt = blockIdx.x;
    int tid = threadIdx.x;
    int c = tid * 4;
    int h = tid >> 4;
    size_t base = (size_t)bt * CC + c;

    float4 yf = *(const float4*)(g_yf + SPAD + base);
    float4 yb = *(const float4*)(g_yb + SPAD + base);
    float gate = g_gate[bt * HH + h];

    float4 xo;
    xo.x = gate * yf.x + (1.f - gate) * yb.x;
    xo.y = gate * yf.y + (1.f - gate) * yb.y;
    xo.z = gate * yf.z + (1.f - gate) * yb.z;
    xo.w = gate * yf.w + (1.f - gate) * yb.w;

    float4 rv = *(const float4*)(g_r + SPAD + base);
    float4 kp = *(const float4*)(g_kp + SPAD + base);
    float4 vv = *(const float4*)(g_v + SPAD + base);
    float4 gv = *(const float4*)(g_g + base);
    float4 rk = *(const float4*)(r_k + c);

    float sum = xo.x + xo.y + xo.z + xo.w;
    float sq  = xo.x*xo.x + xo.y*xo.y + xo.z*xo.z + xo.w*xo.w;
    float sres = rv.x*kp.x*rk.x + rv.y*kp.y*rk.y + rv.z*kp.z*rk.z + rv.w*kp.w*rk.w;
    #pragma unroll
    for (int o = 1; o < 16; o <<= 1) {
        sum  += __shfl_xor_sync(0xffffffffu, sum, o);
        sq   += __shfl_xor_sync(0xffffffffu, sq, o);
        sres += __shfl_xor_sync(0xffffffffu, sres, o);
    }
    float mu = sum * (1.f / 64.f);
    float var = sq * (1.f / 64.f) - mu * mu;
    float rstd = rsqrtf(var + 0.00064f);

    float4 lg = *(const float4*)(ln_g + c);
    float4 lb = *(const float4*)(ln_b + c);

    float4 z;
    z.x = ((xo.x - mu) * rstd * lg.x + lb.x + sres * vv.x) * gv.x;
    z.y = ((xo.y - mu) * rstd * lg.y + lb.y + sres * vv.y) * gv.y;
    z.z = ((xo.z - mu) * rstd * lg.z + lb.z + sres * vv.z) * gv.z;
    z.w = ((xo.w - mu) * rstd * lg.w + lb.w + sres * vv.w) * gv.w;
    *(float4*)(g_z + base) = z;
}

// ---------------------------------------------------------------------------
// Host launcher
// ---------------------------------------------------------------------------
static float *P_r, *P_k, *P_vraw;
static float *P_hw, *P_ha, *P_hv, *P_hg;
static float *P_dec, *P_a, *P_v, *P_g;
static float *P_z;
static bool s_init = false;

extern "C" void kernel_launch(void* const* d_in, const int* in_sizes, int n_in,
                              void* d_out, int out_size)
{
    const float* x       = (const float*)d_in[0];
    const float* v_first = (const float*)d_in[1];
    const float* x_r = (const float*)d_in[2];
    const float* x_w = (const float*)d_in[3];
    const float* x_k = (const float*)d_in[4];
    const float* x_v = (const float*)d_in[5];
    const float* x_a = (const float*)d_in[6];
    const float* x_g = (const float*)d_in[7];
    const float* w0  = (const float*)d_in[8];
    const float* w1  = (const float*)d_in[9];
    const float* w2  = (const float*)d_in[10];
    const float* a0  = (const float*)d_in[11];
    const float* a1  = (const float*)d_in[12];
    const float* a2  = (const float*)d_in[13];
    const float* v0  = (const float*)d_in[14];
    const float* v1  = (const float*)d_in[15];
    const float* v2  = (const float*)d_in[16];
    const float* g1  = (const float*)d_in[17];
    const float* g2  = (const float*)d_in[18];
    const float* k_k = (const float*)d_in[19];
    const float* k_a = (const float*)d_in[20];
    const float* r_k = (const float*)d_in[21];
    const float* gate_w = (const float*)d_in[22];
    const float* ln_g = (const float*)d_in[23];
    const float* ln_b = (const float*)d_in[24];
    const float* Wr = (const float*)d_in[25];
    const float* Wk = (const float*)d_in[26];
    const float* Wv = (const float*)d_in[27];
    const float* Wo = (const float*)d_in[28];
    float* out = (float*)d_out;

    if (!s_init) {
        cudaGetSymbolAddress((void**)&P_r, g_r);       P_r   += SPAD;
        cudaGetSymbolAddress((void**)&P_k, g_k);
        cudaGetSymbolAddress((void**)&P_vraw, g_vraw);
        cudaGetSymbolAddress((void**)&P_hw, g_hw);
        cudaGetSymbolAddress((void**)&P_ha, g_ha);
        cudaGetSymbolAddress((void**)&P_hv, g_hv);
        cudaGetSymbolAddress((void**)&P_hg, g_hg);
        cudaGetSymbolAddress((void**)&P_dec, g_dec);   P_dec += SPAD;
        cudaGetSymbolAddress((void**)&P_a, g_a);
        cudaGetSymbolAddress((void**)&P_v, g_v);       P_v   += SPAD;
        cudaGetSymbolAddress((void**)&P_g, g_g);
        cudaGetSymbolAddress((void**)&P_z, g_z);
        s_init = true;
    }

    // 1) per-head gate
    gate_kernel<<<BT, 128>>>(x, gate_w);

    // 2) big QKV GEMMs — tf32 tensor cores with fused token-shift mixing
    {
        QkvJobs J;
        J.A[0] = x; J.W[0] = Wr; J.C[0] = P_r;    J.mix[0] = x_r;
        J.A[1] = x; J.W[1] = Wk; J.C[1] = P_k;    J.mix[1] = x_k;
        J.A[2] = x; J.W[2] = Wv; J.C[2] = P_vraw; J.mix[2] = x_v;
        gemm_tf32_nt<<<dim3(8, 32, 3), 256>>>(J);
    }

    // 3) stage-1 hidden GEMMs (fp32 FFMA) with fused mixing
    {
        GemmJobs J = {};
        J.count = 4;
        J.tileStart[0] = 0; J.tileStart[1] = 1; J.tileStart[2] = 2; J.tileStart[3] = 3; J.tileStart[4] = 5;
        J.A[0] = x; J.Bm[0] = w1; J.Cm[0] = P_hw; J.N[0] = 64;  J.K[0] = 512; J.transb[0] = 0; J.act[0] = 1; J.mix[0] = x_w;
        J.A[1] = x; J.Bm[1] = a1; J.Cm[1] = P_ha; J.N[1] = 64;  J.K[1] = 512; J.transb[1] = 0; J.act[1] = 0; J.mix[1] = x_a;
        J.A[2] = x; J.Bm[2] = v1; J.Cm[2] = P_hv; J.N[2] = 32;  J.K[2] = 512; J.transb[2] = 0; J.act[2] = 0; J.mix[2] = nullptr;
        J.A[3] = x; J.Bm[3] = g1; J.Cm[3] = P_hg; J.N[3] = 128; J.K[3] = 512; J.transb[3] = 0; J.act[3] = 2; J.mix[3] = x_g;
        for (int jj = 0; jj < 4; jj++) { J.bias[jj] = nullptr; J.aux1[jj] = nullptr; J.aux2[jj] = nullptr; }
        gemm_multi<<<dim3(5, 32), 256>>>(J);
    }

    // 4) stage-2 GEMMs with fused epilogues (fp32 FFMA)
    {
        GemmJobs J = {};
        J.count = 4;
        J.tileStart[0] = 0; J.tileStart[1] = 8; J.tileStart[2] = 16; J.tileStart[3] = 24; J.tileStart[4] = 32;
        J.A[0] = P_hw; J.Bm[0] = w2; J.Cm[0] = P_dec; J.N[0] = 512; J.K[0] = 64;  J.transb[0] = 0; J.act[0] = 3;
        J.bias[0] = w0; J.aux1[0] = nullptr; J.aux2[0] = nullptr; J.mix[0] = nullptr;
        J.A[1] = P_ha; J.Bm[1] = a2; J.Cm[1] = P_a; J.N[1] = 512; J.K[1] = 64;  J.transb[1] = 0; J.act[1] = 2;
        J.bias[1] = a0; J.aux1[1] = nullptr; J.aux2[1] = nullptr; J.mix[1] = nullptr;
        J.A[2] = P_hv; J.Bm[2] = v2; J.Cm[2] = P_v; J.N[2] = 512; J.K[2] = 32;  J.transb[2] = 0; J.act[2] = 4;
        J.bias[2] = v0; J.aux1[2] = P_vraw; J.aux2[2] = v_first; J.mix[2] = nullptr;
        J.A[3] = P_hg; J.Bm[3] = g2; J.Cm[3] = P_g; J.N[3] = 512; J.K[3] = 128; J.transb[3] = 0; J.act[3] = 0;
        J.bias[3] = nullptr; J.aux1[3] = nullptr; J.aux2[3] = nullptr; J.mix[3] = nullptr;
        gemm_multi<<<dim3(32, 32), 256>>>(J);
    }

    // 5) kk normalize, k', aa, bb
    post_kernel<<<BT, 128>>>(k_k, k_a);

    // 5b) A' streams + (beta,kappa) scalars
    prep2_kernel<<<BT, 128>>>();

    // 6) bidirectional WKV7 scan — 256 blocks x 128 threads
    scan_kernel<<<256, 128>>>();

    // 7) combine + groupnorm + residual + *g
    combine_kernel<<<BT, 128>>>(r_k, ln_g, ln_b);

    // 8) out = z @ Wo^T — tf32 tensor cores (no mixing)
    {
        QkvJobs J;
        J.A[0] = P_z; J.W[0] = Wo; J.C[0] = out; J.mix[0] = nullptr;
        J.A[1] = P_z; J.W[1] = Wo; J.C[1] = out; J.mix[1] = nullptr;
        J.A[2] = P_z; J.W[2] = Wo; J.C[2] = out; J.mix[2] = nullptr;
        gemm_tf32_nt<<<dim3(8, 32, 1), 256>>>(J);
    }

    // 9) v_first passthrough if the flattened output includes it
    if (out_size >= 2 * BTC) {
        cudaMemcpyAsync(out + BTC, v_first, (size_t)BTC * sizeof(float),
                        cudaMemcpyDeviceToDevice, 0);
    }
}